// round 3
// baseline (speedup 1.0000x reference)
#include <cuda_runtime.h>
#include <math.h>

// ---------------- geometry ----------------
// x      : [128,  1, 128, 128]
// h1     : [128, 32,  64,  64]   conv1 k4 s2 p1 + relu        (g_h1, reused for d2)
// h2     : [128, 64,  32,  32]   conv2 k4 s2 p1 + relu        (g_h2, reused for d1)
// z      : [128, 64,  32,  32]   conv3 k3 s1 p1               (g_z)
// z_q    : [128, 64,  32,  32]   codebook gather              (g_zq)
// x_rec  : [128,  1, 128, 128]   -> d_out[0 : 2097152]
// d_out[2097152] = recon_loss, d_out[2097153] = vq_loss

#define N_XREC   2097152
#define N_Z      8388608

__device__ float g_h1[128 * 32 * 64 * 64];
__device__ float g_h2[128 * 64 * 32 * 32];
__device__ float g_z [128 * 64 * 32 * 32];
__device__ float g_zq[128 * 64 * 32 * 32];

__global__ void zero_losses_k(float* out) {
    if (threadIdx.x == 0) { out[N_XREC] = 0.0f; out[N_XREC + 1] = 0.0f; }
}

// ---------------- conv1: 1->32, k4 s2 p1, relu ----------------
// block: 1 image, 4 output rows. smem input tile kills predicated LDGs.
__global__ void __launch_bounds__(256) conv1_k(const float* __restrict__ x,
                                               const float* __restrict__ w,
                                               const float* __restrict__ b) {
    __shared__ float tin[10][132];     // input rows 2y0-1 .. 2y0+8, cols -1..128
    __shared__ float ws[512];
    __shared__ float bs[32];
    int n = blockIdx.x >> 4, y0 = (blockIdx.x & 15) * 4;
    int t = threadIdx.x;
    int xo = t & 63, ys = t >> 6, yo = y0 + ys;
    for (int i = t; i < 512; i += 256) ws[i] = w[i];
    if (t < 32) bs[t] = b[t];
    const float* xp = x + n * 16384;
    for (int j = t; j < 1320; j += 256) {
        int r = j / 132, c = j - r * 132;
        int iy = 2 * y0 - 1 + r, ix = c - 1;
        float v = 0.0f;
        if ((unsigned)iy < 128u && (unsigned)ix < 128u) v = xp[iy * 128 + ix];
        tin[r][c] = v;
    }
    __syncthreads();

    float xin[16];
#pragma unroll
    for (int ky = 0; ky < 4; ky++)
#pragma unroll
        for (int kx = 0; kx < 4; kx++)
            xin[ky * 4 + kx] = tin[2 * ys + ky][2 * xo + kx];

    float* outp = g_h1 + n * 131072 + yo * 64 + xo;
#pragma unroll 4
    for (int o = 0; o < 32; o++) {
        float acc = bs[o];
#pragma unroll
        for (int k = 0; k < 16; k++) acc = fmaf(xin[k], ws[o * 16 + k], acc);
        outp[o * 4096] = fmaxf(acc, 0.0f);
    }
}

// ---------------- conv2: 32->64, k4 s2 p1, relu (vectorized) ----------------
// block: 1 image, 64 o, 32x * 4y. thread: 4 o * 8 x. weights [cc][tap][o].
__global__ void __launch_bounds__(256) conv2t_k(const float* __restrict__ w,
                                                const float* __restrict__ b) {
    __shared__ float tin[4][10][68];     // rows padded for float4
    __shared__ float ws[4][16][64];      // [cc][tap][o]
    int n = blockIdx.x >> 3, y0 = (blockIdx.x & 7) * 4;
    int t = threadIdx.x;
    int obase = (t >> 4) * 4;
    int sslot = t & 15;
    int ys = sslot >> 2, x0 = (sslot & 3) * 8;

    float acc[4][8];
#pragma unroll
    for (int j = 0; j < 4; j++)
#pragma unroll
        for (int s = 0; s < 8; s++) acc[j][s] = 0.0f;

    const float* in0 = g_h1 + n * 131072;
    for (int ch = 0; ch < 8; ch++) {
        __syncthreads();
        for (int j = t; j < 4096; j += 256) {          // ws[cc][tap][o]
            int cc = j >> 10, rem = j & 1023, tap = rem >> 6, o = rem & 63;
            ws[cc][tap][o] = w[(o * 32 + ch * 4 + cc) * 16 + tap];
        }
        for (int j = t; j < 2720; j += 256) {          // tin[cc][r][c]
            int cc = j / 680, rem = j - cc * 680, r = rem / 68, c = rem - r * 68;
            int iy = 2 * y0 - 1 + r, ix = c - 1;
            float v = 0.0f;
            if ((unsigned)iy < 64u && (unsigned)ix < 64u)
                v = in0[(ch * 4 + cc) * 4096 + iy * 64 + ix];
            tin[cc][r][c] = v;
        }
        __syncthreads();
#pragma unroll
        for (int cc = 0; cc < 4; cc++) {
#pragma unroll
            for (int ky = 0; ky < 4; ky++) {
                const float* row = &tin[cc][2 * ys + ky][2 * x0];
                float4 xq0 = *(const float4*)(row + 0);
                float4 xq1 = *(const float4*)(row + 4);
                float4 xq2 = *(const float4*)(row + 8);
                float4 xq3 = *(const float4*)(row + 12);
                float4 xq4 = *(const float4*)(row + 16);
                float xr[20] = {xq0.x, xq0.y, xq0.z, xq0.w,
                                xq1.x, xq1.y, xq1.z, xq1.w,
                                xq2.x, xq2.y, xq2.z, xq2.w,
                                xq3.x, xq3.y, xq3.z, xq3.w,
                                xq4.x, xq4.y, xq4.z, xq4.w};
#pragma unroll
                for (int tap = 0; tap < 4; tap++) {
                    float4 wv = *(const float4*)&ws[cc][ky * 4 + tap][obase];
#pragma unroll
                    for (int s = 0; s < 8; s++) {
                        float xv = xr[2 * s + tap];
                        acc[0][s] = fmaf(xv, wv.x, acc[0][s]);
                        acc[1][s] = fmaf(xv, wv.y, acc[1][s]);
                        acc[2][s] = fmaf(xv, wv.z, acc[2][s]);
                        acc[3][s] = fmaf(xv, wv.w, acc[3][s]);
                    }
                }
            }
        }
    }
    float* out0 = g_h2 + n * 65536 + (y0 + ys) * 32 + x0;
#pragma unroll
    for (int j = 0; j < 4; j++) {
        float bv = b[obase + j];
        float4 v0, v1;
        v0.x = fmaxf(acc[j][0] + bv, 0.0f); v0.y = fmaxf(acc[j][1] + bv, 0.0f);
        v0.z = fmaxf(acc[j][2] + bv, 0.0f); v0.w = fmaxf(acc[j][3] + bv, 0.0f);
        v1.x = fmaxf(acc[j][4] + bv, 0.0f); v1.y = fmaxf(acc[j][5] + bv, 0.0f);
        v1.z = fmaxf(acc[j][6] + bv, 0.0f); v1.w = fmaxf(acc[j][7] + bv, 0.0f);
        *(float4*)(out0 + (obase + j) * 1024)     = v0;
        *(float4*)(out0 + (obase + j) * 1024 + 4) = v1;
    }
}

// ---------------- conv3 / deconv1: 64->64, k3 s1 p1 (vectorized) ----------------
template <int FLIP>
__global__ void __launch_bounds__(256) conv3x3_k(const float* __restrict__ w,
                                                 const float* __restrict__ b) {
    __shared__ float tin[8][6][36];      // rows padded for float4
    __shared__ float ws[8][9][64];       // [cc][tap][o]
    int n = blockIdx.x >> 3, y0 = (blockIdx.x & 7) * 4;
    int t = threadIdx.x;
    int obase = (t >> 4) * 4;
    int sslot = t & 15;
    int ys = sslot >> 2, x0 = (sslot & 3) * 8;

    float acc[4][8];
#pragma unroll
    for (int j = 0; j < 4; j++)
#pragma unroll
        for (int s = 0; s < 8; s++) acc[j][s] = 0.0f;

    const float* in0 = (FLIP ? g_zq : g_h2) + n * 65536;
    for (int ch = 0; ch < 8; ch++) {
        __syncthreads();
        for (int j = t; j < 4608; j += 256) {          // ws[cc][tap][o]
            int cc = j / 576, rem = j - cc * 576, tap = rem >> 6, o = rem & 63;
            int ci = ch * 8 + cc;
            ws[cc][tap][o] = FLIP ? w[(ci * 64 + o) * 9 + (8 - tap)]
                                  : w[(o * 64 + ci) * 9 + tap];
        }
        for (int j = t; j < 1728; j += 256) {          // tin[cc][r][c]
            int cc = j / 216, rem = j - cc * 216, r = rem / 36, c = rem - r * 36;
            int iy = y0 - 1 + r, ix = c - 1;
            float v = 0.0f;
            if ((unsigned)iy < 32u && (unsigned)ix < 32u)
                v = in0[(ch * 8 + cc) * 1024 + iy * 32 + ix];
            tin[cc][r][c] = v;
        }
        __syncthreads();
#pragma unroll 2
        for (int cc = 0; cc < 8; cc++) {
#pragma unroll
            for (int ky = 0; ky < 3; ky++) {
                const float* row = &tin[cc][ys + ky][x0];
                float4 xq0 = *(const float4*)(row + 0);
                float4 xq1 = *(const float4*)(row + 4);
                float4 xq2 = *(const float4*)(row + 8);
                float xr[12] = {xq0.x, xq0.y, xq0.z, xq0.w,
                                xq1.x, xq1.y, xq1.z, xq1.w,
                                xq2.x, xq2.y, xq2.z, xq2.w};
#pragma unroll
                for (int tap = 0; tap < 3; tap++) {
                    float4 wv = *(const float4*)&ws[cc][ky * 3 + tap][obase];
#pragma unroll
                    for (int s = 0; s < 8; s++) {
                        float xv = xr[s + tap];
                        acc[0][s] = fmaf(xv, wv.x, acc[0][s]);
                        acc[1][s] = fmaf(xv, wv.y, acc[1][s]);
                        acc[2][s] = fmaf(xv, wv.z, acc[2][s]);
                        acc[3][s] = fmaf(xv, wv.w, acc[3][s]);
                    }
                }
            }
        }
    }
    float* out0 = (FLIP ? g_h2 : g_z) + n * 65536 + (y0 + ys) * 32 + x0;
#pragma unroll
    for (int j = 0; j < 4; j++) {
        float bv = b[obase + j];
        float4 v0, v1;
        if (FLIP) {
            v0.x = fmaxf(acc[j][0] + bv, 0.0f); v0.y = fmaxf(acc[j][1] + bv, 0.0f);
            v0.z = fmaxf(acc[j][2] + bv, 0.0f); v0.w = fmaxf(acc[j][3] + bv, 0.0f);
            v1.x = fmaxf(acc[j][4] + bv, 0.0f); v1.y = fmaxf(acc[j][5] + bv, 0.0f);
            v1.z = fmaxf(acc[j][6] + bv, 0.0f); v1.w = fmaxf(acc[j][7] + bv, 0.0f);
        } else {
            v0.x = acc[j][0] + bv; v0.y = acc[j][1] + bv;
            v0.z = acc[j][2] + bv; v0.w = acc[j][3] + bv;
            v1.x = acc[j][4] + bv; v1.y = acc[j][5] + bv;
            v1.z = acc[j][6] + bv; v1.w = acc[j][7] + bv;
        }
        *(float4*)(out0 + (obase + j) * 1024)     = v0;
        *(float4*)(out0 + (obase + j) * 1024 + 4) = v1;
    }
}

// ---------------- quantize: argmin over 128 codes, dim 64 ----------------
__global__ void __launch_bounds__(256) quantize_k(const float* __restrict__ cb,
                                                  float* out) {
    __shared__ float4 cbs[2048];
    __shared__ float cn[128];
    __shared__ float red[256];
    int t = threadIdx.x;
    for (int i = t; i < 2048; i += 256) cbs[i] = ((const float4*)cb)[i];
    __syncthreads();
    if (t < 128) {
        float s = 0.0f;
        const float4* cp = cbs + t * 16;
#pragma unroll
        for (int d = 0; d < 16; d++) {
            float4 c = cp[d];
            s = fmaf(c.x, c.x, s); s = fmaf(c.y, c.y, s);
            s = fmaf(c.z, c.z, s); s = fmaf(c.w, c.w, s);
        }
        cn[t] = s;
    }
    __syncthreads();

    int p = blockIdx.x * 256 + t;
    int hw = p & 1023, n = p >> 10;
    const float* zp = g_z + n * 65536 + hw;
    float zr[64];
#pragma unroll
    for (int d = 0; d < 64; d++) zr[d] = zp[d * 1024];

    int best = 0;
    float bestv = 3.4e38f;
    for (int e = 0; e < 128; e++) {
        const float4* cp = cbs + e * 16;
        float dot = 0.0f;
#pragma unroll
        for (int d = 0; d < 16; d++) {
            float4 c = cp[d];
            dot = fmaf(zr[4 * d + 0], c.x, dot);
            dot = fmaf(zr[4 * d + 1], c.y, dot);
            dot = fmaf(zr[4 * d + 2], c.z, dot);
            dot = fmaf(zr[4 * d + 3], c.w, dot);
        }
        float sc = cn[e] - 2.0f * dot;
        if (sc < bestv) { bestv = sc; best = e; }
    }

    float vs = 0.0f;
    float* zqp = g_zq + n * 65536 + hw;
    const float* cbest = (const float*)(cbs + best * 16);
#pragma unroll
    for (int d = 0; d < 64; d++) {
        float c = cbest[d];
        zqp[d * 1024] = c;
        float df = zr[d] - c;
        vs = fmaf(df, df, vs);
    }

    red[t] = vs;
    __syncthreads();
    for (int s = 128; s > 0; s >>= 1) {
        if (t < s) red[t] += red[t + s];
        __syncthreads();
    }
    if (t == 0) atomicAdd(out + N_XREC + 1, red[0] * (1.0f / (float)N_Z));
}

// ---------------- deconv2: 64->32, k4 s2 p1, relu (vectorized) ----------------
__global__ void __launch_bounds__(256) deconv2t_k(const float* __restrict__ w,
                                                  const float* __restrict__ b) {
    __shared__ float tin[8][4][36];
    __shared__ float ws[8][16][32];      // [cc][tap][o]
    int n = blockIdx.x >> 4, y0 = (blockIdx.x & 15) * 4;
    int t = threadIdx.x;
    int obase = (t >> 5) * 4;
    int sslot = t & 31;
    int ys = sslot >> 3, x0 = (sslot & 7) * 8;

    int yo = y0 + ys;
    int ky0 = (yo + 1) & 1;
    int yiA = (yo + 1 - ky0) >> 1;
    int rowA = yiA - (y0 >> 1) + 1;
    int rowB = rowA - 1;
    int cbase = x0 >> 1;

    float acc[4][8];
#pragma unroll
    for (int j = 0; j < 4; j++)
#pragma unroll
        for (int s = 0; s < 8; s++) acc[j][s] = 0.0f;

    const float* in0 = g_h2 + n * 65536;
    for (int ch = 0; ch < 8; ch++) {
        __syncthreads();
        for (int j = t; j < 4096; j += 256) {          // ws[cc][tap][o]
            int cc = j >> 9, rem = j & 511, tap = rem >> 5, o = rem & 31;
            ws[cc][tap][o] = w[((ch * 8 + cc) * 32 + o) * 16 + tap];
        }
        for (int j = t; j < 1152; j += 256) {          // tin[cc][r][c]
            int cc = j / 144, rem = j - cc * 144, r = rem / 36, c = rem - r * 36;
            int yi = (y0 >> 1) - 1 + r, xi = c - 1;
            float v = 0.0f;
            if ((unsigned)yi < 32u && (unsigned)xi < 32u)
                v = in0[(ch * 8 + cc) * 1024 + yi * 32 + xi];
            tin[cc][r][c] = v;
        }
        __syncthreads();
#pragma unroll 2
        for (int cc = 0; cc < 8; cc++) {
            float4 aq0 = *(const float4*)&tin[cc][rowA][cbase];
            float4 aq1 = *(const float4*)&tin[cc][rowA][cbase + 4];
            float4 bq0 = *(const float4*)&tin[cc][rowB][cbase];
            float4 bq1 = *(const float4*)&tin[cc][rowB][cbase + 4];
            float a8[8] = {aq0.x, aq0.y, aq0.z, aq0.w, aq1.x, aq1.y, aq1.z, aq1.w};
            float b8[8] = {bq0.x, bq0.y, bq0.z, bq0.w, bq1.x, bq1.y, bq1.z, bq1.w};
#pragma unroll
            for (int kx = 0; kx < 4; kx++) {
                float4 wvA = *(const float4*)&ws[cc][ky0 * 4 + kx][obase];
                float4 wvB = *(const float4*)&ws[cc][(ky0 + 2) * 4 + kx][obase];
                int soff = 1 - (kx & 1);     // kx even -> odd s; kx odd -> even s
                int sub = kx >> 1;           // 0 -> +1 (ia), 1 -> +0 (ib)
#pragma unroll
                for (int ss = 0; ss < 4; ss++) {
                    int s = 2 * ss + soff;
                    int idx = (s >> 1) + (s & 1) + 1 - sub;
                    float xa = a8[idx], xb = b8[idx];
                    acc[0][s] = fmaf(xa, wvA.x, acc[0][s]);
                    acc[1][s] = fmaf(xa, wvA.y, acc[1][s]);
                    acc[2][s] = fmaf(xa, wvA.z, acc[2][s]);
                    acc[3][s] = fmaf(xa, wvA.w, acc[3][s]);
                    acc[0][s] = fmaf(xb, wvB.x, acc[0][s]);
                    acc[1][s] = fmaf(xb, wvB.y, acc[1][s]);
                    acc[2][s] = fmaf(xb, wvB.z, acc[2][s]);
                    acc[3][s] = fmaf(xb, wvB.w, acc[3][s]);
                }
            }
        }
    }
    float* out0 = g_h1 + n * 131072 + yo * 64 + x0;
#pragma unroll
    for (int j = 0; j < 4; j++) {
        float bv = b[obase + j];
        float4 v0, v1;
        v0.x = fmaxf(acc[j][0] + bv, 0.0f); v0.y = fmaxf(acc[j][1] + bv, 0.0f);
        v0.z = fmaxf(acc[j][2] + bv, 0.0f); v0.w = fmaxf(acc[j][3] + bv, 0.0f);
        v1.x = fmaxf(acc[j][4] + bv, 0.0f); v1.y = fmaxf(acc[j][5] + bv, 0.0f);
        v1.z = fmaxf(acc[j][6] + bv, 0.0f); v1.w = fmaxf(acc[j][7] + bv, 0.0f);
        *(float4*)(out0 + (obase + j) * 4096)     = v0;
        *(float4*)(out0 + (obase + j) * 4096 + 4) = v1;
    }
}

// ---------------- deconv3: 32->1, k4 s2 p1, sigmoid + recon loss ----------------
__global__ void __launch_bounds__(256) deconv3t_k(const float* __restrict__ xin,
                                                  const float* __restrict__ w,
                                                  const float* __restrict__ b,
                                                  float* out) {
    __shared__ float tin[8][10][68];
    __shared__ float ws3[512];
    __shared__ float red[256];
    int n = blockIdx.x >> 3, y0 = (blockIdx.x & 7) * 16;
    int t = threadIdx.x;
    int ys = t >> 4, x0 = (t & 15) * 8;
    int yo = y0 + ys;
    int ky0 = (yo + 1) & 1;
    int yiA = (yo + 1 - ky0) >> 1;
    int rowA = yiA - (y0 >> 1) + 1;
    int rowB = rowA - 1;
    int cbase = x0 >> 1;

    for (int j = t; j < 512; j += 256) ws3[j] = w[j];

    float acc[8];
#pragma unroll
    for (int s = 0; s < 8; s++) acc[s] = 0.0f;

    const float* in0 = g_h1 + n * 131072;
    for (int ch = 0; ch < 4; ch++) {
        __syncthreads();
        for (int j = t; j < 5440; j += 256) {
            int cc = j / 680, rem = j - cc * 680, r = rem / 68, c = rem - r * 68;
            int yi = (y0 >> 1) - 1 + r, xi = c - 1;
            float v = 0.0f;
            if ((unsigned)yi < 64u && (unsigned)xi < 64u)
                v = in0[(ch * 8 + cc) * 4096 + yi * 64 + xi];
            tin[cc][r][c] = v;
        }
        __syncthreads();
#pragma unroll 2
        for (int cc = 0; cc < 8; cc++) {
            float4 aq0 = *(const float4*)&tin[cc][rowA][cbase];
            float4 aq1 = *(const float4*)&tin[cc][rowA][cbase + 4];
            float4 bq0 = *(const float4*)&tin[cc][rowB][cbase];
            float4 bq1 = *(const float4*)&tin[cc][rowB][cbase + 4];
            float a8[8] = {aq0.x, aq0.y, aq0.z, aq0.w, aq1.x, aq1.y, aq1.z, aq1.w};
            float b8[8] = {bq0.x, bq0.y, bq0.z, bq0.w, bq1.x, bq1.y, bq1.z, bq1.w};
            int ci = ch * 8 + cc;
            float4 wa = *(const float4*)&ws3[ci * 16 + ky0 * 4];
            float4 wb = *(const float4*)&ws3[ci * 16 + (ky0 + 2) * 4];
#pragma unroll
            for (int s = 0; s < 8; s++) {
                int ia = (s >> 1) + (s & 1) + 1, ib = ia - 1;
                float v = acc[s];
                if (s & 1) {
                    v = fmaf(a8[ia], wa.x, v);
                    v = fmaf(a8[ib], wa.z, v);
                    v = fmaf(b8[ia], wb.x, v);
                    v = fmaf(b8[ib], wb.z, v);
                } else {
                    v = fmaf(a8[ia], wa.y, v);
                    v = fmaf(a8[ib], wa.w, v);
                    v = fmaf(b8[ia], wb.y, v);
                    v = fmaf(b8[ib], wb.w, v);
                }
                acc[s] = v;
            }
        }
    }

    float b0 = b[0];
    const float* xp = xin + n * 16384 + yo * 128 + x0;
    float* op = out + n * 16384 + yo * 128 + x0;
    float ls = 0.0f;
    float rv[8];
#pragma unroll
    for (int s = 0; s < 8; s++) {
        float r = 1.0f / (1.0f + expf(-(acc[s] + b0)));
        rv[s] = r;
        float df = r - xp[s];
        ls = fmaf(df, df, ls);
    }
    *(float4*)(op)     = make_float4(rv[0], rv[1], rv[2], rv[3]);
    *(float4*)(op + 4) = make_float4(rv[4], rv[5], rv[6], rv[7]);

    red[t] = ls;
    __syncthreads();
    for (int s = 128; s > 0; s >>= 1) {
        if (t < s) red[t] += red[t + s];
        __syncthreads();
    }
    if (t == 0) atomicAdd(out + N_XREC, red[0] * (1.0f / (float)N_XREC));
}

// ---------------- launch ----------------
extern "C" void kernel_launch(void* const* d_in, const int* in_sizes, int n_in,
                              void* d_out, int out_size) {
    const float* x   = (const float*)d_in[0];
    const float* w1  = (const float*)d_in[1];
    const float* b1  = (const float*)d_in[2];
    const float* w2  = (const float*)d_in[3];
    const float* b2  = (const float*)d_in[4];
    const float* w3  = (const float*)d_in[5];
    const float* b3  = (const float*)d_in[6];
    const float* cb  = (const float*)d_in[7];
    const float* dw1 = (const float*)d_in[8];
    const float* db1 = (const float*)d_in[9];
    const float* dw2 = (const float*)d_in[10];
    const float* db2 = (const float*)d_in[11];
    const float* dw3 = (const float*)d_in[12];
    const float* db3 = (const float*)d_in[13];
    float* out = (float*)d_out;

    zero_losses_k<<<1, 32>>>(out);
    conv1_k   <<<2048, 256>>>(x, w1, b1);
    conv2t_k  <<<1024, 256>>>(w2, b2);
    conv3x3_k<0><<<1024, 256>>>(w3, b3);
    quantize_k<<<512,  256>>>(cb, out);
    conv3x3_k<1><<<1024, 256>>>(dw1, db1);
    deconv2t_k<<<2048, 256>>>(dw2, db2);
    deconv3t_k<<<1024, 256>>>(x, dw3, db3, out);
}

// round 5
// speedup vs baseline: 1.3681x; 1.3681x over previous
#include <cuda_runtime.h>
#include <stdint.h>
#include <math.h>

// ---------------- geometry ----------------
// x      : [128,  1, 128, 128]
// h1     : [128, 32,  64,  64]   conv1 k4 s2 p1 + relu        (g_h1, reused for d2)
// h2     : [128, 64,  32,  32]   conv2 k4 s2 p1 + relu        (g_h2, reused for d1)
// z      : [128, 64,  32,  32]   conv3 k3 s1 p1               (g_z)
// z_q    : [128, 64,  32,  32]   codebook gather              (g_zq)
// x_rec  : [128,  1, 128, 128]   -> d_out[0 : 2097152]
// d_out[2097152] = recon_loss, d_out[2097153] = vq_loss

#define N_XREC   2097152
#define N_Z      8388608

__device__ float g_h1[128 * 32 * 64 * 64];
__device__ float g_h2[128 * 64 * 32 * 32];
__device__ float g_z [128 * 64 * 32 * 32];
__device__ float g_zq[128 * 64 * 32 * 32];

// ---------------- cp.async helpers ----------------
__device__ __forceinline__ void cp4(uint32_t dst, const float* src, bool p) {
    asm volatile("cp.async.ca.shared.global [%0], [%1], 4, %2;"
                 :: "r"(dst), "l"(src), "r"(p ? 4u : 0u));
}
__device__ __forceinline__ void cp16(uint32_t dst, const float* src) {
    asm volatile("cp.async.ca.shared.global [%0], [%1], 16;"
                 :: "r"(dst), "l"(src));
}
__device__ __forceinline__ void cp_commit() {
    asm volatile("cp.async.commit_group;");
}
__device__ __forceinline__ void cp_wait1() {
    asm volatile("cp.async.wait_group 1;");
}
__device__ __forceinline__ void cp_wait0() {
    asm volatile("cp.async.wait_group 0;");
}

__global__ void zero_losses_k(float* out) {
    if (threadIdx.x == 0) { out[N_XREC] = 0.0f; out[N_XREC + 1] = 0.0f; }
}

// ---------------- conv1: 1->32, k4 s2 p1, relu ----------------
__global__ void __launch_bounds__(256) conv1_k(const float* __restrict__ x,
                                               const float* __restrict__ w,
                                               const float* __restrict__ b) {
    __shared__ float tin[10][132];
    __shared__ float ws[512];
    __shared__ float bs[32];
    int n = blockIdx.x >> 4, y0 = (blockIdx.x & 15) * 4;
    int t = threadIdx.x;
    int xo = t & 63, ys = t >> 6, yo = y0 + ys;
    for (int i = t; i < 512; i += 256) ws[i] = w[i];
    if (t < 32) bs[t] = b[t];
    const float* xp = x + n * 16384;
    for (int j = t; j < 1320; j += 256) {
        int r = j / 132, c = j - r * 132;
        int iy = 2 * y0 - 1 + r, ix = c - 1;
        float v = 0.0f;
        if ((unsigned)iy < 128u && (unsigned)ix < 128u) v = xp[iy * 128 + ix];
        tin[r][c] = v;
    }
    __syncthreads();

    float xin[16];
#pragma unroll
    for (int ky = 0; ky < 4; ky++)
#pragma unroll
        for (int kx = 0; kx < 4; kx++)
            xin[ky * 4 + kx] = tin[2 * ys + ky][2 * xo + kx];

    float* outp = g_h1 + n * 131072 + yo * 64 + xo;
#pragma unroll 4
    for (int o = 0; o < 32; o++) {
        float acc = bs[o];
#pragma unroll
        for (int k = 0; k < 16; k++) acc = fmaf(xin[k], ws[o * 16 + k], acc);
        outp[o * 4096] = fmaxf(acc, 0.0f);
    }
}

// ---------------- conv2: 32->64, k4 s2 p1, relu (double-buffered) ----------------
// dynamic smem: tin[2][4][10][66] (2*2640) + ws[2][4][64][16] (2*4096) = 53888 B
__global__ void __launch_bounds__(256) conv2t_k(const float* __restrict__ w,
                                                const float* __restrict__ b) {
    extern __shared__ float dsm[];
    float* tin = dsm;               // [buf][cc][10][66]
    float* ws  = dsm + 5280;        // [buf][cc][o][16]
    uint32_t tin_s = (uint32_t)__cvta_generic_to_shared(tin);
    uint32_t ws_s  = (uint32_t)__cvta_generic_to_shared(ws);
    int n = blockIdx.x >> 3, y0 = (blockIdx.x & 7) * 4;
    int t = threadIdx.x;
    int obase = (t >> 4) * 4;
    int sslot = t & 15;
    int ys = sslot >> 2, x0 = (sslot & 3) * 8;
    const float* in0 = g_h1 + n * 131072;

    float acc[4][8];
#pragma unroll
    for (int j = 0; j < 4; j++)
#pragma unroll
        for (int s = 0; s < 8; s++) acc[j][s] = 0.0f;

    auto load_chunk = [&](int buf, int ch) {
        for (int j = t; j < 4096; j += 256) {          // ws[cc][o][tap]
            int cc = j >> 10, rem = j & 1023, o = rem >> 4, tap = rem & 15;
            cp4(ws_s + (buf * 4096 + j) * 4,
                &w[(o * 32 + ch * 4 + cc) * 16 + tap], true);
        }
        for (int j = t; j < 2640; j += 256) {          // tin[cc][r][c]
            int cc = j / 660, rem = j - cc * 660, r = rem / 66, c = rem - r * 66;
            int iy = 2 * y0 - 1 + r, ix = c - 1;
            bool p = ((unsigned)iy < 64u) & ((unsigned)ix < 64u);
            const float* src = in0 + (ch * 4 + cc) * 4096 + (p ? iy * 64 + ix : 0);
            cp4(tin_s + (buf * 2640 + j) * 4, src, p);
        }
        cp_commit();
    };

    load_chunk(0, 0);
    for (int ch = 0; ch < 8; ch++) {
        if (ch < 7) { load_chunk((ch + 1) & 1, ch + 1); cp_wait1(); }
        else        { cp_wait0(); }
        __syncthreads();
        const float* tb = tin + (ch & 1) * 2640;
        const float* wb = ws  + (ch & 1) * 4096;
#pragma unroll
        for (int cc = 0; cc < 4; cc++) {
#pragma unroll
            for (int ky = 0; ky < 4; ky++) {
                const float* row = tb + cc * 660 + (2 * ys + ky) * 66 + 2 * x0;
                float xr[18];
#pragma unroll
                for (int c = 0; c < 18; c++) xr[c] = row[c];
#pragma unroll
                for (int j = 0; j < 4; j++) {
                    const float* wp = wb + cc * 1024 + (obase + j) * 16 + ky * 4;
                    float w0 = wp[0], w1 = wp[1], w2 = wp[2], w3 = wp[3];
#pragma unroll
                    for (int s = 0; s < 8; s++) {
                        float a = acc[j][s];
                        a = fmaf(xr[2 * s + 0], w0, a);
                        a = fmaf(xr[2 * s + 1], w1, a);
                        a = fmaf(xr[2 * s + 2], w2, a);
                        a = fmaf(xr[2 * s + 3], w3, a);
                        acc[j][s] = a;
                    }
                }
            }
        }
        __syncthreads();
    }
    float* out0 = g_h2 + n * 65536 + (y0 + ys) * 32 + x0;
#pragma unroll
    for (int j = 0; j < 4; j++) {
        float bv = b[obase + j];
        float4 v0, v1;
        v0.x = fmaxf(acc[j][0] + bv, 0.0f); v0.y = fmaxf(acc[j][1] + bv, 0.0f);
        v0.z = fmaxf(acc[j][2] + bv, 0.0f); v0.w = fmaxf(acc[j][3] + bv, 0.0f);
        v1.x = fmaxf(acc[j][4] + bv, 0.0f); v1.y = fmaxf(acc[j][5] + bv, 0.0f);
        v1.z = fmaxf(acc[j][6] + bv, 0.0f); v1.w = fmaxf(acc[j][7] + bv, 0.0f);
        *(float4*)(out0 + (obase + j) * 1024)     = v0;
        *(float4*)(out0 + (obase + j) * 1024 + 4) = v1;
    }
}

// ---------------- conv3 / deconv1: 64->64, k3 s1 p1 (double-buffered) ----------------
// dynamic smem: tin[2][8][6][34] (2*1632) + ws[2][8][64][9] (2*4608) = 49920 B
template <int FLIP>
__global__ void __launch_bounds__(256) conv3x3_k(const float* __restrict__ w,
                                                 const float* __restrict__ b) {
    extern __shared__ float dsm[];
    float* tin = dsm;               // [buf][cc][6][34]
    float* ws  = dsm + 3264;        // [buf][cc][o][9]
    uint32_t tin_s = (uint32_t)__cvta_generic_to_shared(tin);
    uint32_t ws_s  = (uint32_t)__cvta_generic_to_shared(ws);
    int n = blockIdx.x >> 3, y0 = (blockIdx.x & 7) * 4;
    int t = threadIdx.x;
    int obase = (t >> 4) * 4;
    int sslot = t & 15;
    int ys = sslot >> 2, x0 = (sslot & 3) * 8;
    const float* in0 = (FLIP ? g_zq : g_h2) + n * 65536;

    float acc[4][8];
#pragma unroll
    for (int j = 0; j < 4; j++)
#pragma unroll
        for (int s = 0; s < 8; s++) acc[j][s] = 0.0f;

    auto load_chunk = [&](int buf, int ch) {
        for (int j = t; j < 4608; j += 256) {          // ws[cc][o][tap]
            int cc = j / 576, rem = j - cc * 576, o = rem / 9, tap = rem - o * 9;
            int ci = ch * 8 + cc;
            const float* src = FLIP ? &w[(ci * 64 + o) * 9 + (8 - tap)]
                                    : &w[(o * 64 + ci) * 9 + tap];
            cp4(ws_s + (buf * 4608 + j) * 4, src, true);
        }
        for (int j = t; j < 1632; j += 256) {          // tin[cc][r][c]
            int cc = j / 204, rem = j - cc * 204, r = rem / 34, c = rem - r * 34;
            int iy = y0 - 1 + r, ix = c - 1;
            bool p = ((unsigned)iy < 32u) & ((unsigned)ix < 32u);
            const float* src = in0 + (ch * 8 + cc) * 1024 + (p ? iy * 32 + ix : 0);
            cp4(tin_s + (buf * 1632 + j) * 4, src, p);
        }
        cp_commit();
    };

    load_chunk(0, 0);
    for (int ch = 0; ch < 8; ch++) {
        if (ch < 7) { load_chunk((ch + 1) & 1, ch + 1); cp_wait1(); }
        else        { cp_wait0(); }
        __syncthreads();
        const float* tb = tin + (ch & 1) * 1632;
        const float* wb = ws  + (ch & 1) * 4608;
#pragma unroll 2
        for (int cc = 0; cc < 8; cc++) {
#pragma unroll
            for (int ky = 0; ky < 3; ky++) {
                const float* row = tb + cc * 204 + (ys + ky) * 34 + x0;
                float xr[10];
#pragma unroll
                for (int c = 0; c < 10; c++) xr[c] = row[c];
#pragma unroll
                for (int j = 0; j < 4; j++) {
                    const float* wp = wb + cc * 576 + (obase + j) * 9 + ky * 3;
                    float w0 = wp[0], w1 = wp[1], w2 = wp[2];
#pragma unroll
                    for (int s = 0; s < 8; s++) {
                        float a = acc[j][s];
                        a = fmaf(xr[s + 0], w0, a);
                        a = fmaf(xr[s + 1], w1, a);
                        a = fmaf(xr[s + 2], w2, a);
                        acc[j][s] = a;
                    }
                }
            }
        }
        __syncthreads();
    }
    float* out0 = (FLIP ? g_h2 : g_z) + n * 65536 + (y0 + ys) * 32 + x0;
#pragma unroll
    for (int j = 0; j < 4; j++) {
        float bv = b[obase + j];
        float4 v0, v1;
        if (FLIP) {
            v0.x = fmaxf(acc[j][0] + bv, 0.0f); v0.y = fmaxf(acc[j][1] + bv, 0.0f);
            v0.z = fmaxf(acc[j][2] + bv, 0.0f); v0.w = fmaxf(acc[j][3] + bv, 0.0f);
            v1.x = fmaxf(acc[j][4] + bv, 0.0f); v1.y = fmaxf(acc[j][5] + bv, 0.0f);
            v1.z = fmaxf(acc[j][6] + bv, 0.0f); v1.w = fmaxf(acc[j][7] + bv, 0.0f);
        } else {
            v0.x = acc[j][0] + bv; v0.y = acc[j][1] + bv;
            v0.z = acc[j][2] + bv; v0.w = acc[j][3] + bv;
            v1.x = acc[j][4] + bv; v1.y = acc[j][5] + bv;
            v1.z = acc[j][6] + bv; v1.w = acc[j][7] + bv;
        }
        *(float4*)(out0 + (obase + j) * 1024)     = v0;
        *(float4*)(out0 + (obase + j) * 1024 + 4) = v1;
    }
}

// ---------------- quantize: argmin over 128 codes, dim 64 ----------------
__global__ void __launch_bounds__(256) quantize_k(const float* __restrict__ cb,
                                                  float* out) {
    __shared__ float4 cbs[2048];
    __shared__ float cn[128];
    __shared__ float red[256];
    int t = threadIdx.x;
    for (int i = t; i < 2048; i += 256) cbs[i] = ((const float4*)cb)[i];
    __syncthreads();
    if (t < 128) {
        float s = 0.0f;
        const float4* cp = cbs + t * 16;
#pragma unroll
        for (int d = 0; d < 16; d++) {
            float4 c = cp[d];
            s = fmaf(c.x, c.x, s); s = fmaf(c.y, c.y, s);
            s = fmaf(c.z, c.z, s); s = fmaf(c.w, c.w, s);
        }
        cn[t] = s;
    }
    __syncthreads();

    int p = blockIdx.x * 256 + t;
    int hw = p & 1023, n = p >> 10;
    const float* zp = g_z + n * 65536 + hw;
    float zr[64];
#pragma unroll
    for (int d = 0; d < 64; d++) zr[d] = zp[d * 1024];

    int best = 0;
    float bestv = 3.4e38f;
    for (int e = 0; e < 128; e++) {
        const float4* cp = cbs + e * 16;
        float dot = 0.0f;
#pragma unroll
        for (int d = 0; d < 16; d++) {
            float4 c = cp[d];
            dot = fmaf(zr[4 * d + 0], c.x, dot);
            dot = fmaf(zr[4 * d + 1], c.y, dot);
            dot = fmaf(zr[4 * d + 2], c.z, dot);
            dot = fmaf(zr[4 * d + 3], c.w, dot);
        }
        float sc = cn[e] - 2.0f * dot;
        if (sc < bestv) { bestv = sc; best = e; }
    }

    float vs = 0.0f;
    float* zqp = g_zq + n * 65536 + hw;
    const float* cbest = (const float*)(cbs + best * 16);
#pragma unroll
    for (int d = 0; d < 64; d++) {
        float c = cbest[d];
        zqp[d * 1024] = c;
        float df = zr[d] - c;
        vs = fmaf(df, df, vs);
    }

    red[t] = vs;
    __syncthreads();
    for (int s = 128; s > 0; s >>= 1) {
        if (t < s) red[t] += red[t + s];
        __syncthreads();
    }
    if (t == 0) atomicAdd(out + N_XREC + 1, red[0] * (1.0f / (float)N_Z));
}

// ---------------- deconv2: 64->32, k4 s2 p1, relu (double-buffered, static) ----------------
__global__ void __launch_bounds__(256) deconv2t_k(const float* __restrict__ w,
                                                  const float* __restrict__ b) {
    __shared__ float tin[2][8][4][34];   // 2*1088
    __shared__ float ws[2][4096];        // [buf][ci*512 + o*16 + tap]
    uint32_t tin_s = (uint32_t)__cvta_generic_to_shared(&tin[0][0][0][0]);
    uint32_t ws_s  = (uint32_t)__cvta_generic_to_shared(&ws[0][0]);
    int n = blockIdx.x >> 4, y0 = (blockIdx.x & 15) * 4;
    int t = threadIdx.x;
    int obase = (t >> 5) * 4;
    int sslot = t & 31;
    int ys = sslot >> 3, x0 = (sslot & 7) * 8;

    int yo = y0 + ys;
    int ky0 = (yo + 1) & 1;
    int yiA = (yo + 1 - ky0) >> 1;
    int rowA = yiA - (y0 >> 1) + 1;
    int rowB = rowA - 1;
    int cbase = x0 >> 1;

    float acc[4][8];
#pragma unroll
    for (int j = 0; j < 4; j++)
#pragma unroll
        for (int s = 0; s < 8; s++) acc[j][s] = 0.0f;

    const float* in0 = g_h2 + n * 65536;
    auto load_chunk = [&](int buf, int ch) {
        for (int j = t; j < 1024; j += 256)            // weights, 16B chunks
            cp16(ws_s + (buf * 4096 + j * 4) * 4, w + ch * 4096 + j * 4);
        for (int j = t; j < 1088; j += 256) {          // tin[cc][r][c]
            int cc = j / 136, rem = j - cc * 136, r = rem / 34, c = rem - r * 34;
            int yi = (y0 >> 1) - 1 + r, xi = c - 1;
            bool p = ((unsigned)yi < 32u) & ((unsigned)xi < 32u);
            const float* src = in0 + (ch * 8 + cc) * 1024 + (p ? yi * 32 + xi : 0);
            cp4(tin_s + (buf * 1088 + j) * 4, src, p);
        }
        cp_commit();
    };

    load_chunk(0, 0);
    for (int ch = 0; ch < 8; ch++) {
        if (ch < 7) { load_chunk((ch + 1) & 1, ch + 1); cp_wait1(); }
        else        { cp_wait0(); }
        __syncthreads();
        int buf = ch & 1;
#pragma unroll 2
        for (int cc = 0; cc < 8; cc++) {
            float a[6], bb[6];
#pragma unroll
            for (int c = 0; c < 6; c++) {
                a[c]  = tin[buf][cc][rowA][cbase + c];
                bb[c] = tin[buf][cc][rowB][cbase + c];
            }
#pragma unroll
            for (int j = 0; j < 4; j++) {
                const float* wp = &ws[buf][cc * 512 + (obase + j) * 16];
                float wk0 = wp[ky0 * 4 + 0], wk1 = wp[ky0 * 4 + 1];
                float wk2 = wp[ky0 * 4 + 2], wk3 = wp[ky0 * 4 + 3];
                float wk4 = wp[(ky0 + 2) * 4 + 0], wk5 = wp[(ky0 + 2) * 4 + 1];
                float wk6 = wp[(ky0 + 2) * 4 + 2], wk7 = wp[(ky0 + 2) * 4 + 3];
#pragma unroll
                for (int s = 0; s < 8; s++) {
                    int ia = (s >> 1) + (s & 1) + 1, ib = ia - 1;
                    float v = acc[j][s];
                    if (s & 1) {
                        v = fmaf(a[ia],  wk0, v);
                        v = fmaf(a[ib],  wk2, v);
                        v = fmaf(bb[ia], wk4, v);
                        v = fmaf(bb[ib], wk6, v);
                    } else {
                        v = fmaf(a[ia],  wk1, v);
                        v = fmaf(a[ib],  wk3, v);
                        v = fmaf(bb[ia], wk5, v);
                        v = fmaf(bb[ib], wk7, v);
                    }
                    acc[j][s] = v;
                }
            }
        }
        __syncthreads();
    }
    float* out0 = g_h1 + n * 131072 + yo * 64 + x0;
#pragma unroll
    for (int j = 0; j < 4; j++) {
        float bv = b[obase + j];
        float4 v0, v1;
        v0.x = fmaxf(acc[j][0] + bv, 0.0f); v0.y = fmaxf(acc[j][1] + bv, 0.0f);
        v0.z = fmaxf(acc[j][2] + bv, 0.0f); v0.w = fmaxf(acc[j][3] + bv, 0.0f);
        v1.x = fmaxf(acc[j][4] + bv, 0.0f); v1.y = fmaxf(acc[j][5] + bv, 0.0f);
        v1.z = fmaxf(acc[j][6] + bv, 0.0f); v1.w = fmaxf(acc[j][7] + bv, 0.0f);
        *(float4*)(out0 + (obase + j) * 4096)     = v0;
        *(float4*)(out0 + (obase + j) * 4096 + 4) = v1;
    }
}

// ---------------- deconv3: 32->1, k4 s2 p1, sigmoid + recon loss (double-buffered) ----------------
__global__ void __launch_bounds__(256) deconv3t_k(const float* __restrict__ xin,
                                                  const float* __restrict__ w,
                                                  const float* __restrict__ b,
                                                  float* out) {
    __shared__ float tin[2][8][10][66];  // 2*5280
    __shared__ float ws3[512];
    __shared__ float red[256];
    uint32_t tin_s = (uint32_t)__cvta_generic_to_shared(&tin[0][0][0][0]);
    int n = blockIdx.x >> 3, y0 = (blockIdx.x & 7) * 16;
    int t = threadIdx.x;
    int ys = t >> 4, x0 = (t & 15) * 8;
    int yo = y0 + ys;
    int ky0 = (yo + 1) & 1;
    int yiA = (yo + 1 - ky0) >> 1;
    int rowA = yiA - (y0 >> 1) + 1;
    int rowB = rowA - 1;
    int cbase = x0 >> 1;

    for (int j = t; j < 512; j += 256) ws3[j] = w[j];

    float acc[8];
#pragma unroll
    for (int s = 0; s < 8; s++) acc[s] = 0.0f;

    const float* in0 = g_h1 + n * 131072;
    auto load_chunk = [&](int buf, int ch) {
        for (int j = t; j < 5280; j += 256) {
            int cc = j / 660, rem = j - cc * 660, r = rem / 66, c = rem - r * 66;
            int yi = (y0 >> 1) - 1 + r, xi = c - 1;
            bool p = ((unsigned)yi < 64u) & ((unsigned)xi < 64u);
            const float* src = in0 + (ch * 8 + cc) * 4096 + (p ? yi * 64 + xi : 0);
            cp4(tin_s + (buf * 5280 + j) * 4, src, p);
        }
        cp_commit();
    };

    load_chunk(0, 0);
    for (int ch = 0; ch < 4; ch++) {
        if (ch < 3) { load_chunk((ch + 1) & 1, ch + 1); cp_wait1(); }
        else        { cp_wait0(); }
        __syncthreads();
        int buf = ch & 1;
#pragma unroll 2
        for (int cc = 0; cc < 8; cc++) {
            float a[6], bb[6];
#pragma unroll
            for (int c = 0; c < 6; c++) {
                a[c]  = tin[buf][cc][rowA][cbase + c];
                bb[c] = tin[buf][cc][rowB][cbase + c];
            }
            int ci = ch * 8 + cc;
            const float* wp = &ws3[ci * 16];
            float wa0 = wp[ky0 * 4 + 0], wa1 = wp[ky0 * 4 + 1];
            float wa2 = wp[ky0 * 4 + 2], wa3 = wp[ky0 * 4 + 3];
            float wb0 = wp[(ky0 + 2) * 4 + 0], wb1 = wp[(ky0 + 2) * 4 + 1];
            float wb2 = wp[(ky0 + 2) * 4 + 2], wb3 = wp[(ky0 + 2) * 4 + 3];
#pragma unroll
            for (int s = 0; s < 8; s++) {
                int ia = (s >> 1) + (s & 1) + 1, ib = ia - 1;
                float v = acc[s];
                if (s & 1) {
                    v = fmaf(a[ia],  wa0, v);
                    v = fmaf(a[ib],  wa2, v);
                    v = fmaf(bb[ia], wb0, v);
                    v = fmaf(bb[ib], wb2, v);
                } else {
                    v = fmaf(a[ia],  wa1, v);
                    v = fmaf(a[ib],  wa3, v);
                    v = fmaf(bb[ia], wb1, v);
                    v = fmaf(bb[ib], wb3, v);
                }
                acc[s] = v;
            }
        }
        __syncthreads();
    }

    float b0 = b[0];
    const float* xp = xin + n * 16384 + yo * 128 + x0;
    float* op = out + n * 16384 + yo * 128 + x0;
    float ls = 0.0f;
    float rv[8];
#pragma unroll
    for (int s = 0; s < 8; s++) {
        float r = 1.0f / (1.0f + expf(-(acc[s] + b0)));
        rv[s] = r;
        float df = r - xp[s];
        ls = fmaf(df, df, ls);
    }
    *(float4*)(op)     = make_float4(rv[0], rv[1], rv[2], rv[3]);
    *(float4*)(op + 4) = make_float4(rv[4], rv[5], rv[6], rv[7]);

    red[t] = ls;
    __syncthreads();
    for (int s = 128; s > 0; s >>= 1) {
        if (t < s) red[t] += red[t + s];
        __syncthreads();
    }
    if (t == 0) atomicAdd(out + N_XREC, red[0] * (1.0f / (float)N_XREC));
}

// ---------------- launch ----------------
extern "C" void kernel_launch(void* const* d_in, const int* in_sizes, int n_in,
                              void* d_out, int out_size) {
    const float* x   = (const float*)d_in[0];
    const float* w1  = (const float*)d_in[1];
    const float* b1  = (const float*)d_in[2];
    const float* w2  = (const float*)d_in[3];
    const float* b2  = (const float*)d_in[4];
    const float* w3  = (const float*)d_in[5];
    const float* b3  = (const float*)d_in[6];
    const float* cb  = (const float*)d_in[7];
    const float* dw1 = (const float*)d_in[8];
    const float* db1 = (const float*)d_in[9];
    const float* dw2 = (const float*)d_in[10];
    const float* db2 = (const float*)d_in[11];
    const float* dw3 = (const float*)d_in[12];
    const float* db3 = (const float*)d_in[13];
    float* out = (float*)d_out;

    static bool attr_done = false;
    if (!attr_done) {
        cudaFuncSetAttribute(conv2t_k, cudaFuncAttributeMaxDynamicSharedMemorySize, 53888);
        cudaFuncSetAttribute(conv3x3_k<0>, cudaFuncAttributeMaxDynamicSharedMemorySize, 49920);
        cudaFuncSetAttribute(conv3x3_k<1>, cudaFuncAttributeMaxDynamicSharedMemorySize, 49920);
        attr_done = true;
    }

    zero_losses_k<<<1, 32>>>(out);
    conv1_k   <<<2048, 256>>>(x, w1, b1);
    conv2t_k  <<<1024, 256, 53888>>>(w2, b2);
    conv3x3_k<0><<<1024, 256, 49920>>>(w3, b3);
    quantize_k<<<512,  256>>>(cb, out);
    conv3x3_k<1><<<1024, 256, 49920>>>(dw1, db1);
    deconv2t_k<<<2048, 256>>>(dw2, db2);
    deconv3t_k<<<1024, 256>>>(x, dw3, db3, out);
}

// round 6
// speedup vs baseline: 1.6807x; 1.2284x over previous
#include <cuda_runtime.h>
#include <stdint.h>
#include <math.h>

// ---------------- geometry ----------------
// x      : [128,  1, 128, 128]
// h1     : [128, 32,  64,  64]   conv1 k4 s2 p1 + relu        (g_h1, reused for d2)
// h2     : [128, 64,  32,  32]   conv2 k4 s2 p1 + relu        (g_h2, reused for d1)
// z      : [128, 64,  32,  32]   conv3 k3 s1 p1               (g_z)   [tf32 mma]
// z_q    : [128, 64,  32,  32]   codebook gather              (g_zq)
// x_rec  : [128,  1, 128, 128]   -> d_out[0 : 2097152]
// d_out[2097152] = recon_loss, d_out[2097153] = vq_loss

#define N_XREC   2097152
#define N_Z      8388608

__device__ float g_h1[128 * 32 * 64 * 64];
__device__ float g_h2[128 * 64 * 32 * 32];
__device__ float g_z [128 * 64 * 32 * 32];
__device__ float g_zq[128 * 64 * 32 * 32];

// ---------------- cp.async helpers ----------------
__device__ __forceinline__ void cp4(uint32_t dst, const float* src, bool p) {
    asm volatile("cp.async.ca.shared.global [%0], [%1], 4, %2;"
                 :: "r"(dst), "l"(src), "r"(p ? 4u : 0u));
}
__device__ __forceinline__ void cp16(uint32_t dst, const float* src) {
    asm volatile("cp.async.ca.shared.global [%0], [%1], 16;"
                 :: "r"(dst), "l"(src));
}
__device__ __forceinline__ void cp_commit() {
    asm volatile("cp.async.commit_group;");
}
__device__ __forceinline__ void cp_wait1() {
    asm volatile("cp.async.wait_group 1;");
}
__device__ __forceinline__ void cp_wait0() {
    asm volatile("cp.async.wait_group 0;");
}

// ---------------- tf32 mma helpers ----------------
__device__ __forceinline__ uint32_t f2tf(float f) {
    uint32_t r; asm("cvt.rna.tf32.f32 %0, %1;" : "=r"(r) : "f"(f)); return r;
}
__device__ __forceinline__ void mma_tf32(float& d0, float& d1, float& d2, float& d3,
                                         uint32_t a0, uint32_t a1, uint32_t a2, uint32_t a3,
                                         uint32_t b0, uint32_t b1) {
    asm volatile("mma.sync.aligned.m16n8k8.row.col.f32.tf32.tf32.f32 "
                 "{%0,%1,%2,%3}, {%4,%5,%6,%7}, {%8,%9}, {%0,%1,%2,%3};"
                 : "+f"(d0), "+f"(d1), "+f"(d2), "+f"(d3)
                 : "r"(a0), "r"(a1), "r"(a2), "r"(a3), "r"(b0), "r"(b1));
}

__global__ void zero_losses_k(float* out) {
    if (threadIdx.x == 0) { out[N_XREC] = 0.0f; out[N_XREC + 1] = 0.0f; }
}

// ---------------- conv1: 1->32, k4 s2 p1, relu ----------------
__global__ void __launch_bounds__(256) conv1_k(const float* __restrict__ x,
                                               const float* __restrict__ w,
                                               const float* __restrict__ b) {
    __shared__ float tin[10][132];
    __shared__ float ws[512];
    __shared__ float bs[32];
    int n = blockIdx.x >> 4, y0 = (blockIdx.x & 15) * 4;
    int t = threadIdx.x;
    int xo = t & 63, ys = t >> 6, yo = y0 + ys;
    for (int i = t; i < 512; i += 256) ws[i] = w[i];
    if (t < 32) bs[t] = b[t];
    const float* xp = x + n * 16384;
    for (int j = t; j < 1320; j += 256) {
        int r = j / 132, c = j - r * 132;
        int iy = 2 * y0 - 1 + r, ix = c - 1;
        float v = 0.0f;
        if ((unsigned)iy < 128u && (unsigned)ix < 128u) v = xp[iy * 128 + ix];
        tin[r][c] = v;
    }
    __syncthreads();

    float xin[16];
#pragma unroll
    for (int ky = 0; ky < 4; ky++)
#pragma unroll
        for (int kx = 0; kx < 4; kx++)
            xin[ky * 4 + kx] = tin[2 * ys + ky][2 * xo + kx];

    float* outp = g_h1 + n * 131072 + yo * 64 + xo;
#pragma unroll 4
    for (int o = 0; o < 32; o++) {
        float acc = bs[o];
#pragma unroll
        for (int k = 0; k < 16; k++) acc = fmaf(xin[k], ws[o * 16 + k], acc);
        outp[o * 4096] = fmaxf(acc, 0.0f);
    }
}

// ---------------- conv2: 32->64, k4 s2 p1, relu (double-buffered FFMA) ----------------
// dynamic smem: tin[2][4][10][66] (2*2640) + ws[2][4][64][16] (2*4096) = 53888 B
__global__ void __launch_bounds__(256) conv2t_k(const float* __restrict__ w,
                                                const float* __restrict__ b) {
    extern __shared__ float dsm[];
    float* tin = dsm;               // [buf][cc][10][66]
    float* ws  = dsm + 5280;        // [buf][cc][o][16]
    uint32_t tin_s = (uint32_t)__cvta_generic_to_shared(tin);
    uint32_t ws_s  = (uint32_t)__cvta_generic_to_shared(ws);
    int n = blockIdx.x >> 3, y0 = (blockIdx.x & 7) * 4;
    int t = threadIdx.x;
    int obase = (t >> 4) * 4;
    int sslot = t & 15;
    int ys = sslot >> 2, x0 = (sslot & 3) * 8;
    const float* in0 = g_h1 + n * 131072;

    float acc[4][8];
#pragma unroll
    for (int j = 0; j < 4; j++)
#pragma unroll
        for (int s = 0; s < 8; s++) acc[j][s] = 0.0f;

    auto load_chunk = [&](int buf, int ch) {
        for (int j = t; j < 4096; j += 256) {          // ws[cc][o][tap]
            int cc = j >> 10, rem = j & 1023, o = rem >> 4, tap = rem & 15;
            cp4(ws_s + (buf * 4096 + j) * 4,
                &w[(o * 32 + ch * 4 + cc) * 16 + tap], true);
        }
        for (int j = t; j < 2640; j += 256) {          // tin[cc][r][c]
            int cc = j / 660, rem = j - cc * 660, r = rem / 66, c = rem - r * 66;
            int iy = 2 * y0 - 1 + r, ix = c - 1;
            bool p = ((unsigned)iy < 64u) & ((unsigned)ix < 64u);
            const float* src = in0 + (ch * 4 + cc) * 4096 + (p ? iy * 64 + ix : 0);
            cp4(tin_s + (buf * 2640 + j) * 4, src, p);
        }
        cp_commit();
    };

    load_chunk(0, 0);
    for (int ch = 0; ch < 8; ch++) {
        if (ch < 7) { load_chunk((ch + 1) & 1, ch + 1); cp_wait1(); }
        else        { cp_wait0(); }
        __syncthreads();
        const float* tb = tin + (ch & 1) * 2640;
        const float* wb = ws  + (ch & 1) * 4096;
#pragma unroll
        for (int cc = 0; cc < 4; cc++) {
#pragma unroll
            for (int ky = 0; ky < 4; ky++) {
                const float* row = tb + cc * 660 + (2 * ys + ky) * 66 + 2 * x0;
                float xr[18];
#pragma unroll
                for (int c = 0; c < 18; c++) xr[c] = row[c];
#pragma unroll
                for (int j = 0; j < 4; j++) {
                    const float* wp = wb + cc * 1024 + (obase + j) * 16 + ky * 4;
                    float w0 = wp[0], w1 = wp[1], w2 = wp[2], w3 = wp[3];
#pragma unroll
                    for (int s = 0; s < 8; s++) {
                        float a = acc[j][s];
                        a = fmaf(xr[2 * s + 0], w0, a);
                        a = fmaf(xr[2 * s + 1], w1, a);
                        a = fmaf(xr[2 * s + 2], w2, a);
                        a = fmaf(xr[2 * s + 3], w3, a);
                        acc[j][s] = a;
                    }
                }
            }
        }
        __syncthreads();
    }
    float* out0 = g_h2 + n * 65536 + (y0 + ys) * 32 + x0;
#pragma unroll
    for (int j = 0; j < 4; j++) {
        float bv = b[obase + j];
        float4 v0, v1;
        v0.x = fmaxf(acc[j][0] + bv, 0.0f); v0.y = fmaxf(acc[j][1] + bv, 0.0f);
        v0.z = fmaxf(acc[j][2] + bv, 0.0f); v0.w = fmaxf(acc[j][3] + bv, 0.0f);
        v1.x = fmaxf(acc[j][4] + bv, 0.0f); v1.y = fmaxf(acc[j][5] + bv, 0.0f);
        v1.z = fmaxf(acc[j][6] + bv, 0.0f); v1.w = fmaxf(acc[j][7] + bv, 0.0f);
        *(float4*)(out0 + (obase + j) * 1024)     = v0;
        *(float4*)(out0 + (obase + j) * 1024 + 4) = v1;
    }
}

// ---------------- conv3 / deconv1: 64->64, k3 s1 p1 — tf32 tensor-core implicit GEMM ----
// Per block: 1 image, 4 output rows (128 pixels), all 64 o-channels.
// GEMM: M=64 (o) x N=128 (pix) x K=576 (9 taps x 64 ci), k tap-major in 8-ci slices.
// Warp w: m-tile obase=(w&3)*16, n-half nbase=(w>>2)*64 (8 n-tiles of 8 pixels).
// dynamic smem: tin[2][8][6][36] (2*1728) + ws[2][8][64][9] (2*4608) = 50688 B
template <int FLIP>
__global__ void __launch_bounds__(256) conv3x3_k(const float* __restrict__ w,
                                                 const float* __restrict__ b) {
    extern __shared__ float dsm[];
    float* tin = dsm;               // [buf][ci][6][36]
    float* ws  = dsm + 3456;        // [buf][ci][o][9]
    uint32_t tin_s = (uint32_t)__cvta_generic_to_shared(tin);
    uint32_t ws_s  = (uint32_t)__cvta_generic_to_shared(ws);
    int n = blockIdx.x >> 3, y0 = (blockIdx.x & 7) * 4;
    int t = threadIdx.x;
    int wid = t >> 5, lane = t & 31;
    int g = lane >> 2, tg = lane & 3;
    int obase = (wid & 3) * 16;
    int nbase = (wid >> 2) * 64;
    int o_lo = obase + g, o_hi = o_lo + 8;
    const float* in0 = (FLIP ? g_zq : g_h2) + n * 65536;

    // per-ntile base offsets into a ci-plane (6 rows x 36 stride)
    int boff[8];
#pragma unroll
    for (int nt = 0; nt < 8; nt++) {
        int pix = nbase + nt * 8 + g;
        boff[nt] = (pix >> 5) * 36 + (pix & 31);
    }

    float acc[8][4];
#pragma unroll
    for (int nt = 0; nt < 8; nt++)
#pragma unroll
        for (int j = 0; j < 4; j++) acc[nt][j] = 0.0f;

    auto load_chunk = [&](int buf, int ch) {
        for (int j = t; j < 4608; j += 256) {          // ws[cc][o][tap]
            int cc = j / 576, rem = j - cc * 576, o = rem / 9, tap = rem - o * 9;
            int ci = ch * 8 + cc;
            const float* src = FLIP ? &w[(ci * 64 + o) * 9 + (8 - tap)]
                                    : &w[(o * 64 + ci) * 9 + tap];
            cp4(ws_s + (buf * 4608 + j) * 4, src, true);
        }
        for (int j = t; j < 1632; j += 256) {          // tin[cc][r][c], stride 36
            int cc = j / 204, rem = j - cc * 204, r = rem / 34, c = rem - r * 34;
            int iy = y0 - 1 + r, ix = c - 1;
            bool p = ((unsigned)iy < 32u) & ((unsigned)ix < 32u);
            const float* src = in0 + (ch * 8 + cc) * 1024 + (p ? iy * 32 + ix : 0);
            cp4(tin_s + (buf * 1728 + cc * 216 + r * 36 + c) * 4, src, p);
        }
        cp_commit();
    };

    load_chunk(0, 0);
    for (int ch = 0; ch < 8; ch++) {
        if (ch < 7) { load_chunk((ch + 1) & 1, ch + 1); cp_wait1(); }
        else        { cp_wait0(); }
        __syncthreads();
        const float* tb = tin + (ch & 1) * 1728;
        const float* wb = ws  + (ch & 1) * 4608;
#pragma unroll
        for (int tap = 0; tap < 9; tap++) {
            int ky = tap / 3, kx = tap - ky * 3;
            // A fragment: rows o_lo/o_hi, k-cols tg / tg+4 (ci within octet)
            const float* wpb = wb + tap;
            uint32_t ra0 = f2tf(wpb[(tg * 64 + o_lo) * 9]);
            uint32_t ra1 = f2tf(wpb[(tg * 64 + o_hi) * 9]);
            uint32_t ra2 = f2tf(wpb[((tg + 4) * 64 + o_lo) * 9]);
            uint32_t ra3 = f2tf(wpb[((tg + 4) * 64 + o_hi) * 9]);
            const float* tpb = tb + ky * 36 + kx;
#pragma unroll
            for (int nt = 0; nt < 8; nt++) {
                uint32_t rb0 = f2tf(tpb[tg * 216 + boff[nt]]);
                uint32_t rb1 = f2tf(tpb[(tg + 4) * 216 + boff[nt]]);
                mma_tf32(acc[nt][0], acc[nt][1], acc[nt][2], acc[nt][3],
                         ra0, ra1, ra2, ra3, rb0, rb1);
            }
        }
        __syncthreads();
    }

    // epilogue: thread holds (o_lo, o_hi) x (pc, pc+1) per n-tile
    float bv_lo = b[o_lo], bv_hi = b[o_hi];
    float* outbase = (FLIP ? g_h2 : g_z) + n * 65536 + y0 * 32;
#pragma unroll
    for (int nt = 0; nt < 8; nt++) {
        int pc = nbase + nt * 8 + tg * 2;
        float v0 = acc[nt][0] + bv_lo, v1 = acc[nt][1] + bv_lo;
        float v2 = acc[nt][2] + bv_hi, v3 = acc[nt][3] + bv_hi;
        if (FLIP) {
            v0 = fmaxf(v0, 0.0f); v1 = fmaxf(v1, 0.0f);
            v2 = fmaxf(v2, 0.0f); v3 = fmaxf(v3, 0.0f);
        }
        *(float2*)(outbase + o_lo * 1024 + pc) = make_float2(v0, v1);
        *(float2*)(outbase + o_hi * 1024 + pc) = make_float2(v2, v3);
    }
}

// ---------------- quantize: argmin over 128 codes, dim 64 ----------------
__global__ void __launch_bounds__(256) quantize_k(const float* __restrict__ cb,
                                                  float* out) {
    __shared__ float4 cbs[2048];
    __shared__ float cn[128];
    __shared__ float red[256];
    int t = threadIdx.x;
    for (int i = t; i < 2048; i += 256) cbs[i] = ((const float4*)cb)[i];
    __syncthreads();
    if (t < 128) {
        float s = 0.0f;
        const float4* cp = cbs + t * 16;
#pragma unroll
        for (int d = 0; d < 16; d++) {
            float4 c = cp[d];
            s = fmaf(c.x, c.x, s); s = fmaf(c.y, c.y, s);
            s = fmaf(c.z, c.z, s); s = fmaf(c.w, c.w, s);
        }
        cn[t] = s;
    }
    __syncthreads();

    int p = blockIdx.x * 256 + t;
    int hw = p & 1023, n = p >> 10;
    const float* zp = g_z + n * 65536 + hw;
    float zr[64];
#pragma unroll
    for (int d = 0; d < 64; d++) zr[d] = zp[d * 1024];

    int best = 0;
    float bestv = 3.4e38f;
    for (int e = 0; e < 128; e++) {
        const float4* cp = cbs + e * 16;
        float dot = 0.0f;
#pragma unroll
        for (int d = 0; d < 16; d++) {
            float4 c = cp[d];
            dot = fmaf(zr[4 * d + 0], c.x, dot);
            dot = fmaf(zr[4 * d + 1], c.y, dot);
            dot = fmaf(zr[4 * d + 2], c.z, dot);
            dot = fmaf(zr[4 * d + 3], c.w, dot);
        }
        float sc = cn[e] - 2.0f * dot;
        if (sc < bestv) { bestv = sc; best = e; }
    }

    float vs = 0.0f;
    float* zqp = g_zq + n * 65536 + hw;
    const float* cbest = (const float*)(cbs + best * 16);
#pragma unroll
    for (int d = 0; d < 64; d++) {
        float c = cbest[d];
        zqp[d * 1024] = c;
        float df = zr[d] - c;
        vs = fmaf(df, df, vs);
    }

    red[t] = vs;
    __syncthreads();
    for (int s = 128; s > 0; s >>= 1) {
        if (t < s) red[t] += red[t + s];
        __syncthreads();
    }
    if (t == 0) atomicAdd(out + N_XREC + 1, red[0] * (1.0f / (float)N_Z));
}

// ---------------- deconv2: 64->32, k4 s2 p1, relu (double-buffered, static) ----------------
__global__ void __launch_bounds__(256) deconv2t_k(const float* __restrict__ w,
                                                  const float* __restrict__ b) {
    __shared__ float tin[2][8][4][34];   // 2*1088
    __shared__ float ws[2][4096];        // [buf][ci*512 + o*16 + tap]
    uint32_t tin_s = (uint32_t)__cvta_generic_to_shared(&tin[0][0][0][0]);
    uint32_t ws_s  = (uint32_t)__cvta_generic_to_shared(&ws[0][0]);
    int n = blockIdx.x >> 4, y0 = (blockIdx.x & 15) * 4;
    int t = threadIdx.x;
    int obase = (t >> 5) * 4;
    int sslot = t & 31;
    int ys = sslot >> 3, x0 = (sslot & 7) * 8;

    int yo = y0 + ys;
    int ky0 = (yo + 1) & 1;
    int yiA = (yo + 1 - ky0) >> 1;
    int rowA = yiA - (y0 >> 1) + 1;
    int rowB = rowA - 1;
    int cbase = x0 >> 1;

    float acc[4][8];
#pragma unroll
    for (int j = 0; j < 4; j++)
#pragma unroll
        for (int s = 0; s < 8; s++) acc[j][s] = 0.0f;

    const float* in0 = g_h2 + n * 65536;
    auto load_chunk = [&](int buf, int ch) {
        for (int j = t; j < 1024; j += 256)
            cp16(ws_s + (buf * 4096 + j * 4) * 4, w + ch * 4096 + j * 4);
        for (int j = t; j < 1088; j += 256) {
            int cc = j / 136, rem = j - cc * 136, r = rem / 34, c = rem - r * 34;
            int yi = (y0 >> 1) - 1 + r, xi = c - 1;
            bool p = ((unsigned)yi < 32u) & ((unsigned)xi < 32u);
            const float* src = in0 + (ch * 8 + cc) * 1024 + (p ? yi * 32 + xi : 0);
            cp4(tin_s + (buf * 1088 + j) * 4, src, p);
        }
        cp_commit();
    };

    load_chunk(0, 0);
    for (int ch = 0; ch < 8; ch++) {
        if (ch < 7) { load_chunk((ch + 1) & 1, ch + 1); cp_wait1(); }
        else        { cp_wait0(); }
        __syncthreads();
        int buf = ch & 1;
#pragma unroll 2
        for (int cc = 0; cc < 8; cc++) {
            float a[6], bb[6];
#pragma unroll
            for (int c = 0; c < 6; c++) {
                a[c]  = tin[buf][cc][rowA][cbase + c];
                bb[c] = tin[buf][cc][rowB][cbase + c];
            }
#pragma unroll
            for (int j = 0; j < 4; j++) {
                const float* wp = &ws[buf][cc * 512 + (obase + j) * 16];
                float wk0 = wp[ky0 * 4 + 0], wk1 = wp[ky0 * 4 + 1];
                float wk2 = wp[ky0 * 4 + 2], wk3 = wp[ky0 * 4 + 3];
                float wk4 = wp[(ky0 + 2) * 4 + 0], wk5 = wp[(ky0 + 2) * 4 + 1];
                float wk6 = wp[(ky0 + 2) * 4 + 2], wk7 = wp[(ky0 + 2) * 4 + 3];
#pragma unroll
                for (int s = 0; s < 8; s++) {
                    int ia = (s >> 1) + (s & 1) + 1, ib = ia - 1;
                    float v = acc[j][s];
                    if (s & 1) {
                        v = fmaf(a[ia],  wk0, v);
                        v = fmaf(a[ib],  wk2, v);
                        v = fmaf(bb[ia], wk4, v);
                        v = fmaf(bb[ib], wk6, v);
                    } else {
                        v = fmaf(a[ia],  wk1, v);
                        v = fmaf(a[ib],  wk3, v);
                        v = fmaf(bb[ia], wk5, v);
                        v = fmaf(bb[ib], wk7, v);
                    }
                    acc[j][s] = v;
                }
            }
        }
        __syncthreads();
    }
    float* out0 = g_h1 + n * 131072 + yo * 64 + x0;
#pragma unroll
    for (int j = 0; j < 4; j++) {
        float bv = b[obase + j];
        float4 v0, v1;
        v0.x = fmaxf(acc[j][0] + bv, 0.0f); v0.y = fmaxf(acc[j][1] + bv, 0.0f);
        v0.z = fmaxf(acc[j][2] + bv, 0.0f); v0.w = fmaxf(acc[j][3] + bv, 0.0f);
        v1.x = fmaxf(acc[j][4] + bv, 0.0f); v1.y = fmaxf(acc[j][5] + bv, 0.0f);
        v1.z = fmaxf(acc[j][6] + bv, 0.0f); v1.w = fmaxf(acc[j][7] + bv, 0.0f);
        *(float4*)(out0 + (obase + j) * 4096)     = v0;
        *(float4*)(out0 + (obase + j) * 4096 + 4) = v1;
    }
}

// ---------------- deconv3: 32->1, k4 s2 p1, sigmoid + recon loss (double-buffered) ----------------
__global__ void __launch_bounds__(256) deconv3t_k(const float* __restrict__ xin,
                                                  const float* __restrict__ w,
                                                  const float* __restrict__ b,
                                                  float* out) {
    __shared__ float tin[2][8][10][66];  // 2*5280
    __shared__ float ws3[512];
    __shared__ float red[256];
    uint32_t tin_s = (uint32_t)__cvta_generic_to_shared(&tin[0][0][0][0]);
    int n = blockIdx.x >> 3, y0 = (blockIdx.x & 7) * 16;
    int t = threadIdx.x;
    int ys = t >> 4, x0 = (t & 15) * 8;
    int yo = y0 + ys;
    int ky0 = (yo + 1) & 1;
    int yiA = (yo + 1 - ky0) >> 1;
    int rowA = yiA - (y0 >> 1) + 1;
    int rowB = rowA - 1;
    int cbase = x0 >> 1;

    for (int j = t; j < 512; j += 256) ws3[j] = w[j];

    float acc[8];
#pragma unroll
    for (int s = 0; s < 8; s++) acc[s] = 0.0f;

    const float* in0 = g_h1 + n * 131072;
    auto load_chunk = [&](int buf, int ch) {
        for (int j = t; j < 5280; j += 256) {
            int cc = j / 660, rem = j - cc * 660, r = rem / 66, c = rem - r * 66;
            int yi = (y0 >> 1) - 1 + r, xi = c - 1;
            bool p = ((unsigned)yi < 64u) & ((unsigned)xi < 64u);
            const float* src = in0 + (ch * 8 + cc) * 4096 + (p ? yi * 64 + xi : 0);
            cp4(tin_s + (buf * 5280 + j) * 4, src, p);
        }
        cp_commit();
    };

    load_chunk(0, 0);
    for (int ch = 0; ch < 4; ch++) {
        if (ch < 3) { load_chunk((ch + 1) & 1, ch + 1); cp_wait1(); }
        else        { cp_wait0(); }
        __syncthreads();
        int buf = ch & 1;
#pragma unroll 2
        for (int cc = 0; cc < 8; cc++) {
            float a[6], bb[6];
#pragma unroll
            for (int c = 0; c < 6; c++) {
                a[c]  = tin[buf][cc][rowA][cbase + c];
                bb[c] = tin[buf][cc][rowB][cbase + c];
            }
            int ci = ch * 8 + cc;
            const float* wp = &ws3[ci * 16];
            float wa0 = wp[ky0 * 4 + 0], wa1 = wp[ky0 * 4 + 1];
            float wa2 = wp[ky0 * 4 + 2], wa3 = wp[ky0 * 4 + 3];
            float wb0 = wp[(ky0 + 2) * 4 + 0], wb1 = wp[(ky0 + 2) * 4 + 1];
            float wb2 = wp[(ky0 + 2) * 4 + 2], wb3 = wp[(ky0 + 2) * 4 + 3];
#pragma unroll
            for (int s = 0; s < 8; s++) {
                int ia = (s >> 1) + (s & 1) + 1, ib = ia - 1;
                float v = acc[s];
                if (s & 1) {
                    v = fmaf(a[ia],  wa0, v);
                    v = fmaf(a[ib],  wa2, v);
                    v = fmaf(bb[ia], wb0, v);
                    v = fmaf(bb[ib], wb2, v);
                } else {
                    v = fmaf(a[ia],  wa1, v);
                    v = fmaf(a[ib],  wa3, v);
                    v = fmaf(bb[ia], wb1, v);
                    v = fmaf(bb[ib], wb3, v);
                }
                acc[s] = v;
            }
        }
        __syncthreads();
    }

    float b0 = b[0];
    const float* xp = xin + n * 16384 + yo * 128 + x0;
    float* op = out + n * 16384 + yo * 128 + x0;
    float ls = 0.0f;
    float rv[8];
#pragma unroll
    for (int s = 0; s < 8; s++) {
        float r = 1.0f / (1.0f + expf(-(acc[s] + b0)));
        rv[s] = r;
        float df = r - xp[s];
        ls = fmaf(df, df, ls);
    }
    *(float4*)(op)     = make_float4(rv[0], rv[1], rv[2], rv[3]);
    *(float4*)(op + 4) = make_float4(rv[4], rv[5], rv[6], rv[7]);

    red[t] = ls;
    __syncthreads();
    for (int s = 128; s > 0; s >>= 1) {
        if (t < s) red[t] += red[t + s];
        __syncthreads();
    }
    if (t == 0) atomicAdd(out + N_XREC, red[0] * (1.0f / (float)N_XREC));
}

// ---------------- launch ----------------
extern "C" void kernel_launch(void* const* d_in, const int* in_sizes, int n_in,
                              void* d_out, int out_size) {
    const float* x   = (const float*)d_in[0];
    const float* w1  = (const float*)d_in[1];
    const float* b1  = (const float*)d_in[2];
    const float* w2  = (const float*)d_in[3];
    const float* b2  = (const float*)d_in[4];
    const float* w3  = (const float*)d_in[5];
    const float* b3  = (const float*)d_in[6];
    const float* cb  = (const float*)d_in[7];
    const float* dw1 = (const float*)d_in[8];
    const float* db1 = (const float*)d_in[9];
    const float* dw2 = (const float*)d_in[10];
    const float* db2 = (const float*)d_in[11];
    const float* dw3 = (const float*)d_in[12];
    const float* db3 = (const float*)d_in[13];
    float* out = (float*)d_out;

    static bool attr_done = false;
    if (!attr_done) {
        cudaFuncSetAttribute(conv2t_k, cudaFuncAttributeMaxDynamicSharedMemorySize, 53888);
        cudaFuncSetAttribute(conv3x3_k<0>, cudaFuncAttributeMaxDynamicSharedMemorySize, 50688);
        cudaFuncSetAttribute(conv3x3_k<1>, cudaFuncAttributeMaxDynamicSharedMemorySize, 50688);
        attr_done = true;
    }

    zero_losses_k<<<1, 32>>>(out);
    conv1_k   <<<2048, 256>>>(x, w1, b1);
    conv2t_k  <<<1024, 256, 53888>>>(w2, b2);
    conv3x3_k<0><<<1024, 256, 50688>>>(w3, b3);
    quantize_k<<<512,  256>>>(cb, out);
    conv3x3_k<1><<<1024, 256, 50688>>>(dw1, db1);
    deconv2t_k<<<2048, 256>>>(dw2, db2);
    deconv3t_k<<<1024, 256>>>(x, dw3, db3, out);
}

// round 7
// speedup vs baseline: 1.8627x; 1.1083x over previous
#include <cuda_runtime.h>
#include <stdint.h>
#include <math.h>

// ---------------- geometry ----------------
// x      : [128,  1, 128, 128]
// h1     : [128, 32,  64,  64]   conv1 k4 s2 p1 + relu        (g_h1, reused for d2)
// h2     : [128, 64,  32,  32]   conv2 k4 s2 p1 + relu [tf32] (g_h2, reused for d1)
// z      : [128, 64,  32,  32]   conv3 k3 s1 p1 (tf32 mma)    (g_z)
// z_q    : [128, 64,  32,  32]   codebook gather [tf32]       (g_zq)
// x_rec  : [128,  1, 128, 128]   -> d_out[0 : 2097152]
// d_out[2097152] = recon_loss, d_out[2097153] = vq_loss

#define N_XREC   2097152
#define N_Z      8388608

__device__ float g_h1[128 * 32 * 64 * 64];
__device__ float g_h2[128 * 64 * 32 * 32];
__device__ float g_z [128 * 64 * 32 * 32];
__device__ float g_zq[128 * 64 * 32 * 32];
// tf32-rounded 3x3 weights: [set][ch(8)][tap(9)][k(8)][72]  (o padded 64->72)
__device__ float g_wt[2 * 41472];

// ---------------- cp.async helpers ----------------
__device__ __forceinline__ void cp4(uint32_t dst, const float* src, bool p) {
    asm volatile("cp.async.ca.shared.global [%0], [%1], 4, %2;"
                 :: "r"(dst), "l"(src), "r"(p ? 4u : 0u));
}
__device__ __forceinline__ void cp16(uint32_t dst, const float* src) {
    asm volatile("cp.async.ca.shared.global [%0], [%1], 16;"
                 :: "r"(dst), "l"(src));
}
__device__ __forceinline__ void cp_commit() {
    asm volatile("cp.async.commit_group;");
}
__device__ __forceinline__ void cp_wait1() {
    asm volatile("cp.async.wait_group 1;");
}
__device__ __forceinline__ void cp_wait0() {
    asm volatile("cp.async.wait_group 0;");
}

// ---------------- tf32 mma helpers ----------------
__device__ __forceinline__ uint32_t f2tf(float f) {
    uint32_t r; asm("cvt.rna.tf32.f32 %0, %1;" : "=r"(r) : "f"(f)); return r;
}
__device__ __forceinline__ float f2tf_f(float f) {
    uint32_t r = f2tf(f); return __uint_as_float(r);
}
__device__ __forceinline__ void mma_tf32(float& d0, float& d1, float& d2, float& d3,
                                         uint32_t a0, uint32_t a1, uint32_t a2, uint32_t a3,
                                         uint32_t b0, uint32_t b1) {
    asm volatile("mma.sync.aligned.m16n8k8.row.col.f32.tf32.tf32.f32 "
                 "{%0,%1,%2,%3}, {%4,%5,%6,%7}, {%8,%9}, {%0,%1,%2,%3};"
                 : "+f"(d0), "+f"(d1), "+f"(d2), "+f"(d3)
                 : "r"(a0), "r"(a1), "r"(a2), "r"(a3), "r"(b0), "r"(b1));
}

__global__ void zero_losses_k(float* out) {
    if (threadIdx.x == 0) { out[N_XREC] = 0.0f; out[N_XREC + 1] = 0.0f; }
}

// ---------------- weight prep: round 3x3 weights to tf32, mma-friendly layout ----
// g_wt[set]: idx = ((ch*9 + tap)*8 + k)*72 + o ; ci = ch*8 + k
__global__ void __launch_bounds__(256) prep_w_k(const float* __restrict__ w3,
                                                const float* __restrict__ dw1) {
    int i = blockIdx.x * 256 + threadIdx.x;          // 82944 total
    int set = i / 41472, r = i - set * 41472;
    int o = r % 72, q = r / 72;
    int k = q & 7, q2 = q >> 3;
    int tap = q2 % 9, ch = q2 / 9;
    int ci = ch * 8 + k;
    float v = 0.0f;
    if (o < 64) v = set ? dw1[(ci * 64 + o) * 9 + (8 - tap)]
                        : w3[(o * 64 + ci) * 9 + tap];
    g_wt[i] = f2tf_f(v);
}

// ---------------- conv1: 1->32, k4 s2 p1, relu ----------------
__global__ void __launch_bounds__(256) conv1_k(const float* __restrict__ x,
                                               const float* __restrict__ w,
                                               const float* __restrict__ b) {
    __shared__ float tin[10][132];
    __shared__ float ws[512];
    __shared__ float bs[32];
    int n = blockIdx.x >> 4, y0 = (blockIdx.x & 15) * 4;
    int t = threadIdx.x;
    int xo = t & 63, ys = t >> 6, yo = y0 + ys;
    for (int i = t; i < 512; i += 256) ws[i] = w[i];
    if (t < 32) bs[t] = b[t];
    const float* xp = x + n * 16384;
    for (int j = t; j < 1320; j += 256) {
        int r = j / 132, c = j - r * 132;
        int iy = 2 * y0 - 1 + r, ix = c - 1;
        float v = 0.0f;
        if ((unsigned)iy < 128u && (unsigned)ix < 128u) v = xp[iy * 128 + ix];
        tin[r][c] = v;
    }
    __syncthreads();

    float xin[16];
#pragma unroll
    for (int ky = 0; ky < 4; ky++)
#pragma unroll
        for (int kx = 0; kx < 4; kx++)
            xin[ky * 4 + kx] = tin[2 * ys + ky][2 * xo + kx];

    float* outp = g_h1 + n * 131072 + yo * 64 + xo;
#pragma unroll 4
    for (int o = 0; o < 32; o++) {
        float acc = bs[o];
#pragma unroll
        for (int k = 0; k < 16; k++) acc = fmaf(xin[k], ws[o * 16 + k], acc);
        outp[o * 4096] = fmaxf(acc, 0.0f);
    }
}

// ---------------- conv2: 32->64, k4 s2 p1, relu (FFMA); output tf32-rounded ----
// dynamic smem: tin[2][4][10][66] (2*2640) + ws[2][4][64][16] (2*4096) = 53888 B
__global__ void __launch_bounds__(256) conv2t_k(const float* __restrict__ w,
                                                const float* __restrict__ b) {
    extern __shared__ float dsm[];
    float* tin = dsm;               // [buf][cc][10][66]
    float* ws  = dsm + 5280;        // [buf][cc][o][16]
    uint32_t tin_s = (uint32_t)__cvta_generic_to_shared(tin);
    uint32_t ws_s  = (uint32_t)__cvta_generic_to_shared(ws);
    int n = blockIdx.x >> 3, y0 = (blockIdx.x & 7) * 4;
    int t = threadIdx.x;
    int obase = (t >> 4) * 4;
    int sslot = t & 15;
    int ys = sslot >> 2, x0 = (sslot & 3) * 8;
    const float* in0 = g_h1 + n * 131072;

    float acc[4][8];
#pragma unroll
    for (int j = 0; j < 4; j++)
#pragma unroll
        for (int s = 0; s < 8; s++) acc[j][s] = 0.0f;

    auto load_chunk = [&](int buf, int ch) {
        for (int j = t; j < 4096; j += 256) {          // ws[cc][o][tap]
            int cc = j >> 10, rem = j & 1023, o = rem >> 4, tap = rem & 15;
            cp4(ws_s + (buf * 4096 + j) * 4,
                &w[(o * 32 + ch * 4 + cc) * 16 + tap], true);
        }
        for (int j = t; j < 2640; j += 256) {          // tin[cc][r][c]
            int cc = j / 660, rem = j - cc * 660, r = rem / 66, c = rem - r * 66;
            int iy = 2 * y0 - 1 + r, ix = c - 1;
            bool p = ((unsigned)iy < 64u) & ((unsigned)ix < 64u);
            const float* src = in0 + (ch * 4 + cc) * 4096 + (p ? iy * 64 + ix : 0);
            cp4(tin_s + (buf * 2640 + j) * 4, src, p);
        }
        cp_commit();
    };

    load_chunk(0, 0);
    for (int ch = 0; ch < 8; ch++) {
        if (ch < 7) { load_chunk((ch + 1) & 1, ch + 1); cp_wait1(); }
        else        { cp_wait0(); }
        __syncthreads();
        const float* tb = tin + (ch & 1) * 2640;
        const float* wb = ws  + (ch & 1) * 4096;
#pragma unroll
        for (int cc = 0; cc < 4; cc++) {
#pragma unroll
            for (int ky = 0; ky < 4; ky++) {
                const float* row = tb + cc * 660 + (2 * ys + ky) * 66 + 2 * x0;
                float xr[18];
#pragma unroll
                for (int c = 0; c < 18; c++) xr[c] = row[c];
#pragma unroll
                for (int j = 0; j < 4; j++) {
                    const float* wp = wb + cc * 1024 + (obase + j) * 16 + ky * 4;
                    float w0 = wp[0], w1 = wp[1], w2 = wp[2], w3 = wp[3];
#pragma unroll
                    for (int s = 0; s < 8; s++) {
                        float a = acc[j][s];
                        a = fmaf(xr[2 * s + 0], w0, a);
                        a = fmaf(xr[2 * s + 1], w1, a);
                        a = fmaf(xr[2 * s + 2], w2, a);
                        a = fmaf(xr[2 * s + 3], w3, a);
                        acc[j][s] = a;
                    }
                }
            }
        }
        __syncthreads();
    }
    float* out0 = g_h2 + n * 65536 + (y0 + ys) * 32 + x0;
#pragma unroll
    for (int j = 0; j < 4; j++) {
        float bv = b[obase + j];
        float4 v0, v1;
        v0.x = f2tf_f(fmaxf(acc[j][0] + bv, 0.0f));
        v0.y = f2tf_f(fmaxf(acc[j][1] + bv, 0.0f));
        v0.z = f2tf_f(fmaxf(acc[j][2] + bv, 0.0f));
        v0.w = f2tf_f(fmaxf(acc[j][3] + bv, 0.0f));
        v1.x = f2tf_f(fmaxf(acc[j][4] + bv, 0.0f));
        v1.y = f2tf_f(fmaxf(acc[j][5] + bv, 0.0f));
        v1.z = f2tf_f(fmaxf(acc[j][6] + bv, 0.0f));
        v1.w = f2tf_f(fmaxf(acc[j][7] + bv, 0.0f));
        *(float4*)(out0 + (obase + j) * 1024)     = v0;
        *(float4*)(out0 + (obase + j) * 1024 + 4) = v1;
    }
}

// ---------------- conv3 / deconv1: tf32 mma, pre-rounded operands ----------------
// GEMM: M=64 (o) x N=128 (pix) x K=576. Operands already tf32 bits in gmem.
// smem: tin[2][8][6][36] (2*1728) + ws[2][9*8][72] (2*5184) = 55296 B
template <int SET>
__global__ void __launch_bounds__(256) conv3x3_k(const float* __restrict__ b) {
    extern __shared__ float dsm[];
    float* tin = dsm;               // [buf][ci][6][36]
    float* ws  = dsm + 3456;        // [buf][(tap*8 + k)][72]
    uint32_t tin_s = (uint32_t)__cvta_generic_to_shared(tin);
    uint32_t ws_s  = (uint32_t)__cvta_generic_to_shared(ws);
    int n = blockIdx.x >> 3, y0 = (blockIdx.x & 7) * 4;
    int t = threadIdx.x;
    int wid = t >> 5, lane = t & 31;
    int g = lane >> 2, tg = lane & 3;
    int obase = (wid & 3) * 16;
    int nbase = (wid >> 2) * 64;
    int o_lo = obase + g, o_hi = o_lo + 8;
    const float* in0 = (SET ? g_zq : g_h2) + n * 65536;
    const float* wsrc = g_wt + SET * 41472;

    int boff[8];
#pragma unroll
    for (int nt = 0; nt < 8; nt++) {
        int pix = nbase + nt * 8 + g;
        boff[nt] = (pix >> 5) * 36 + (pix & 31);
    }

    float acc[8][4];
#pragma unroll
    for (int nt = 0; nt < 8; nt++)
#pragma unroll
        for (int j = 0; j < 4; j++) acc[nt][j] = 0.0f;

    auto load_chunk = [&](int buf, int ch) {
        const float* src = wsrc + ch * 5184;           // contiguous [tap][k][72]
        for (int j = t; j < 1296; j += 256)
            cp16(ws_s + (buf * 5184 + j * 4) * 4, src + j * 4);
        for (int j = t; j < 1632; j += 256) {          // tin[cc][r][c], stride 36
            int cc = j / 204, rem = j - cc * 204, r = rem / 34, c = rem - r * 34;
            int iy = y0 - 1 + r, ix = c - 1;
            bool p = ((unsigned)iy < 32u) & ((unsigned)ix < 32u);
            const float* s2 = in0 + (ch * 8 + cc) * 1024 + (p ? iy * 32 + ix : 0);
            cp4(tin_s + (buf * 1728 + cc * 216 + r * 36 + c) * 4, s2, p);
        }
        cp_commit();
    };

    load_chunk(0, 0);
    for (int ch = 0; ch < 8; ch++) {
        if (ch < 7) { load_chunk((ch + 1) & 1, ch + 1); cp_wait1(); }
        else        { cp_wait0(); }
        __syncthreads();
        const float* tb = tin + (ch & 1) * 1728;
        const float* wb = ws  + (ch & 1) * 5184;
#pragma unroll
        for (int tap = 0; tap < 9; tap++) {
            int ky = tap / 3, kx = tap - ky * 3;
            const float* wpb = wb + tap * 576;         // [k][72]
            uint32_t ra0 = *(const uint32_t*)&wpb[tg * 72 + o_lo];
            uint32_t ra1 = *(const uint32_t*)&wpb[tg * 72 + o_hi];
            uint32_t ra2 = *(const uint32_t*)&wpb[(tg + 4) * 72 + o_lo];
            uint32_t ra3 = *(const uint32_t*)&wpb[(tg + 4) * 72 + o_hi];
            const float* tpb = tb + ky * 36 + kx;
#pragma unroll
            for (int nt = 0; nt < 8; nt++) {
                uint32_t rb0 = *(const uint32_t*)&tpb[tg * 216 + boff[nt]];
                uint32_t rb1 = *(const uint32_t*)&tpb[(tg + 4) * 216 + boff[nt]];
                mma_tf32(acc[nt][0], acc[nt][1], acc[nt][2], acc[nt][3],
                         ra0, ra1, ra2, ra3, rb0, rb1);
            }
        }
        __syncthreads();
    }

    float bv_lo = b[o_lo], bv_hi = b[o_hi];
    float* outbase = (SET ? g_h2 : g_z) + n * 65536 + y0 * 32;
#pragma unroll
    for (int nt = 0; nt < 8; nt++) {
        int pc = nbase + nt * 8 + tg * 2;
        float v0 = acc[nt][0] + bv_lo, v1 = acc[nt][1] + bv_lo;
        float v2 = acc[nt][2] + bv_hi, v3 = acc[nt][3] + bv_hi;
        if (SET) {
            v0 = fmaxf(v0, 0.0f); v1 = fmaxf(v1, 0.0f);
            v2 = fmaxf(v2, 0.0f); v3 = fmaxf(v3, 0.0f);
        }
        *(float2*)(outbase + o_lo * 1024 + pc) = make_float2(v0, v1);
        *(float2*)(outbase + o_hi * 1024 + pc) = make_float2(v2, v3);
    }
}

// ---------------- quantize: argmin over 128 codes, dim 64; z_q stored tf32 ----
__global__ void __launch_bounds__(256) quantize_k(const float* __restrict__ cb,
                                                  float* out) {
    __shared__ float4 cbs[2048];
    __shared__ float cn[128];
    __shared__ float red[256];
    int t = threadIdx.x;
    for (int i = t; i < 2048; i += 256) cbs[i] = ((const float4*)cb)[i];
    __syncthreads();
    if (t < 128) {
        float s = 0.0f;
        const float4* cp = cbs + t * 16;
#pragma unroll
        for (int d = 0; d < 16; d++) {
            float4 c = cp[d];
            s = fmaf(c.x, c.x, s); s = fmaf(c.y, c.y, s);
            s = fmaf(c.z, c.z, s); s = fmaf(c.w, c.w, s);
        }
        cn[t] = s;
    }
    __syncthreads();

    int p = blockIdx.x * 256 + t;
    int hw = p & 1023, n = p >> 10;
    const float* zp = g_z + n * 65536 + hw;
    float zr[64];
#pragma unroll
    for (int d = 0; d < 64; d++) zr[d] = zp[d * 1024];

    int best = 0;
    float bestv = 3.4e38f;
    for (int e = 0; e < 128; e++) {
        const float4* cp = cbs + e * 16;
        float dot = 0.0f;
#pragma unroll
        for (int d = 0; d < 16; d++) {
            float4 c = cp[d];
            dot = fmaf(zr[4 * d + 0], c.x, dot);
            dot = fmaf(zr[4 * d + 1], c.y, dot);
            dot = fmaf(zr[4 * d + 2], c.z, dot);
            dot = fmaf(zr[4 * d + 3], c.w, dot);
        }
        float sc = cn[e] - 2.0f * dot;
        if (sc < bestv) { bestv = sc; best = e; }
    }

    float vs = 0.0f;
    float* zqp = g_zq + n * 65536 + hw;
    const float* cbest = (const float*)(cbs + best * 16);
#pragma unroll
    for (int d = 0; d < 64; d++) {
        float c = cbest[d];
        zqp[d * 1024] = f2tf_f(c);      // deconv1 reads tf32 bits
        float df = zr[d] - c;           // loss uses exact codebook value
        vs = fmaf(df, df, vs);
    }

    red[t] = vs;
    __syncthreads();
    for (int s = 128; s > 0; s >>= 1) {
        if (t < s) red[t] += red[t + s];
        __syncthreads();
    }
    if (t == 0) atomicAdd(out + N_XREC + 1, red[0] * (1.0f / (float)N_Z));
}

// ---------------- deconv2: 64->32, k4 s2 p1, relu (double-buffered, static) ----------------
__global__ void __launch_bounds__(256) deconv2t_k(const float* __restrict__ w,
                                                  const float* __restrict__ b) {
    __shared__ float tin[2][8][4][34];   // 2*1088
    __shared__ float ws[2][4096];        // [buf][ci*512 + o*16 + tap]
    uint32_t tin_s = (uint32_t)__cvta_generic_to_shared(&tin[0][0][0][0]);
    uint32_t ws_s  = (uint32_t)__cvta_generic_to_shared(&ws[0][0]);
    int n = blockIdx.x >> 4, y0 = (blockIdx.x & 15) * 4;
    int t = threadIdx.x;
    int obase = (t >> 5) * 4;
    int sslot = t & 31;
    int ys = sslot >> 3, x0 = (sslot & 7) * 8;

    int yo = y0 + ys;
    int ky0 = (yo + 1) & 1;
    int yiA = (yo + 1 - ky0) >> 1;
    int rowA = yiA - (y0 >> 1) + 1;
    int rowB = rowA - 1;
    int cbase = x0 >> 1;

    float acc[4][8];
#pragma unroll
    for (int j = 0; j < 4; j++)
#pragma unroll
        for (int s = 0; s < 8; s++) acc[j][s] = 0.0f;

    const float* in0 = g_h2 + n * 65536;
    auto load_chunk = [&](int buf, int ch) {
        for (int j = t; j < 1024; j += 256)
            cp16(ws_s + (buf * 4096 + j * 4) * 4, w + ch * 4096 + j * 4);
        for (int j = t; j < 1088; j += 256) {
            int cc = j / 136, rem = j - cc * 136, r = rem / 34, c = rem - r * 34;
            int yi = (y0 >> 1) - 1 + r, xi = c - 1;
            bool p = ((unsigned)yi < 32u) & ((unsigned)xi < 32u);
            const float* src = in0 + (ch * 8 + cc) * 1024 + (p ? yi * 32 + xi : 0);
            cp4(tin_s + (buf * 1088 + j) * 4, src, p);
        }
        cp_commit();
    };

    load_chunk(0, 0);
    for (int ch = 0; ch < 8; ch++) {
        if (ch < 7) { load_chunk((ch + 1) & 1, ch + 1); cp_wait1(); }
        else        { cp_wait0(); }
        __syncthreads();
        int buf = ch & 1;
#pragma unroll 2
        for (int cc = 0; cc < 8; cc++) {
            float a[6], bb[6];
#pragma unroll
            for (int c = 0; c < 6; c++) {
                a[c]  = tin[buf][cc][rowA][cbase + c];
                bb[c] = tin[buf][cc][rowB][cbase + c];
            }
#pragma unroll
            for (int j = 0; j < 4; j++) {
                const float* wp = &ws[buf][cc * 512 + (obase + j) * 16];
                float wk0 = wp[ky0 * 4 + 0], wk1 = wp[ky0 * 4 + 1];
                float wk2 = wp[ky0 * 4 + 2], wk3 = wp[ky0 * 4 + 3];
                float wk4 = wp[(ky0 + 2) * 4 + 0], wk5 = wp[(ky0 + 2) * 4 + 1];
                float wk6 = wp[(ky0 + 2) * 4 + 2], wk7 = wp[(ky0 + 2) * 4 + 3];
#pragma unroll
                for (int s = 0; s < 8; s++) {
                    int ia = (s >> 1) + (s & 1) + 1, ib = ia - 1;
                    float v = acc[j][s];
                    if (s & 1) {
                        v = fmaf(a[ia],  wk0, v);
                        v = fmaf(a[ib],  wk2, v);
                        v = fmaf(bb[ia], wk4, v);
                        v = fmaf(bb[ib], wk6, v);
                    } else {
                        v = fmaf(a[ia],  wk1, v);
                        v = fmaf(a[ib],  wk3, v);
                        v = fmaf(bb[ia], wk5, v);
                        v = fmaf(bb[ib], wk7, v);
                    }
                    acc[j][s] = v;
                }
            }
        }
        __syncthreads();
    }
    float* out0 = g_h1 + n * 131072 + yo * 64 + x0;
#pragma unroll
    for (int j = 0; j < 4; j++) {
        float bv = b[obase + j];
        float4 v0, v1;
        v0.x = fmaxf(acc[j][0] + bv, 0.0f); v0.y = fmaxf(acc[j][1] + bv, 0.0f);
        v0.z = fmaxf(acc[j][2] + bv, 0.0f); v0.w = fmaxf(acc[j][3] + bv, 0.0f);
        v1.x = fmaxf(acc[j][4] + bv, 0.0f); v1.y = fmaxf(acc[j][5] + bv, 0.0f);
        v1.z = fmaxf(acc[j][6] + bv, 0.0f); v1.w = fmaxf(acc[j][7] + bv, 0.0f);
        *(float4*)(out0 + (obase + j) * 4096)     = v0;
        *(float4*)(out0 + (obase + j) * 4096 + 4) = v1;
    }
}

// ---------------- deconv3: 32->1, k4 s2 p1, sigmoid + recon loss (double-buffered) ----------------
__global__ void __launch_bounds__(256) deconv3t_k(const float* __restrict__ xin,
                                                  const float* __restrict__ w,
                                                  const float* __restrict__ b,
                                                  float* out) {
    __shared__ float tin[2][8][10][66];  // 2*5280
    __shared__ float ws3[512];
    __shared__ float red[256];
    uint32_t tin_s = (uint32_t)__cvta_generic_to_shared(&tin[0][0][0][0]);
    int n = blockIdx.x >> 3, y0 = (blockIdx.x & 7) * 16;
    int t = threadIdx.x;
    int ys = t >> 4, x0 = (t & 15) * 8;
    int yo = y0 + ys;
    int ky0 = (yo + 1) & 1;
    int yiA = (yo + 1 - ky0) >> 1;
    int rowA = yiA - (y0 >> 1) + 1;
    int rowB = rowA - 1;
    int cbase = x0 >> 1;

    for (int j = t; j < 512; j += 256) ws3[j] = w[j];

    float acc[8];
#pragma unroll
    for (int s = 0; s < 8; s++) acc[s] = 0.0f;

    const float* in0 = g_h1 + n * 131072;
    auto load_chunk = [&](int buf, int ch) {
        for (int j = t; j < 5280; j += 256) {
            int cc = j / 660, rem = j - cc * 660, r = rem / 66, c = rem - r * 66;
            int yi = (y0 >> 1) - 1 + r, xi = c - 1;
            bool p = ((unsigned)yi < 64u) & ((unsigned)xi < 64u);
            const float* src = in0 + (ch * 8 + cc) * 4096 + (p ? yi * 64 + xi : 0);
            cp4(tin_s + (buf * 5280 + j) * 4, src, p);
        }
        cp_commit();
    };

    load_chunk(0, 0);
    for (int ch = 0; ch < 4; ch++) {
        if (ch < 3) { load_chunk((ch + 1) & 1, ch + 1); cp_wait1(); }
        else        { cp_wait0(); }
        __syncthreads();
        int buf = ch & 1;
#pragma unroll 2
        for (int cc = 0; cc < 8; cc++) {
            float a[6], bb[6];
#pragma unroll
            for (int c = 0; c < 6; c++) {
                a[c]  = tin[buf][cc][rowA][cbase + c];
                bb[c] = tin[buf][cc][rowB][cbase + c];
            }
            int ci = ch * 8 + cc;
            const float* wp = &ws3[ci * 16];
            float wa0 = wp[ky0 * 4 + 0], wa1 = wp[ky0 * 4 + 1];
            float wa2 = wp[ky0 * 4 + 2], wa3 = wp[ky0 * 4 + 3];
            float wb0 = wp[(ky0 + 2) * 4 + 0], wb1 = wp[(ky0 + 2) * 4 + 1];
            float wb2 = wp[(ky0 + 2) * 4 + 2], wb3 = wp[(ky0 + 2) * 4 + 3];
#pragma unroll
            for (int s = 0; s < 8; s++) {
                int ia = (s >> 1) + (s & 1) + 1, ib = ia - 1;
                float v = acc[s];
                if (s & 1) {
                    v = fmaf(a[ia],  wa0, v);
                    v = fmaf(a[ib],  wa2, v);
                    v = fmaf(bb[ia], wb0, v);
                    v = fmaf(bb[ib], wb2, v);
                } else {
                    v = fmaf(a[ia],  wa1, v);
                    v = fmaf(a[ib],  wa3, v);
                    v = fmaf(bb[ia], wb1, v);
                    v = fmaf(bb[ib], wb3, v);
                }
                acc[s] = v;
            }
        }
        __syncthreads();
    }

    float b0 = b[0];
    const float* xp = xin + n * 16384 + yo * 128 + x0;
    float* op = out + n * 16384 + yo * 128 + x0;
    float ls = 0.0f;
    float rv[8];
#pragma unroll
    for (int s = 0; s < 8; s++) {
        float r = 1.0f / (1.0f + expf(-(acc[s] + b0)));
        rv[s] = r;
        float df = r - xp[s];
        ls = fmaf(df, df, ls);
    }
    *(float4*)(op)     = make_float4(rv[0], rv[1], rv[2], rv[3]);
    *(float4*)(op + 4) = make_float4(rv[4], rv[5], rv[6], rv[7]);

    red[t] = ls;
    __syncthreads();
    for (int s = 128; s > 0; s >>= 1) {
        if (t < s) red[t] += red[t + s];
        __syncthreads();
    }
    if (t == 0) atomicAdd(out + N_XREC, red[0] * (1.0f / (float)N_XREC));
}

// ---------------- launch ----------------
extern "C" void kernel_launch(void* const* d_in, const int* in_sizes, int n_in,
                              void* d_out, int out_size) {
    const float* x   = (const float*)d_in[0];
    const float* w1  = (const float*)d_in[1];
    const float* b1  = (const float*)d_in[2];
    const float* w2  = (const float*)d_in[3];
    const float* b2  = (const float*)d_in[4];
    const float* w3  = (const float*)d_in[5];
    const float* b3  = (const float*)d_in[6];
    const float* cb  = (const float*)d_in[7];
    const float* dw1 = (const float*)d_in[8];
    const float* db1 = (const float*)d_in[9];
    const float* dw2 = (const float*)d_in[10];
    const float* db2 = (const float*)d_in[11];
    const float* dw3 = (const float*)d_in[12];
    const float* db3 = (const float*)d_in[13];
    float* out = (float*)d_out;

    static bool attr_done = false;
    if (!attr_done) {
        cudaFuncSetAttribute(conv2t_k, cudaFuncAttributeMaxDynamicSharedMemorySize, 53888);
        cudaFuncSetAttribute(conv3x3_k<0>, cudaFuncAttributeMaxDynamicSharedMemorySize, 55296);
        cudaFuncSetAttribute(conv3x3_k<1>, cudaFuncAttributeMaxDynamicSharedMemorySize, 55296);
        attr_done = true;
    }

    zero_losses_k<<<1, 32>>>(out);
    prep_w_k  <<<324,  256>>>(w3, dw1);
    conv1_k   <<<2048, 256>>>(x, w1, b1);
    conv2t_k  <<<1024, 256, 53888>>>(w2, b2);
    conv3x3_k<0><<<1024, 256, 55296>>>(b3);
    quantize_k<<<512,  256>>>(cb, out);
    conv3x3_k<1><<<1024, 256, 55296>>>(db1);
    deconv2t_k<<<2048, 256>>>(dw2, db2);
    deconv3t_k<<<1024, 256>>>(x, dw3, db3, out);
}

// round 8
// speedup vs baseline: 2.1915x; 1.1765x over previous
#include <cuda_runtime.h>
#include <stdint.h>
#include <math.h>

// ---------------- geometry ----------------
// x      : [128,  1, 128, 128]
// h1     : [128, 32,  64,  64]   conv1 k4 s2 p1 + relu [tf32] (g_h1, reused for d2)
// h2     : [128, 64,  32,  32]   conv2 k4 s2 p1 (tf32 mma)    (g_h2, reused for d1)
// z      : [128, 64,  32,  32]   conv3 k3 s1 p1 (tf32 mma)    (g_z)
// z_q    : [128, 64,  32,  32]   codebook gather [tf32]       (g_zq)
// x_rec  : [128,  1, 128, 128]   -> d_out[0 : 2097152]
// d_out[2097152] = recon_loss, d_out[2097153] = vq_loss

#define N_XREC   2097152
#define N_Z      8388608

__device__ float g_h1[128 * 32 * 64 * 64];
__device__ float g_h2[128 * 64 * 32 * 32];
__device__ float g_z [128 * 64 * 32 * 32];
__device__ float g_zq[128 * 64 * 32 * 32];
// tf32-rounded 3x3 weights: [set][ch(8)][tap(9)][k(8)][72]
__device__ float g_wt[2 * 41472];
// tf32-rounded conv2 weights: [ch(4)][tap(16)][k(8)][72]
__device__ float g_w2t[36864];

// ---------------- cp.async helpers ----------------
__device__ __forceinline__ void cp4(uint32_t dst, const float* src, bool p) {
    asm volatile("cp.async.ca.shared.global [%0], [%1], 4, %2;"
                 :: "r"(dst), "l"(src), "r"(p ? 4u : 0u));
}
__device__ __forceinline__ void cp16(uint32_t dst, const float* src) {
    asm volatile("cp.async.ca.shared.global [%0], [%1], 16;"
                 :: "r"(dst), "l"(src));
}
__device__ __forceinline__ void cp_commit() {
    asm volatile("cp.async.commit_group;");
}
__device__ __forceinline__ void cp_wait1() {
    asm volatile("cp.async.wait_group 1;");
}
__device__ __forceinline__ void cp_wait0() {
    asm volatile("cp.async.wait_group 0;");
}

// ---------------- tf32 mma helpers ----------------
__device__ __forceinline__ uint32_t f2tf(float f) {
    uint32_t r; asm("cvt.rna.tf32.f32 %0, %1;" : "=r"(r) : "f"(f)); return r;
}
__device__ __forceinline__ float f2tf_f(float f) {
    uint32_t r = f2tf(f); return __uint_as_float(r);
}
__device__ __forceinline__ void mma_tf32(float& d0, float& d1, float& d2, float& d3,
                                         uint32_t a0, uint32_t a1, uint32_t a2, uint32_t a3,
                                         uint32_t b0, uint32_t b1) {
    asm volatile("mma.sync.aligned.m16n8k8.row.col.f32.tf32.tf32.f32 "
                 "{%0,%1,%2,%3}, {%4,%5,%6,%7}, {%8,%9}, {%0,%1,%2,%3};"
                 : "+f"(d0), "+f"(d1), "+f"(d2), "+f"(d3)
                 : "r"(a0), "r"(a1), "r"(a2), "r"(a3), "r"(b0), "r"(b1));
}

__global__ void zero_losses_k(float* out) {
    if (threadIdx.x == 0) { out[N_XREC] = 0.0f; out[N_XREC + 1] = 0.0f; }
}

// ---------------- weight prep: 3x3 weights (both sets) ----------------
__global__ void __launch_bounds__(256) prep_w_k(const float* __restrict__ w3,
                                                const float* __restrict__ dw1) {
    int i = blockIdx.x * 256 + threadIdx.x;          // 82944 total
    int set = i / 41472, r = i - set * 41472;
    int o = r % 72, q = r / 72;
    int k = q & 7, q2 = q >> 3;
    int tap = q2 % 9, ch = q2 / 9;
    int ci = ch * 8 + k;
    float v = 0.0f;
    if (o < 64) v = set ? dw1[(ci * 64 + o) * 9 + (8 - tap)]
                        : w3[(o * 64 + ci) * 9 + tap];
    g_wt[i] = f2tf_f(v);
}

// ---------------- weight prep: conv2 weights ----------------
// g_w2t idx = ((ch*16 + tap)*8 + k)*72 + o ; ci = ch*8 + k
__global__ void __launch_bounds__(256) prep_w2_k(const float* __restrict__ w2) {
    int i = blockIdx.x * 256 + threadIdx.x;          // 36864 total
    int o = i % 72, q = i / 72;
    int k = q & 7, q2 = q >> 3;
    int tap = q2 & 15, ch = q2 >> 4;
    int ci = ch * 8 + k;
    float v = 0.0f;
    if (o < 64) v = w2[(o * 32 + ci) * 16 + tap];
    g_w2t[i] = f2tf_f(v);
}

// ---------------- conv1: 1->32, k4 s2 p1, relu; output tf32-rounded ----------------
__global__ void __launch_bounds__(256) conv1_k(const float* __restrict__ x,
                                               const float* __restrict__ w,
                                               const float* __restrict__ b) {
    __shared__ float tin[10][132];
    __shared__ float ws[512];
    __shared__ float bs[32];
    int n = blockIdx.x >> 4, y0 = (blockIdx.x & 15) * 4;
    int t = threadIdx.x;
    int xo = t & 63, ys = t >> 6, yo = y0 + ys;
    for (int i = t; i < 512; i += 256) ws[i] = w[i];
    if (t < 32) bs[t] = b[t];
    const float* xp = x + n * 16384;
    for (int j = t; j < 1320; j += 256) {
        int r = j / 132, c = j - r * 132;
        int iy = 2 * y0 - 1 + r, ix = c - 1;
        float v = 0.0f;
        if ((unsigned)iy < 128u && (unsigned)ix < 128u) v = xp[iy * 128 + ix];
        tin[r][c] = v;
    }
    __syncthreads();

    float xin[16];
#pragma unroll
    for (int ky = 0; ky < 4; ky++)
#pragma unroll
        for (int kx = 0; kx < 4; kx++)
            xin[ky * 4 + kx] = tin[2 * ys + ky][2 * xo + kx];

    float* outp = g_h1 + n * 131072 + yo * 64 + xo;
#pragma unroll 4
    for (int o = 0; o < 32; o++) {
        float acc = bs[o];
#pragma unroll
        for (int k = 0; k < 16; k++) acc = fmaf(xin[k], ws[o * 16 + k], acc);
        outp[o * 4096] = f2tf_f(fmaxf(acc, 0.0f));
    }
}

// ---------------- conv2: 32->64, k4 s2 p1, relu — tf32 mma implicit GEMM ----------
// Block: 1 image, 2 out rows (64 px), all 64 o. K=512 in 4 chunks of 8 ci.
// smem: tin[2][8][6][68] (2*3264) + ws[2][16*8][72] (2*9216) = 99840 B
__global__ void __launch_bounds__(256) conv2m_k(const float* __restrict__ b) {
    extern __shared__ float dsm[];
    float* tin = dsm;               // [buf][ci][6][68]
    float* ws  = dsm + 6528;        // [buf][(tap*8 + k)][72]
    uint32_t tin_s = (uint32_t)__cvta_generic_to_shared(tin);
    uint32_t ws_s  = (uint32_t)__cvta_generic_to_shared(ws);
    int n = blockIdx.x >> 4, y0 = (blockIdx.x & 15) * 2;
    int t = threadIdx.x;
    int wid = t >> 5, lane = t & 31;
    int g = lane >> 2, tg = lane & 3;
    int obase = (wid & 3) * 16;
    int nbase = (wid >> 2) * 32;
    int o_lo = obase + g, o_hi = o_lo + 8;
    const float* in0 = g_h1 + n * 131072;

    int boff[4];
#pragma unroll
    for (int nt = 0; nt < 4; nt++) {
        int pix = nbase + nt * 8 + g;
        boff[nt] = (pix >> 5) * 136 + (pix & 31) * 2;   // input r=2*row, c=2*col
    }

    float acc[4][4];
#pragma unroll
    for (int nt = 0; nt < 4; nt++)
#pragma unroll
        for (int j = 0; j < 4; j++) acc[nt][j] = 0.0f;

    auto load_chunk = [&](int buf, int ch) {
        const float* src = g_w2t + ch * 9216;          // contiguous [tap][k][72]
        for (int j = t; j < 2304; j += 256)
            cp16(ws_s + (buf * 9216 + j * 4) * 4, src + j * 4);
        for (int j = t; j < 3168; j += 256) {          // tin[cc][r][c], 8x6x66
            int cc = j / 396, rem = j - cc * 396, r = rem / 66, c = rem - r * 66;
            int iy = 2 * y0 - 1 + r, ix = c - 1;
            bool p = ((unsigned)iy < 64u) & ((unsigned)ix < 64u);
            const float* s2 = in0 + (ch * 8 + cc) * 4096 + (p ? iy * 64 + ix : 0);
            cp4(tin_s + (buf * 3264 + cc * 408 + r * 68 + c) * 4, s2, p);
        }
        cp_commit();
    };

    load_chunk(0, 0);
    for (int ch = 0; ch < 4; ch++) {
        if (ch < 3) { load_chunk((ch + 1) & 1, ch + 1); cp_wait1(); }
        else        { cp_wait0(); }
        __syncthreads();
        const float* tb = tin + (ch & 1) * 3264;
        const float* wb = ws  + (ch & 1) * 9216;
#pragma unroll
        for (int tap = 0; tap < 16; tap++) {
            int ky = tap >> 2, kx = tap & 3;
            const float* wpb = wb + tap * 576;         // [k][72]
            uint32_t ra0 = *(const uint32_t*)&wpb[tg * 72 + o_lo];
            uint32_t ra1 = *(const uint32_t*)&wpb[tg * 72 + o_hi];
            uint32_t ra2 = *(const uint32_t*)&wpb[(tg + 4) * 72 + o_lo];
            uint32_t ra3 = *(const uint32_t*)&wpb[(tg + 4) * 72 + o_hi];
            const float* tpb = tb + ky * 68 + kx;
#pragma unroll
            for (int nt = 0; nt < 4; nt++) {
                uint32_t rb0 = *(const uint32_t*)&tpb[tg * 408 + boff[nt]];
                uint32_t rb1 = *(const uint32_t*)&tpb[(tg + 4) * 408 + boff[nt]];
                mma_tf32(acc[nt][0], acc[nt][1], acc[nt][2], acc[nt][3],
                         ra0, ra1, ra2, ra3, rb0, rb1);
            }
        }
        __syncthreads();
    }

    float bv_lo = b[o_lo], bv_hi = b[o_hi];
    float* outbase = g_h2 + n * 65536 + y0 * 32;
#pragma unroll
    for (int nt = 0; nt < 4; nt++) {
        int pc = nbase + nt * 8 + tg * 2;
        float v0 = f2tf_f(fmaxf(acc[nt][0] + bv_lo, 0.0f));
        float v1 = f2tf_f(fmaxf(acc[nt][1] + bv_lo, 0.0f));
        float v2 = f2tf_f(fmaxf(acc[nt][2] + bv_hi, 0.0f));
        float v3 = f2tf_f(fmaxf(acc[nt][3] + bv_hi, 0.0f));
        *(float2*)(outbase + o_lo * 1024 + pc) = make_float2(v0, v1);
        *(float2*)(outbase + o_hi * 1024 + pc) = make_float2(v2, v3);
    }
}

// ---------------- conv3 / deconv1: tf32 mma, pre-rounded operands ----------------
// smem: tin[2][8][6][36] (2*1728) + ws[2][9*8][72] (2*5184) = 55296 B
template <int SET>
__global__ void __launch_bounds__(256) conv3x3_k(const float* __restrict__ b) {
    extern __shared__ float dsm[];
    float* tin = dsm;               // [buf][ci][6][36]
    float* ws  = dsm + 3456;        // [buf][(tap*8 + k)][72]
    uint32_t tin_s = (uint32_t)__cvta_generic_to_shared(tin);
    uint32_t ws_s  = (uint32_t)__cvta_generic_to_shared(ws);
    int n = blockIdx.x >> 3, y0 = (blockIdx.x & 7) * 4;
    int t = threadIdx.x;
    int wid = t >> 5, lane = t & 31;
    int g = lane >> 2, tg = lane & 3;
    int obase = (wid & 3) * 16;
    int nbase = (wid >> 2) * 64;
    int o_lo = obase + g, o_hi = o_lo + 8;
    const float* in0 = (SET ? g_zq : g_h2) + n * 65536;
    const float* wsrc = g_wt + SET * 41472;

    int boff[8];
#pragma unroll
    for (int nt = 0; nt < 8; nt++) {
        int pix = nbase + nt * 8 + g;
        boff[nt] = (pix >> 5) * 36 + (pix & 31);
    }

    float acc[8][4];
#pragma unroll
    for (int nt = 0; nt < 8; nt++)
#pragma unroll
        for (int j = 0; j < 4; j++) acc[nt][j] = 0.0f;

    auto load_chunk = [&](int buf, int ch) {
        const float* src = wsrc + ch * 5184;           // contiguous [tap][k][72]
        for (int j = t; j < 1296; j += 256)
            cp16(ws_s + (buf * 5184 + j * 4) * 4, src + j * 4);
        for (int j = t; j < 1632; j += 256) {          // tin[cc][r][c], stride 36
            int cc = j / 204, rem = j - cc * 204, r = rem / 34, c = rem - r * 34;
            int iy = y0 - 1 + r, ix = c - 1;
            bool p = ((unsigned)iy < 32u) & ((unsigned)ix < 32u);
            const float* s2 = in0 + (ch * 8 + cc) * 1024 + (p ? iy * 32 + ix : 0);
            cp4(tin_s + (buf * 1728 + cc * 216 + r * 36 + c) * 4, s2, p);
        }
        cp_commit();
    };

    load_chunk(0, 0);
    for (int ch = 0; ch < 8; ch++) {
        if (ch < 7) { load_chunk((ch + 1) & 1, ch + 1); cp_wait1(); }
        else        { cp_wait0(); }
        __syncthreads();
        const float* tb = tin + (ch & 1) * 1728;
        const float* wb = ws  + (ch & 1) * 5184;
#pragma unroll
        for (int tap = 0; tap < 9; tap++) {
            int ky = tap / 3, kx = tap - ky * 3;
            const float* wpb = wb + tap * 576;         // [k][72]
            uint32_t ra0 = *(const uint32_t*)&wpb[tg * 72 + o_lo];
            uint32_t ra1 = *(const uint32_t*)&wpb[tg * 72 + o_hi];
            uint32_t ra2 = *(const uint32_t*)&wpb[(tg + 4) * 72 + o_lo];
            uint32_t ra3 = *(const uint32_t*)&wpb[(tg + 4) * 72 + o_hi];
            const float* tpb = tb + ky * 36 + kx;
#pragma unroll
            for (int nt = 0; nt < 8; nt++) {
                uint32_t rb0 = *(const uint32_t*)&tpb[tg * 216 + boff[nt]];
                uint32_t rb1 = *(const uint32_t*)&tpb[(tg + 4) * 216 + boff[nt]];
                mma_tf32(acc[nt][0], acc[nt][1], acc[nt][2], acc[nt][3],
                         ra0, ra1, ra2, ra3, rb0, rb1);
            }
        }
        __syncthreads();
    }

    float bv_lo = b[o_lo], bv_hi = b[o_hi];
    float* outbase = (SET ? g_h2 : g_z) + n * 65536 + y0 * 32;
#pragma unroll
    for (int nt = 0; nt < 8; nt++) {
        int pc = nbase + nt * 8 + tg * 2;
        float v0 = acc[nt][0] + bv_lo, v1 = acc[nt][1] + bv_lo;
        float v2 = acc[nt][2] + bv_hi, v3 = acc[nt][3] + bv_hi;
        if (SET) {
            v0 = fmaxf(v0, 0.0f); v1 = fmaxf(v1, 0.0f);
            v2 = fmaxf(v2, 0.0f); v3 = fmaxf(v3, 0.0f);
        }
        *(float2*)(outbase + o_lo * 1024 + pc) = make_float2(v0, v1);
        *(float2*)(outbase + o_hi * 1024 + pc) = make_float2(v2, v3);
    }
}

// ---------------- quantize: argmin over 128 codes, dim 64; z_q stored tf32 ----
__global__ void __launch_bounds__(256) quantize_k(const float* __restrict__ cb,
                                                  float* out) {
    __shared__ float4 cbs[2048];
    __shared__ float cn[128];
    __shared__ float red[256];
    int t = threadIdx.x;
    for (int i = t; i < 2048; i += 256) cbs[i] = ((const float4*)cb)[i];
    __syncthreads();
    if (t < 128) {
        float s = 0.0f;
        const float4* cp = cbs + t * 16;
#pragma unroll
        for (int d = 0; d < 16; d++) {
            float4 c = cp[d];
            s = fmaf(c.x, c.x, s); s = fmaf(c.y, c.y, s);
            s = fmaf(c.z, c.z, s); s = fmaf(c.w, c.w, s);
        }
        cn[t] = s;
    }
    __syncthreads();

    int p = blockIdx.x * 256 + t;
    int hw = p & 1023, n = p >> 10;
    const float* zp = g_z + n * 65536 + hw;
    float zr[64];
#pragma unroll
    for (int d = 0; d < 64; d++) zr[d] = zp[d * 1024];

    int best = 0;
    float bestv = 3.4e38f;
    for (int e = 0; e < 128; e++) {
        const float4* cp = cbs + e * 16;
        float dot = 0.0f;
#pragma unroll
        for (int d = 0; d < 16; d++) {
            float4 c = cp[d];
            dot = fmaf(zr[4 * d + 0], c.x, dot);
            dot = fmaf(zr[4 * d + 1], c.y, dot);
            dot = fmaf(zr[4 * d + 2], c.z, dot);
            dot = fmaf(zr[4 * d + 3], c.w, dot);
        }
        float sc = cn[e] - 2.0f * dot;
        if (sc < bestv) { bestv = sc; best = e; }
    }

    float vs = 0.0f;
    float* zqp = g_zq + n * 65536 + hw;
    const float* cbest = (const float*)(cbs + best * 16);
#pragma unroll
    for (int d = 0; d < 64; d++) {
        float c = cbest[d];
        zqp[d * 1024] = f2tf_f(c);      // deconv1 reads tf32 bits
        float df = zr[d] - c;           // loss uses exact codebook value
        vs = fmaf(df, df, vs);
    }

    red[t] = vs;
    __syncthreads();
    for (int s = 128; s > 0; s >>= 1) {
        if (t < s) red[t] += red[t + s];
        __syncthreads();
    }
    if (t == 0) atomicAdd(out + N_XREC + 1, red[0] * (1.0f / (float)N_Z));
}

// ---------------- deconv2: 64->32, k4 s2 p1, relu (double-buffered FFMA) ----------------
__global__ void __launch_bounds__(256) deconv2t_k(const float* __restrict__ w,
                                                  const float* __restrict__ b) {
    __shared__ float tin[2][8][4][34];   // 2*1088
    __shared__ float ws[2][4096];        // [buf][ci*512 + o*16 + tap]
    uint32_t tin_s = (uint32_t)__cvta_generic_to_shared(&tin[0][0][0][0]);
    uint32_t ws_s  = (uint32_t)__cvta_generic_to_shared(&ws[0][0]);
    int n = blockIdx.x >> 4, y0 = (blockIdx.x & 15) * 4;
    int t = threadIdx.x;
    int obase = (t >> 5) * 4;
    int sslot = t & 31;
    int ys = sslot >> 3, x0 = (sslot & 7) * 8;

    int yo = y0 + ys;
    int ky0 = (yo + 1) & 1;
    int yiA = (yo + 1 - ky0) >> 1;
    int rowA = yiA - (y0 >> 1) + 1;
    int rowB = rowA - 1;
    int cbase = x0 >> 1;

    float acc[4][8];
#pragma unroll
    for (int j = 0; j < 4; j++)
#pragma unroll
        for (int s = 0; s < 8; s++) acc[j][s] = 0.0f;

    const float* in0 = g_h2 + n * 65536;
    auto load_chunk = [&](int buf, int ch) {
        for (int j = t; j < 1024; j += 256)
            cp16(ws_s + (buf * 4096 + j * 4) * 4, w + ch * 4096 + j * 4);
        for (int j = t; j < 1088; j += 256) {
            int cc = j / 136, rem = j - cc * 136, r = rem / 34, c = rem - r * 34;
            int yi = (y0 >> 1) - 1 + r, xi = c - 1;
            bool p = ((unsigned)yi < 32u) & ((unsigned)xi < 32u);
            const float* src = in0 + (ch * 8 + cc) * 1024 + (p ? yi * 32 + xi : 0);
            cp4(tin_s + (buf * 1088 + j) * 4, src, p);
        }
        cp_commit();
    };

    load_chunk(0, 0);
    for (int ch = 0; ch < 8; ch++) {
        if (ch < 7) { load_chunk((ch + 1) & 1, ch + 1); cp_wait1(); }
        else        { cp_wait0(); }
        __syncthreads();
        int buf = ch & 1;
#pragma unroll 2
        for (int cc = 0; cc < 8; cc++) {
            float a[6], bb[6];
#pragma unroll
            for (int c = 0; c < 6; c++) {
                a[c]  = tin[buf][cc][rowA][cbase + c];
                bb[c] = tin[buf][cc][rowB][cbase + c];
            }
#pragma unroll
            for (int j = 0; j < 4; j++) {
                const float* wp = &ws[buf][cc * 512 + (obase + j) * 16];
                float wk0 = wp[ky0 * 4 + 0], wk1 = wp[ky0 * 4 + 1];
                float wk2 = wp[ky0 * 4 + 2], wk3 = wp[ky0 * 4 + 3];
                float wk4 = wp[(ky0 + 2) * 4 + 0], wk5 = wp[(ky0 + 2) * 4 + 1];
                float wk6 = wp[(ky0 + 2) * 4 + 2], wk7 = wp[(ky0 + 2) * 4 + 3];
#pragma unroll
                for (int s = 0; s < 8; s++) {
                    int ia = (s >> 1) + (s & 1) + 1, ib = ia - 1;
                    float v = acc[j][s];
                    if (s & 1) {
                        v = fmaf(a[ia],  wk0, v);
                        v = fmaf(a[ib],  wk2, v);
                        v = fmaf(bb[ia], wk4, v);
                        v = fmaf(bb[ib], wk6, v);
                    } else {
                        v = fmaf(a[ia],  wk1, v);
                        v = fmaf(a[ib],  wk3, v);
                        v = fmaf(bb[ia], wk5, v);
                        v = fmaf(bb[ib], wk7, v);
                    }
                    acc[j][s] = v;
                }
            }
        }
        __syncthreads();
    }
    float* out0 = g_h1 + n * 131072 + yo * 64 + x0;
#pragma unroll
    for (int j = 0; j < 4; j++) {
        float bv = b[obase + j];
        float4 v0, v1;
        v0.x = fmaxf(acc[j][0] + bv, 0.0f); v0.y = fmaxf(acc[j][1] + bv, 0.0f);
        v0.z = fmaxf(acc[j][2] + bv, 0.0f); v0.w = fmaxf(acc[j][3] + bv, 0.0f);
        v1.x = fmaxf(acc[j][4] + bv, 0.0f); v1.y = fmaxf(acc[j][5] + bv, 0.0f);
        v1.z = fmaxf(acc[j][6] + bv, 0.0f); v1.w = fmaxf(acc[j][7] + bv, 0.0f);
        *(float4*)(out0 + (obase + j) * 4096)     = v0;
        *(float4*)(out0 + (obase + j) * 4096 + 4) = v1;
    }
}

// ---------------- deconv3: 32->1, k4 s2 p1, sigmoid + recon loss (double-buffered) ----------------
__global__ void __launch_bounds__(256) deconv3t_k(const float* __restrict__ xin,
                                                  const float* __restrict__ w,
                                                  const float* __restrict__ b,
                                                  float* out) {
    __shared__ float tin[2][8][10][66];  // 2*5280
    __shared__ float ws3[512];
    __shared__ float red[256];
    uint32_t tin_s = (uint32_t)__cvta_generic_to_shared(&tin[0][0][0][0]);
    int n = blockIdx.x >> 3, y0 = (blockIdx.x & 7) * 16;
    int t = threadIdx.x;
    int ys = t >> 4, x0 = (t & 15) * 8;
    int yo = y0 + ys;
    int ky0 = (yo + 1) & 1;
    int yiA = (yo + 1 - ky0) >> 1;
    int rowA = yiA - (y0 >> 1) + 1;
    int rowB = rowA - 1;
    int cbase = x0 >> 1;

    for (int j = t; j < 512; j += 256) ws3[j] = w[j];

    float acc[8];
#pragma unroll
    for (int s = 0; s < 8; s++) acc[s] = 0.0f;

    const float* in0 = g_h1 + n * 131072;
    auto load_chunk = [&](int buf, int ch) {
        for (int j = t; j < 5280; j += 256) {
            int cc = j / 660, rem = j - cc * 660, r = rem / 66, c = rem - r * 66;
            int yi = (y0 >> 1) - 1 + r, xi = c - 1;
            bool p = ((unsigned)yi < 64u) & ((unsigned)xi < 64u);
            const float* src = in0 + (ch * 8 + cc) * 4096 + (p ? yi * 64 + xi : 0);
            cp4(tin_s + (buf * 5280 + j) * 4, src, p);
        }
        cp_commit();
    };

    load_chunk(0, 0);
    for (int ch = 0; ch < 4; ch++) {
        if (ch < 3) { load_chunk((ch + 1) & 1, ch + 1); cp_wait1(); }
        else        { cp_wait0(); }
        __syncthreads();
        int buf = ch & 1;
#pragma unroll 2
        for (int cc = 0; cc < 8; cc++) {
            float a[6], bb[6];
#pragma unroll
            for (int c = 0; c < 6; c++) {
                a[c]  = tin[buf][cc][rowA][cbase + c];
                bb[c] = tin[buf][cc][rowB][cbase + c];
            }
            int ci = ch * 8 + cc;
            const float* wp = &ws3[ci * 16];
            float wa0 = wp[ky0 * 4 + 0], wa1 = wp[ky0 * 4 + 1];
            float wa2 = wp[ky0 * 4 + 2], wa3 = wp[ky0 * 4 + 3];
            float wb0 = wp[(ky0 + 2) * 4 + 0], wb1 = wp[(ky0 + 2) * 4 + 1];
            float wb2 = wp[(ky0 + 2) * 4 + 2], wb3 = wp[(ky0 + 2) * 4 + 3];
#pragma unroll
            for (int s = 0; s < 8; s++) {
                int ia = (s >> 1) + (s & 1) + 1, ib = ia - 1;
                float v = acc[s];
                if (s & 1) {
                    v = fmaf(a[ia],  wa0, v);
                    v = fmaf(a[ib],  wa2, v);
                    v = fmaf(bb[ia], wb0, v);
                    v = fmaf(bb[ib], wb2, v);
                } else {
                    v = fmaf(a[ia],  wa1, v);
                    v = fmaf(a[ib],  wa3, v);
                    v = fmaf(bb[ia], wb1, v);
                    v = fmaf(bb[ib], wb3, v);
                }
                acc[s] = v;
            }
        }
        __syncthreads();
    }

    float b0 = b[0];
    const float* xp = xin + n * 16384 + yo * 128 + x0;
    float* op = out + n * 16384 + yo * 128 + x0;
    float ls = 0.0f;
    float rv[8];
#pragma unroll
    for (int s = 0; s < 8; s++) {
        float r = 1.0f / (1.0f + expf(-(acc[s] + b0)));
        rv[s] = r;
        float df = r - xp[s];
        ls = fmaf(df, df, ls);
    }
    *(float4*)(op)     = make_float4(rv[0], rv[1], rv[2], rv[3]);
    *(float4*)(op + 4) = make_float4(rv[4], rv[5], rv[6], rv[7]);

    red[t] = ls;
    __syncthreads();
    for (int s = 128; s > 0; s >>= 1) {
        if (t < s) red[t] += red[t + s];
        __syncthreads();
    }
    if (t == 0) atomicAdd(out + N_XREC, red[0] * (1.0f / (float)N_XREC));
}

// ---------------- launch ----------------
extern "C" void kernel_launch(void* const* d_in, const int* in_sizes, int n_in,
                              void* d_out, int out_size) {
    const float* x   = (const float*)d_in[0];
    const float* w1  = (const float*)d_in[1];
    const float* b1  = (const float*)d_in[2];
    const float* w2  = (const float*)d_in[3];
    const float* b2  = (const float*)d_in[4];
    const float* w3  = (const float*)d_in[5];
    const float* b3  = (const float*)d_in[6];
    const float* cb  = (const float*)d_in[7];
    const float* dw1 = (const float*)d_in[8];
    const float* db1 = (const float*)d_in[9];
    const float* dw2 = (const float*)d_in[10];
    const float* db2 = (const float*)d_in[11];
    const float* dw3 = (const float*)d_in[12];
    const float* db3 = (const float*)d_in[13];
    float* out = (float*)d_out;

    static bool attr_done = false;
    if (!attr_done) {
        cudaFuncSetAttribute(conv2m_k, cudaFuncAttributeMaxDynamicSharedMemorySize, 99840);
        cudaFuncSetAttribute(conv3x3_k<0>, cudaFuncAttributeMaxDynamicSharedMemorySize, 55296);
        cudaFuncSetAttribute(conv3x3_k<1>, cudaFuncAttributeMaxDynamicSharedMemorySize, 55296);
        attr_done = true;
    }

    zero_losses_k<<<1, 32>>>(out);
    prep_w_k  <<<324,  256>>>(w3, dw1);
    prep_w2_k <<<144,  256>>>(w2);
    conv1_k   <<<2048, 256>>>(x, w1, b1);
    conv2m_k  <<<2048, 256, 99840>>>(b2);
    conv3x3_k<0><<<1024, 256, 55296>>>(b3);
    quantize_k<<<512,  256>>>(cb, out);
    conv3x3_k<1><<<1024, 256, 55296>>>(db1);
    deconv2t_k<<<2048, 256>>>(dw2, db2);
    deconv3t_k<<<1024, 256>>>(x, dw3, db3, out);
}

// round 9
// speedup vs baseline: 2.4571x; 1.1212x over previous
#include <cuda_runtime.h>
#include <stdint.h>
#include <math.h>

// ---------------- geometry ----------------
// x      : [128,  1, 128, 128]
// h1     : [128, 32,  64,  64]   conv1 k4 s2 p1 + relu [tf32] (g_h1, reused for d2)
// h2     : [128, 64,  32,  32]   conv2 k4 s2 p1 (tf32 mma)    (g_h2, reused for d1 [tf32])
// z      : [128, 64,  32,  32]   conv3 k3 s1 p1 (tf32 mma)    (g_z)
// z_q    : [128, 64,  32,  32]   codebook gather [tf32]       (g_zq)
// x_rec  : [128,  1, 128, 128]   -> d_out[0 : 2097152]
// d_out[2097152] = recon_loss, d_out[2097153] = vq_loss

#define N_XREC   2097152
#define N_Z      8388608

__device__ float g_h1[128 * 32 * 64 * 64];
__device__ float g_h2[128 * 64 * 32 * 32];
__device__ float g_z [128 * 64 * 32 * 32];
__device__ float g_zq[128 * 64 * 32 * 32];
// tf32-rounded 3x3 weights: [set][ch(8)][tap(9)][k(8)][72]
__device__ float g_wt[2 * 41472];
// tf32-rounded conv2 weights: [ch(4)][tap(16)][k(8)][72]
__device__ float g_w2t[36864];
// tf32-rounded deconv2 weights: [par(4)][ci(64)][ji(4)][40]
__device__ float g_wd2t[40960];

// ---------------- cp.async helpers ----------------
__device__ __forceinline__ void cp4(uint32_t dst, const float* src, bool p) {
    asm volatile("cp.async.ca.shared.global [%0], [%1], 4, %2;"
                 :: "r"(dst), "l"(src), "r"(p ? 4u : 0u));
}
__device__ __forceinline__ void cp16(uint32_t dst, const float* src) {
    asm volatile("cp.async.ca.shared.global [%0], [%1], 16;"
                 :: "r"(dst), "l"(src));
}
__device__ __forceinline__ void cp_commit() {
    asm volatile("cp.async.commit_group;");
}
__device__ __forceinline__ void cp_wait1() {
    asm volatile("cp.async.wait_group 1;");
}
__device__ __forceinline__ void cp_wait0() {
    asm volatile("cp.async.wait_group 0;");
}

// ---------------- tf32 mma helpers ----------------
__device__ __forceinline__ uint32_t f2tf(float f) {
    uint32_t r; asm("cvt.rna.tf32.f32 %0, %1;" : "=r"(r) : "f"(f)); return r;
}
__device__ __forceinline__ float f2tf_f(float f) {
    uint32_t r = f2tf(f); return __uint_as_float(r);
}
__device__ __forceinline__ void mma_tf32(float& d0, float& d1, float& d2, float& d3,
                                         uint32_t a0, uint32_t a1, uint32_t a2, uint32_t a3,
                                         uint32_t b0, uint32_t b1) {
    asm volatile("mma.sync.aligned.m16n8k8.row.col.f32.tf32.tf32.f32 "
                 "{%0,%1,%2,%3}, {%4,%5,%6,%7}, {%8,%9}, {%0,%1,%2,%3};"
                 : "+f"(d0), "+f"(d1), "+f"(d2), "+f"(d3)
                 : "r"(a0), "r"(a1), "r"(a2), "r"(a3), "r"(b0), "r"(b1));
}

__global__ void zero_losses_k(float* out) {
    if (threadIdx.x == 0) { out[N_XREC] = 0.0f; out[N_XREC + 1] = 0.0f; }
}

// ---------------- weight prep: 3x3 weights (both sets) ----------------
__global__ void __launch_bounds__(256) prep_w_k(const float* __restrict__ w3,
                                                const float* __restrict__ dw1) {
    int i = blockIdx.x * 256 + threadIdx.x;          // 82944 total
    int set = i / 41472, r = i - set * 41472;
    int o = r % 72, q = r / 72;
    int k = q & 7, q2 = q >> 3;
    int tap = q2 % 9, ch = q2 / 9;
    int ci = ch * 8 + k;
    float v = 0.0f;
    if (o < 64) v = set ? dw1[(ci * 64 + o) * 9 + (8 - tap)]
                        : w3[(o * 64 + ci) * 9 + tap];
    g_wt[i] = f2tf_f(v);
}

// ---------------- weight prep: conv2 weights ----------------
__global__ void __launch_bounds__(256) prep_w2_k(const float* __restrict__ w2) {
    int i = blockIdx.x * 256 + threadIdx.x;          // 36864 total
    int o = i % 72, q = i / 72;
    int k = q & 7, q2 = q >> 3;
    int tap = q2 & 15, ch = q2 >> 4;
    int ci = ch * 8 + k;
    float v = 0.0f;
    if (o < 64) v = w2[(o * 32 + ci) * 16 + tap];
    g_w2t[i] = f2tf_f(v);
}

// ---------------- weight prep: deconv2 weights, parity-partitioned ----------------
// g_wd2t idx = ((par*64 + ci)*4 + ji)*40 + o
// par=(py,px); taps: ky = (1-py)+2j, kx = (1-px)+2i; ji = j*2+i
__global__ void __launch_bounds__(256) prep_wd2_k(const float* __restrict__ dw2) {
    int i = blockIdx.x * 256 + threadIdx.x;          // 40960 total
    int o = i % 40, q = i / 40;
    int ji = q & 3, q2 = q >> 2;
    int ci = q2 & 63, par = q2 >> 6;
    int py = par >> 1, px = par & 1;
    int ky = (1 - py) + 2 * (ji >> 1);
    int kx = (1 - px) + 2 * (ji & 1);
    float v = 0.0f;
    if (o < 32) v = dw2[(ci * 32 + o) * 16 + ky * 4 + kx];
    g_wd2t[i] = f2tf_f(v);
}

// ---------------- conv1: 1->32, k4 s2 p1, relu; output tf32-rounded ----------------
__global__ void __launch_bounds__(256) conv1_k(const float* __restrict__ x,
                                               const float* __restrict__ w,
                                               const float* __restrict__ b) {
    __shared__ float tin[10][132];
    __shared__ float ws[512];
    __shared__ float bs[32];
    int n = blockIdx.x >> 4, y0 = (blockIdx.x & 15) * 4;
    int t = threadIdx.x;
    int xo = t & 63, ys = t >> 6, yo = y0 + ys;
    for (int i = t; i < 512; i += 256) ws[i] = w[i];
    if (t < 32) bs[t] = b[t];
    const float* xp = x + n * 16384;
    for (int j = t; j < 1320; j += 256) {
        int r = j / 132, c = j - r * 132;
        int iy = 2 * y0 - 1 + r, ix = c - 1;
        float v = 0.0f;
        if ((unsigned)iy < 128u && (unsigned)ix < 128u) v = xp[iy * 128 + ix];
        tin[r][c] = v;
    }
    __syncthreads();

    float xin[16];
#pragma unroll
    for (int ky = 0; ky < 4; ky++)
#pragma unroll
        for (int kx = 0; kx < 4; kx++)
            xin[ky * 4 + kx] = tin[2 * ys + ky][2 * xo + kx];

    float* outp = g_h1 + n * 131072 + yo * 64 + xo;
#pragma unroll 4
    for (int o = 0; o < 32; o++) {
        float acc = bs[o];
#pragma unroll
        for (int k = 0; k < 16; k++) acc = fmaf(xin[k], ws[o * 16 + k], acc);
        outp[o * 4096] = f2tf_f(fmaxf(acc, 0.0f));
    }
}

// ---------------- conv2: 32->64, k4 s2 p1, relu — tf32 mma implicit GEMM ----------
// smem: tin[2][8][6][68] (2*3264) + ws[2][16*8][72] (2*9216) = 99840 B
__global__ void __launch_bounds__(256) conv2m_k(const float* __restrict__ b) {
    extern __shared__ float dsm[];
    float* tin = dsm;               // [buf][ci][6][68]
    float* ws  = dsm + 6528;        // [buf][(tap*8 + k)][72]
    uint32_t tin_s = (uint32_t)__cvta_generic_to_shared(tin);
    uint32_t ws_s  = (uint32_t)__cvta_generic_to_shared(ws);
    int n = blockIdx.x >> 4, y0 = (blockIdx.x & 15) * 2;
    int t = threadIdx.x;
    int wid = t >> 5, lane = t & 31;
    int g = lane >> 2, tg = lane & 3;
    int obase = (wid & 3) * 16;
    int nbase = (wid >> 2) * 32;
    int o_lo = obase + g, o_hi = o_lo + 8;
    const float* in0 = g_h1 + n * 131072;

    int boff[4];
#pragma unroll
    for (int nt = 0; nt < 4; nt++) {
        int pix = nbase + nt * 8 + g;
        boff[nt] = (pix >> 5) * 136 + (pix & 31) * 2;
    }

    float acc[4][4];
#pragma unroll
    for (int nt = 0; nt < 4; nt++)
#pragma unroll
        for (int j = 0; j < 4; j++) acc[nt][j] = 0.0f;

    auto load_chunk = [&](int buf, int ch) {
        const float* src = g_w2t + ch * 9216;
        for (int j = t; j < 2304; j += 256)
            cp16(ws_s + (buf * 9216 + j * 4) * 4, src + j * 4);
        for (int j = t; j < 3168; j += 256) {
            int cc = j / 396, rem = j - cc * 396, r = rem / 66, c = rem - r * 66;
            int iy = 2 * y0 - 1 + r, ix = c - 1;
            bool p = ((unsigned)iy < 64u) & ((unsigned)ix < 64u);
            const float* s2 = in0 + (ch * 8 + cc) * 4096 + (p ? iy * 64 + ix : 0);
            cp4(tin_s + (buf * 3264 + cc * 408 + r * 68 + c) * 4, s2, p);
        }
        cp_commit();
    };

    load_chunk(0, 0);
    for (int ch = 0; ch < 4; ch++) {
        if (ch < 3) { load_chunk((ch + 1) & 1, ch + 1); cp_wait1(); }
        else        { cp_wait0(); }
        __syncthreads();
        const float* tb = tin + (ch & 1) * 3264;
        const float* wb = ws  + (ch & 1) * 9216;
#pragma unroll
        for (int tap = 0; tap < 16; tap++) {
            int ky = tap >> 2, kx = tap & 3;
            const float* wpb = wb + tap * 576;
            uint32_t ra0 = *(const uint32_t*)&wpb[tg * 72 + o_lo];
            uint32_t ra1 = *(const uint32_t*)&wpb[tg * 72 + o_hi];
            uint32_t ra2 = *(const uint32_t*)&wpb[(tg + 4) * 72 + o_lo];
            uint32_t ra3 = *(const uint32_t*)&wpb[(tg + 4) * 72 + o_hi];
            const float* tpb = tb + ky * 68 + kx;
#pragma unroll
            for (int nt = 0; nt < 4; nt++) {
                uint32_t rb0 = *(const uint32_t*)&tpb[tg * 408 + boff[nt]];
                uint32_t rb1 = *(const uint32_t*)&tpb[(tg + 4) * 408 + boff[nt]];
                mma_tf32(acc[nt][0], acc[nt][1], acc[nt][2], acc[nt][3],
                         ra0, ra1, ra2, ra3, rb0, rb1);
            }
        }
        __syncthreads();
    }

    float bv_lo = b[o_lo], bv_hi = b[o_hi];
    float* outbase = g_h2 + n * 65536 + y0 * 32;
#pragma unroll
    for (int nt = 0; nt < 4; nt++) {
        int pc = nbase + nt * 8 + tg * 2;
        float v0 = f2tf_f(fmaxf(acc[nt][0] + bv_lo, 0.0f));
        float v1 = f2tf_f(fmaxf(acc[nt][1] + bv_lo, 0.0f));
        float v2 = f2tf_f(fmaxf(acc[nt][2] + bv_hi, 0.0f));
        float v3 = f2tf_f(fmaxf(acc[nt][3] + bv_hi, 0.0f));
        *(float2*)(outbase + o_lo * 1024 + pc) = make_float2(v0, v1);
        *(float2*)(outbase + o_hi * 1024 + pc) = make_float2(v2, v3);
    }
}

// ---------------- conv3 / deconv1: tf32 mma, pre-rounded operands ----------------
// SET=1 epilogue rounds output to tf32 (feeds deconv2 mma)
template <int SET>
__global__ void __launch_bounds__(256) conv3x3_k(const float* __restrict__ b) {
    extern __shared__ float dsm[];
    float* tin = dsm;               // [buf][ci][6][36]
    float* ws  = dsm + 3456;        // [buf][(tap*8 + k)][72]
    uint32_t tin_s = (uint32_t)__cvta_generic_to_shared(tin);
    uint32_t ws_s  = (uint32_t)__cvta_generic_to_shared(ws);
    int n = blockIdx.x >> 3, y0 = (blockIdx.x & 7) * 4;
    int t = threadIdx.x;
    int wid = t >> 5, lane = t & 31;
    int g = lane >> 2, tg = lane & 3;
    int obase = (wid & 3) * 16;
    int nbase = (wid >> 2) * 64;
    int o_lo = obase + g, o_hi = o_lo + 8;
    const float* in0 = (SET ? g_zq : g_h2) + n * 65536;
    const float* wsrc = g_wt + SET * 41472;

    int boff[8];
#pragma unroll
    for (int nt = 0; nt < 8; nt++) {
        int pix = nbase + nt * 8 + g;
        boff[nt] = (pix >> 5) * 36 + (pix & 31);
    }

    float acc[8][4];
#pragma unroll
    for (int nt = 0; nt < 8; nt++)
#pragma unroll
        for (int j = 0; j < 4; j++) acc[nt][j] = 0.0f;

    auto load_chunk = [&](int buf, int ch) {
        const float* src = wsrc + ch * 5184;
        for (int j = t; j < 1296; j += 256)
            cp16(ws_s + (buf * 5184 + j * 4) * 4, src + j * 4);
        for (int j = t; j < 1632; j += 256) {
            int cc = j / 204, rem = j - cc * 204, r = rem / 34, c = rem - r * 34;
            int iy = y0 - 1 + r, ix = c - 1;
            bool p = ((unsigned)iy < 32u) & ((unsigned)ix < 32u);
            const float* s2 = in0 + (ch * 8 + cc) * 1024 + (p ? iy * 32 + ix : 0);
            cp4(tin_s + (buf * 1728 + cc * 216 + r * 36 + c) * 4, s2, p);
        }
        cp_commit();
    };

    load_chunk(0, 0);
    for (int ch = 0; ch < 8; ch++) {
        if (ch < 7) { load_chunk((ch + 1) & 1, ch + 1); cp_wait1(); }
        else        { cp_wait0(); }
        __syncthreads();
        const float* tb = tin + (ch & 1) * 1728;
        const float* wb = ws  + (ch & 1) * 5184;
#pragma unroll
        for (int tap = 0; tap < 9; tap++) {
            int ky = tap / 3, kx = tap - ky * 3;
            const float* wpb = wb + tap * 576;
            uint32_t ra0 = *(const uint32_t*)&wpb[tg * 72 + o_lo];
            uint32_t ra1 = *(const uint32_t*)&wpb[tg * 72 + o_hi];
            uint32_t ra2 = *(const uint32_t*)&wpb[(tg + 4) * 72 + o_lo];
            uint32_t ra3 = *(const uint32_t*)&wpb[(tg + 4) * 72 + o_hi];
            const float* tpb = tb + ky * 36 + kx;
#pragma unroll
            for (int nt = 0; nt < 8; nt++) {
                uint32_t rb0 = *(const uint32_t*)&tpb[tg * 216 + boff[nt]];
                uint32_t rb1 = *(const uint32_t*)&tpb[(tg + 4) * 216 + boff[nt]];
                mma_tf32(acc[nt][0], acc[nt][1], acc[nt][2], acc[nt][3],
                         ra0, ra1, ra2, ra3, rb0, rb1);
            }
        }
        __syncthreads();
    }

    float bv_lo = b[o_lo], bv_hi = b[o_hi];
    float* outbase = (SET ? g_h2 : g_z) + n * 65536 + y0 * 32;
#pragma unroll
    for (int nt = 0; nt < 8; nt++) {
        int pc = nbase + nt * 8 + tg * 2;
        float v0 = acc[nt][0] + bv_lo, v1 = acc[nt][1] + bv_lo;
        float v2 = acc[nt][2] + bv_hi, v3 = acc[nt][3] + bv_hi;
        if (SET) {
            v0 = f2tf_f(fmaxf(v0, 0.0f)); v1 = f2tf_f(fmaxf(v1, 0.0f));
            v2 = f2tf_f(fmaxf(v2, 0.0f)); v3 = f2tf_f(fmaxf(v3, 0.0f));
        }
        *(float2*)(outbase + o_lo * 1024 + pc) = make_float2(v0, v1);
        *(float2*)(outbase + o_hi * 1024 + pc) = make_float2(v2, v3);
    }
}

// ---------------- quantize: argmin over 128 codes, dim 64; z_q stored tf32 ----
__global__ void __launch_bounds__(256) quantize_k(const float* __restrict__ cb,
                                                  float* out) {
    __shared__ float4 cbs[2048];
    __shared__ float cn[128];
    __shared__ float red[256];
    int t = threadIdx.x;
    for (int i = t; i < 2048; i += 256) cbs[i] = ((const float4*)cb)[i];
    __syncthreads();
    if (t < 128) {
        float s = 0.0f;
        const float4* cp = cbs + t * 16;
#pragma unroll
        for (int d = 0; d < 16; d++) {
            float4 c = cp[d];
            s = fmaf(c.x, c.x, s); s = fmaf(c.y, c.y, s);
            s = fmaf(c.z, c.z, s); s = fmaf(c.w, c.w, s);
        }
        cn[t] = s;
    }
    __syncthreads();

    int p = blockIdx.x * 256 + t;
    int hw = p & 1023, n = p >> 10;
    const float* zp = g_z + n * 65536 + hw;
    float zr[64];
#pragma unroll
    for (int d = 0; d < 64; d++) zr[d] = zp[d * 1024];

    int best = 0;
    float bestv = 3.4e38f;
    for (int e = 0; e < 128; e++) {
        const float4* cp = cbs + e * 16;
        float dot = 0.0f;
#pragma unroll
        for (int d = 0; d < 16; d++) {
            float4 c = cp[d];
            dot = fmaf(zr[4 * d + 0], c.x, dot);
            dot = fmaf(zr[4 * d + 1], c.y, dot);
            dot = fmaf(zr[4 * d + 2], c.z, dot);
            dot = fmaf(zr[4 * d + 3], c.w, dot);
        }
        float sc = cn[e] - 2.0f * dot;
        if (sc < bestv) { bestv = sc; best = e; }
    }

    float vs = 0.0f;
    float* zqp = g_zq + n * 65536 + hw;
    const float* cbest = (const float*)(cbs + best * 16);
#pragma unroll
    for (int d = 0; d < 64; d++) {
        float c = cbest[d];
        zqp[d * 1024] = f2tf_f(c);
        float df = zr[d] - c;
        vs = fmaf(df, df, vs);
    }

    red[t] = vs;
    __syncthreads();
    for (int s = 128; s > 0; s >>= 1) {
        if (t < s) red[t] += red[t + s];
        __syncthreads();
    }
    if (t == 0) atomicAdd(out + N_XREC + 1, red[0] * (1.0f / (float)N_Z));
}

// ---------------- deconv2: 64->32, k4 s2 p1, relu — tf32 mma, parity GEMM ----------
// Block: 1 image, output rows 4*band..4*band+3 (u0 = 2*band, 2 u per block).
// Warp: mt = wid&1 (o-tile), par = wid>>1 (py=par>>1, px=par&1). N=64 px/warp.
// smem: tin[2][8][4][36] (2*1152) + ws[2][par(4)][32k][40] (2*5120) = 50176 B
__global__ void __launch_bounds__(256) deconv2m_k(const float* __restrict__ b) {
    extern __shared__ float dsm[];
    float* tin = dsm;               // [buf][cil(8)][4][36]
    float* ws  = dsm + 2304;        // [buf][par(4)][k(32)][40]
    uint32_t tin_s = (uint32_t)__cvta_generic_to_shared(tin);
    uint32_t ws_s  = (uint32_t)__cvta_generic_to_shared(ws);
    int n = blockIdx.x >> 4, u0 = (blockIdx.x & 15) * 2;
    int t = threadIdx.x;
    int wid = t >> 5, lane = t & 31;
    int g = lane >> 2, tg = lane & 3;
    int mt = wid & 1, par = wid >> 1;
    int py = par >> 1, px = par & 1;
    int obase = mt * 16;
    int o_lo = obase + g, o_hi = o_lo + 8;
    // tap slot (j,i) from tg; input offset per slot
    int jj = tg >> 1, ii = tg & 1;
    int dy = py ? (1 - jj) : (-jj);
    int dx = px ? (1 - ii) : (-ii);
    int toff = (1 + dy) * 36 + (1 + dx);
    const float* in0 = g_h2 + n * 65536;

    int boff[8];
#pragma unroll
    for (int nt = 0; nt < 8; nt++) {
        int pix = nt * 8 + g;                     // n = u_l*32 + v
        boff[nt] = (pix >> 5) * 36 + (pix & 31);
    }

    float acc[8][4];
#pragma unroll
    for (int nt = 0; nt < 8; nt++)
#pragma unroll
        for (int j = 0; j < 4; j++) acc[nt][j] = 0.0f;

    auto load_chunk = [&](int buf, int ch) {
        for (int j = t; j < 1280; j += 256) {      // weights: 4 parity sections
            int p2 = j / 320, rem = j - p2 * 320;
            cp16(ws_s + (buf * 5120 + p2 * 1280 + rem * 4) * 4,
                 g_wd2t + p2 * 10240 + ch * 1280 + rem * 4);
        }
        for (int j = t; j < 1088; j += 256) {      // tin[cc][r(4)][c(34)]
            int cc = j / 136, rem = j - cc * 136, r = rem / 34, c = rem - r * 34;
            int yi = u0 - 1 + r, xi = c - 1;
            bool p = ((unsigned)yi < 32u) & ((unsigned)xi < 32u);
            const float* s2 = in0 + (ch * 8 + cc) * 1024 + (p ? yi * 32 + xi : 0);
            cp4(tin_s + (buf * 1152 + cc * 144 + r * 36 + c) * 4, s2, p);
        }
        cp_commit();
    };

    load_chunk(0, 0);
    for (int ch = 0; ch < 8; ch++) {
        if (ch < 7) { load_chunk((ch + 1) & 1, ch + 1); cp_wait1(); }
        else        { cp_wait0(); }
        __syncthreads();
        const float* tb = tin + (ch & 1) * 1152;
        const float* wb = ws  + (ch & 1) * 5120 + par * 1280;
#pragma unroll
        for (int s = 0; s < 4; s++) {              // k-steps; k = cil*4 + ji
            uint32_t ra0 = *(const uint32_t*)&wb[(s * 8 + tg) * 40 + o_lo];
            uint32_t ra1 = *(const uint32_t*)&wb[(s * 8 + tg) * 40 + o_hi];
            uint32_t ra2 = *(const uint32_t*)&wb[(s * 8 + tg + 4) * 40 + o_lo];
            uint32_t ra3 = *(const uint32_t*)&wb[(s * 8 + tg + 4) * 40 + o_hi];
            const float* t0 = tb + (2 * s) * 144 + toff;       // cil = 2s
            const float* t1 = tb + (2 * s + 1) * 144 + toff;   // cil = 2s+1
#pragma unroll
            for (int nt = 0; nt < 8; nt++) {
                uint32_t rb0 = *(const uint32_t*)&t0[boff[nt]];
                uint32_t rb1 = *(const uint32_t*)&t1[boff[nt]];
                mma_tf32(acc[nt][0], acc[nt][1], acc[nt][2], acc[nt][3],
                         ra0, ra1, ra2, ra3, rb0, rb1);
            }
        }
        __syncthreads();
    }

    float bv_lo = b[o_lo], bv_hi = b[o_hi];
    float* ob = g_h1 + n * 131072;
#pragma unroll
    for (int nt = 0; nt < 8; nt++) {
#pragma unroll
        for (int c2 = 0; c2 < 2; c2++) {
            int np = nt * 8 + tg * 2 + c2;
            int u_l = np >> 5, v = np & 31;
            int yo = 2 * (u0 + u_l) + py, xo = 2 * v + px;
            ob[o_lo * 4096 + yo * 64 + xo] = fmaxf(acc[nt][c2]     + bv_lo, 0.0f);
            ob[o_hi * 4096 + yo * 64 + xo] = fmaxf(acc[nt][c2 + 2] + bv_hi, 0.0f);
        }
    }
}

// ---------------- deconv3: 32->1, k4 s2 p1, sigmoid + recon loss (double-buffered) ----------------
__global__ void __launch_bounds__(256) deconv3t_k(const float* __restrict__ xin,
                                                  const float* __restrict__ w,
                                                  const float* __restrict__ b,
                                                  float* out) {
    __shared__ float tin[2][8][10][66];  // 2*5280
    __shared__ float ws3[512];
    __shared__ float red[256];
    uint32_t tin_s = (uint32_t)__cvta_generic_to_shared(&tin[0][0][0][0]);
    int n = blockIdx.x >> 3, y0 = (blockIdx.x & 7) * 16;
    int t = threadIdx.x;
    int ys = t >> 4, x0 = (t & 15) * 8;
    int yo = y0 + ys;
    int ky0 = (yo + 1) & 1;
    int yiA = (yo + 1 - ky0) >> 1;
    int rowA = yiA - (y0 >> 1) + 1;
    int rowB = rowA - 1;
    int cbase = x0 >> 1;

    for (int j = t; j < 512; j += 256) ws3[j] = w[j];

    float acc[8];
#pragma unroll
    for (int s = 0; s < 8; s++) acc[s] = 0.0f;

    const float* in0 = g_h1 + n * 131072;
    auto load_chunk = [&](int buf, int ch) {
        for (int j = t; j < 5280; j += 256) {
            int cc = j / 660, rem = j - cc * 660, r = rem / 66, c = rem - r * 66;
            int yi = (y0 >> 1) - 1 + r, xi = c - 1;
            bool p = ((unsigned)yi < 64u) & ((unsigned)xi < 64u);
            const float* src = in0 + (ch * 8 + cc) * 4096 + (p ? yi * 64 + xi : 0);
            cp4(tin_s + (buf * 5280 + j) * 4, src, p);
        }
        cp_commit();
    };

    load_chunk(0, 0);
    for (int ch = 0; ch < 4; ch++) {
        if (ch < 3) { load_chunk((ch + 1) & 1, ch + 1); cp_wait1(); }
        else        { cp_wait0(); }
        __syncthreads();
        int buf = ch & 1;
#pragma unroll 2
        for (int cc = 0; cc < 8; cc++) {
            float a[6], bb[6];
#pragma unroll
            for (int c = 0; c < 6; c++) {
                a[c]  = tin[buf][cc][rowA][cbase + c];
                bb[c] = tin[buf][cc][rowB][cbase + c];
            }
            int ci = ch * 8 + cc;
            const float* wp = &ws3[ci * 16];
            float wa0 = wp[ky0 * 4 + 0], wa1 = wp[ky0 * 4 + 1];
            float wa2 = wp[ky0 * 4 + 2], wa3 = wp[ky0 * 4 + 3];
            float wb0 = wp[(ky0 + 2) * 4 + 0], wb1 = wp[(ky0 + 2) * 4 + 1];
            float wb2 = wp[(ky0 + 2) * 4 + 2], wb3 = wp[(ky0 + 2) * 4 + 3];
#pragma unroll
            for (int s = 0; s < 8; s++) {
                int ia = (s >> 1) + (s & 1) + 1, ib = ia - 1;
                float v = acc[s];
                if (s & 1) {
                    v = fmaf(a[ia],  wa0, v);
                    v = fmaf(a[ib],  wa2, v);
                    v = fmaf(bb[ia], wb0, v);
                    v = fmaf(bb[ib], wb2, v);
                } else {
                    v = fmaf(a[ia],  wa1, v);
                    v = fmaf(a[ib],  wa3, v);
                    v = fmaf(bb[ia], wb1, v);
                    v = fmaf(bb[ib], wb3, v);
                }
                acc[s] = v;
            }
        }
        __syncthreads();
    }

    float b0 = b[0];
    const float* xp = xin + n * 16384 + yo * 128 + x0;
    float* op = out + n * 16384 + yo * 128 + x0;
    float ls = 0.0f;
    float rv[8];
#pragma unroll
    for (int s = 0; s < 8; s++) {
        float r = 1.0f / (1.0f + expf(-(acc[s] + b0)));
        rv[s] = r;
        float df = r - xp[s];
        ls = fmaf(df, df, ls);
    }
    *(float4*)(op)     = make_float4(rv[0], rv[1], rv[2], rv[3]);
    *(float4*)(op + 4) = make_float4(rv[4], rv[5], rv[6], rv[7]);

    red[t] = ls;
    __syncthreads();
    for (int s = 128; s > 0; s >>= 1) {
        if (t < s) red[t] += red[t + s];
        __syncthreads();
    }
    if (t == 0) atomicAdd(out + N_XREC, red[0] * (1.0f / (float)N_XREC));
}

// ---------------- launch ----------------
extern "C" void kernel_launch(void* const* d_in, const int* in_sizes, int n_in,
                              void* d_out, int out_size) {
    const float* x   = (const float*)d_in[0];
    const float* w1  = (const float*)d_in[1];
    const float* b1  = (const float*)d_in[2];
    const float* w2  = (const float*)d_in[3];
    const float* b2  = (const float*)d_in[4];
    const float* w3  = (const float*)d_in[5];
    const float* b3  = (const float*)d_in[6];
    const float* cb  = (const float*)d_in[7];
    const float* dw1 = (const float*)d_in[8];
    const float* db1 = (const float*)d_in[9];
    const float* dw2 = (const float*)d_in[10];
    const float* db2 = (const float*)d_in[11];
    const float* dw3 = (const float*)d_in[12];
    const float* db3 = (const float*)d_in[13];
    float* out = (float*)d_out;

    static bool attr_done = false;
    if (!attr_done) {
        cudaFuncSetAttribute(conv2m_k, cudaFuncAttributeMaxDynamicSharedMemorySize, 99840);
        cudaFuncSetAttribute(conv3x3_k<0>, cudaFuncAttributeMaxDynamicSharedMemorySize, 55296);
        cudaFuncSetAttribute(conv3x3_k<1>, cudaFuncAttributeMaxDynamicSharedMemorySize, 55296);
        cudaFuncSetAttribute(deconv2m_k, cudaFuncAttributeMaxDynamicSharedMemorySize, 50176);
        attr_done = true;
    }

    zero_losses_k<<<1, 32>>>(out);
    prep_w_k   <<<324,  256>>>(w3, dw1);
    prep_w2_k  <<<144,  256>>>(w2);
    prep_wd2_k <<<160,  256>>>(dw2);
    conv1_k    <<<2048, 256>>>(x, w1, b1);
    conv2m_k   <<<2048, 256, 99840>>>(b2);
    conv3x3_k<0><<<1024, 256, 55296>>>(b3);
    quantize_k <<<512,  256>>>(cb, out);
    conv3x3_k<1><<<1024, 256, 55296>>>(db1);
    deconv2m_k <<<2048, 256, 50176>>>(db2);
    deconv3t_k <<<1024, 256>>>(x, dw3, db3, out);
}

// round 10
// speedup vs baseline: 2.5477x; 1.0369x over previous
#include <cuda_runtime.h>
#include <stdint.h>
#include <math.h>

// ---------------- geometry ----------------
// x      : [128,  1, 128, 128]
// h1     : [128, 32,  64,  64]   conv1 + relu [tf32]          (g_h1, reused for d2)
// h2     : [128, 64,  32,  32]   conv2 (tf32 mma)             (g_h2, reused for d1 [tf32])
// z      : [128, 64,  32,  32]   conv3 (tf32 mma)             (g_z)
// z_q    : [128, 64,  32,  32]   codebook gather [tf32]       (g_zq)
// x_rec  : [128,  1, 128, 128]   -> d_out[0 : 2097152]
// d_out[2097152] = recon_loss, d_out[2097153] = vq_loss

#define N_XREC   2097152
#define N_Z      8388608

__device__ float g_h1[128 * 32 * 64 * 64];
__device__ float g_h2[128 * 64 * 32 * 32];
__device__ float g_z [128 * 64 * 32 * 32];
__device__ float g_zq[128 * 64 * 32 * 32];
// tf32-rounded 3x3 weights: [set][ch(8)][tap(9)][k(8)][72]
__device__ float g_wt[2 * 41472];
// tf32-rounded conv2 weights: [ch(4)][tap(16)][k(8)][72]
__device__ float g_w2t[36864];
// tf32-rounded deconv2 weights: [par(4)][ci(64)][ji(4)][40]
__device__ float g_wd2t[40960];
// tf32-rounded codebook: [k(64)][136]  (codes padded 128->136)
__device__ float g_cbt[8704];

// ---------------- cp.async helpers ----------------
__device__ __forceinline__ void cp4(uint32_t dst, const float* src, bool p) {
    asm volatile("cp.async.ca.shared.global [%0], [%1], 4, %2;"
                 :: "r"(dst), "l"(src), "r"(p ? 4u : 0u));
}
__device__ __forceinline__ void cp16(uint32_t dst, const float* src) {
    asm volatile("cp.async.ca.shared.global [%0], [%1], 16;"
                 :: "r"(dst), "l"(src));
}
__device__ __forceinline__ void cp_commit() {
    asm volatile("cp.async.commit_group;");
}
__device__ __forceinline__ void cp_wait1() {
    asm volatile("cp.async.wait_group 1;");
}
__device__ __forceinline__ void cp_wait0() {
    asm volatile("cp.async.wait_group 0;");
}

// ---------------- tf32 mma helpers ----------------
__device__ __forceinline__ uint32_t f2tf(float f) {
    uint32_t r; asm("cvt.rna.tf32.f32 %0, %1;" : "=r"(r) : "f"(f)); return r;
}
__device__ __forceinline__ float f2tf_f(float f) {
    uint32_t r = f2tf(f); return __uint_as_float(r);
}
__device__ __forceinline__ void mma_tf32(float& d0, float& d1, float& d2, float& d3,
                                         uint32_t a0, uint32_t a1, uint32_t a2, uint32_t a3,
                                         uint32_t b0, uint32_t b1) {
    asm volatile("mma.sync.aligned.m16n8k8.row.col.f32.tf32.tf32.f32 "
                 "{%0,%1,%2,%3}, {%4,%5,%6,%7}, {%8,%9}, {%0,%1,%2,%3};"
                 : "+f"(d0), "+f"(d1), "+f"(d2), "+f"(d3)
                 : "r"(a0), "r"(a1), "r"(a2), "r"(a3), "r"(b0), "r"(b1));
}

// ---------------- merged prep: all weight layouts + codebook + loss zero ----------
// ranges: [0,82944) g_wt | [82944,119808) g_w2t | [119808,160768) g_wd2t
//         [160768,169472) g_cbt
__global__ void __launch_bounds__(256) prep_all_k(const float* __restrict__ w3,
                                                  const float* __restrict__ dw1,
                                                  const float* __restrict__ w2,
                                                  const float* __restrict__ dw2,
                                                  const float* __restrict__ cb,
                                                  float* out) {
    int i = blockIdx.x * 256 + threadIdx.x;
    if (i < 2) { out[N_XREC + i] = 0.0f; }
    if (i < 82944) {
        int set = i / 41472, r = i - set * 41472;
        int o = r % 72, q = r / 72;
        int k = q & 7, q2 = q >> 3;
        int tap = q2 % 9, ch = q2 / 9;
        int ci = ch * 8 + k;
        float v = 0.0f;
        if (o < 64) v = set ? dw1[(ci * 64 + o) * 9 + (8 - tap)]
                            : w3[(o * 64 + ci) * 9 + tap];
        g_wt[i] = f2tf_f(v);
    } else if (i < 119808) {
        int j = i - 82944;
        int o = j % 72, q = j / 72;
        int k = q & 7, q2 = q >> 3;
        int tap = q2 & 15, ch = q2 >> 4;
        int ci = ch * 8 + k;
        float v = 0.0f;
        if (o < 64) v = w2[(o * 32 + ci) * 16 + tap];
        g_w2t[j] = f2tf_f(v);
    } else if (i < 160768) {
        int j = i - 119808;
        int o = j % 40, q = j / 40;
        int ji = q & 3, q2 = q >> 2;
        int ci = q2 & 63, par = q2 >> 6;
        int py = par >> 1, px = par & 1;
        int ky = (1 - py) + 2 * (ji >> 1);
        int kx = (1 - px) + 2 * (ji & 1);
        float v = 0.0f;
        if (o < 32) v = dw2[(ci * 32 + o) * 16 + ky * 4 + kx];
        g_wd2t[j] = f2tf_f(v);
    } else if (i < 169472) {
        int j = i - 160768;
        int m = j % 136, k = j / 136;
        float v = 0.0f;
        if (m < 128) v = cb[m * 64 + k];
        g_cbt[j] = f2tf_f(v);
    }
}

// ---------------- conv1: 1->32, k4 s2 p1, relu; output tf32-rounded ----------------
__global__ void __launch_bounds__(256) conv1_k(const float* __restrict__ x,
                                               const float* __restrict__ w,
                                               const float* __restrict__ b) {
    __shared__ float tin[10][132];
    __shared__ float ws[512];
    __shared__ float bs[32];
    int n = blockIdx.x >> 4, y0 = (blockIdx.x & 15) * 4;
    int t = threadIdx.x;
    int xo = t & 63, ys = t >> 6, yo = y0 + ys;
    for (int i = t; i < 512; i += 256) ws[i] = w[i];
    if (t < 32) bs[t] = b[t];
    const float* xp = x + n * 16384;
    for (int j = t; j < 1320; j += 256) {
        int r = j / 132, c = j - r * 132;
        int iy = 2 * y0 - 1 + r, ix = c - 1;
        float v = 0.0f;
        if ((unsigned)iy < 128u && (unsigned)ix < 128u) v = xp[iy * 128 + ix];
        tin[r][c] = v;
    }
    __syncthreads();

    float xin[16];
#pragma unroll
    for (int ky = 0; ky < 4; ky++)
#pragma unroll
        for (int kx = 0; kx < 4; kx++)
            xin[ky * 4 + kx] = tin[2 * ys + ky][2 * xo + kx];

    float* outp = g_h1 + n * 131072 + yo * 64 + xo;
#pragma unroll 4
    for (int o = 0; o < 32; o++) {
        float acc = bs[o];
#pragma unroll
        for (int k = 0; k < 16; k++) acc = fmaf(xin[k], ws[o * 16 + k], acc);
        outp[o * 4096] = f2tf_f(fmaxf(acc, 0.0f));
    }
}

// ---------------- conv2: 32->64, k4 s2 p1, relu — tf32 mma implicit GEMM ----------
__global__ void __launch_bounds__(256) conv2m_k(const float* __restrict__ b) {
    extern __shared__ float dsm[];
    float* tin = dsm;               // [buf][ci][6][68]
    float* ws  = dsm + 6528;        // [buf][(tap*8 + k)][72]
    uint32_t tin_s = (uint32_t)__cvta_generic_to_shared(tin);
    uint32_t ws_s  = (uint32_t)__cvta_generic_to_shared(ws);
    int n = blockIdx.x >> 4, y0 = (blockIdx.x & 15) * 2;
    int t = threadIdx.x;
    int wid = t >> 5, lane = t & 31;
    int g = lane >> 2, tg = lane & 3;
    int obase = (wid & 3) * 16;
    int nbase = (wid >> 2) * 32;
    int o_lo = obase + g, o_hi = o_lo + 8;
    const float* in0 = g_h1 + n * 131072;

    int boff[4];
#pragma unroll
    for (int nt = 0; nt < 4; nt++) {
        int pix = nbase + nt * 8 + g;
        boff[nt] = (pix >> 5) * 136 + (pix & 31) * 2;
    }

    float acc[4][4];
#pragma unroll
    for (int nt = 0; nt < 4; nt++)
#pragma unroll
        for (int j = 0; j < 4; j++) acc[nt][j] = 0.0f;

    auto load_chunk = [&](int buf, int ch) {
        const float* src = g_w2t + ch * 9216;
        for (int j = t; j < 2304; j += 256)
            cp16(ws_s + (buf * 9216 + j * 4) * 4, src + j * 4);
        for (int j = t; j < 3168; j += 256) {
            int cc = j / 396, rem = j - cc * 396, r = rem / 66, c = rem - r * 66;
            int iy = 2 * y0 - 1 + r, ix = c - 1;
            bool p = ((unsigned)iy < 64u) & ((unsigned)ix < 64u);
            const float* s2 = in0 + (ch * 8 + cc) * 4096 + (p ? iy * 64 + ix : 0);
            cp4(tin_s + (buf * 3264 + cc * 408 + r * 68 + c) * 4, s2, p);
        }
        cp_commit();
    };

    load_chunk(0, 0);
    for (int ch = 0; ch < 4; ch++) {
        if (ch < 3) { load_chunk((ch + 1) & 1, ch + 1); cp_wait1(); }
        else        { cp_wait0(); }
        __syncthreads();
        const float* tb = tin + (ch & 1) * 3264;
        const float* wb = ws  + (ch & 1) * 9216;
#pragma unroll
        for (int tap = 0; tap < 16; tap++) {
            int ky = tap >> 2, kx = tap & 3;
            const float* wpb = wb + tap * 576;
            uint32_t ra0 = *(const uint32_t*)&wpb[tg * 72 + o_lo];
            uint32_t ra1 = *(const uint32_t*)&wpb[tg * 72 + o_hi];
            uint32_t ra2 = *(const uint32_t*)&wpb[(tg + 4) * 72 + o_lo];
            uint32_t ra3 = *(const uint32_t*)&wpb[(tg + 4) * 72 + o_hi];
            const float* tpb = tb + ky * 68 + kx;
#pragma unroll
            for (int nt = 0; nt < 4; nt++) {
                uint32_t rb0 = *(const uint32_t*)&tpb[tg * 408 + boff[nt]];
                uint32_t rb1 = *(const uint32_t*)&tpb[(tg + 4) * 408 + boff[nt]];
                mma_tf32(acc[nt][0], acc[nt][1], acc[nt][2], acc[nt][3],
                         ra0, ra1, ra2, ra3, rb0, rb1);
            }
        }
        __syncthreads();
    }

    float bv_lo = b[o_lo], bv_hi = b[o_hi];
    float* outbase = g_h2 + n * 65536 + y0 * 32;
#pragma unroll
    for (int nt = 0; nt < 4; nt++) {
        int pc = nbase + nt * 8 + tg * 2;
        float v0 = f2tf_f(fmaxf(acc[nt][0] + bv_lo, 0.0f));
        float v1 = f2tf_f(fmaxf(acc[nt][1] + bv_lo, 0.0f));
        float v2 = f2tf_f(fmaxf(acc[nt][2] + bv_hi, 0.0f));
        float v3 = f2tf_f(fmaxf(acc[nt][3] + bv_hi, 0.0f));
        *(float2*)(outbase + o_lo * 1024 + pc) = make_float2(v0, v1);
        *(float2*)(outbase + o_hi * 1024 + pc) = make_float2(v2, v3);
    }
}

// ---------------- conv3 / deconv1: tf32 mma, pre-rounded operands ----------------
template <int SET>
__global__ void __launch_bounds__(256) conv3x3_k(const float* __restrict__ b) {
    extern __shared__ float dsm[];
    float* tin = dsm;               // [buf][ci][6][36]
    float* ws  = dsm + 3456;        // [buf][(tap*8 + k)][72]
    uint32_t tin_s = (uint32_t)__cvta_generic_to_shared(tin);
    uint32_t ws_s  = (uint32_t)__cvta_generic_to_shared(ws);
    int n = blockIdx.x >> 3, y0 = (blockIdx.x & 7) * 4;
    int t = threadIdx.x;
    int wid = t >> 5, lane = t & 31;
    int g = lane >> 2, tg = lane & 3;
    int obase = (wid & 3) * 16;
    int nbase = (wid >> 2) * 64;
    int o_lo = obase + g, o_hi = o_lo + 8;
    const float* in0 = (SET ? g_zq : g_h2) + n * 65536;
    const float* wsrc = g_wt + SET * 41472;

    int boff[8];
#pragma unroll
    for (int nt = 0; nt < 8; nt++) {
        int pix = nbase + nt * 8 + g;
        boff[nt] = (pix >> 5) * 36 + (pix & 31);
    }

    float acc[8][4];
#pragma unroll
    for (int nt = 0; nt < 8; nt++)
#pragma unroll
        for (int j = 0; j < 4; j++) acc[nt][j] = 0.0f;

    auto load_chunk = [&](int buf, int ch) {
        const float* src = wsrc + ch * 5184;
        for (int j = t; j < 1296; j += 256)
            cp16(ws_s + (buf * 5184 + j * 4) * 4, src + j * 4);
        for (int j = t; j < 1632; j += 256) {
            int cc = j / 204, rem = j - cc * 204, r = rem / 34, c = rem - r * 34;
            int iy = y0 - 1 + r, ix = c - 1;
            bool p = ((unsigned)iy < 32u) & ((unsigned)ix < 32u);
            const float* s2 = in0 + (ch * 8 + cc) * 1024 + (p ? iy * 32 + ix : 0);
            cp4(tin_s + (buf * 1728 + cc * 216 + r * 36 + c) * 4, s2, p);
        }
        cp_commit();
    };

    load_chunk(0, 0);
    for (int ch = 0; ch < 8; ch++) {
        if (ch < 7) { load_chunk((ch + 1) & 1, ch + 1); cp_wait1(); }
        else        { cp_wait0(); }
        __syncthreads();
        const float* tb = tin + (ch & 1) * 1728;
        const float* wb = ws  + (ch & 1) * 5184;
#pragma unroll
        for (int tap = 0; tap < 9; tap++) {
            int ky = tap / 3, kx = tap - ky * 3;
            const float* wpb = wb + tap * 576;
            uint32_t ra0 = *(const uint32_t*)&wpb[tg * 72 + o_lo];
            uint32_t ra1 = *(const uint32_t*)&wpb[tg * 72 + o_hi];
            uint32_t ra2 = *(const uint32_t*)&wpb[(tg + 4) * 72 + o_lo];
            uint32_t ra3 = *(const uint32_t*)&wpb[(tg + 4) * 72 + o_hi];
            const float* tpb = tb + ky * 36 + kx;
#pragma unroll
            for (int nt = 0; nt < 8; nt++) {
                uint32_t rb0 = *(const uint32_t*)&tpb[tg * 216 + boff[nt]];
                uint32_t rb1 = *(const uint32_t*)&tpb[(tg + 4) * 216 + boff[nt]];
                mma_tf32(acc[nt][0], acc[nt][1], acc[nt][2], acc[nt][3],
                         ra0, ra1, ra2, ra3, rb0, rb1);
            }
        }
        __syncthreads();
    }

    float bv_lo = b[o_lo], bv_hi = b[o_hi];
    float* outbase = (SET ? g_h2 : g_z) + n * 65536 + y0 * 32;
#pragma unroll
    for (int nt = 0; nt < 8; nt++) {
        int pc = nbase + nt * 8 + tg * 2;
        float v0 = acc[nt][0] + bv_lo, v1 = acc[nt][1] + bv_lo;
        float v2 = acc[nt][2] + bv_hi, v3 = acc[nt][3] + bv_hi;
        if (SET) {
            v0 = f2tf_f(fmaxf(v0, 0.0f)); v1 = f2tf_f(fmaxf(v1, 0.0f));
            v2 = f2tf_f(fmaxf(v2, 0.0f)); v3 = f2tf_f(fmaxf(v3, 0.0f));
        }
        *(float2*)(outbase + o_lo * 1024 + pc) = make_float2(v0, v1);
        *(float2*)(outbase + o_hi * 1024 + pc) = make_float2(v2, v3);
    }
}

// ---------------- quantize — tf32 mma GEMM (scores = cb @ z^T) + argmin ----------
// Block: 128 pixels (one image octant). M=128 codes, N=128 px, K=64.
// smem floats: zt[64][136] @0 | cbt[64][136] @8704 | minS[8][128] @17408
//              minI[8][128] @18432 | cn[128] @19456 | red[256] @19584  -> 79360 B
__global__ void __launch_bounds__(256) quantize_m_k(const float* __restrict__ cb,
                                                    float* out) {
    extern __shared__ float dsm[];
    float* zt   = dsm;
    float* cbt  = dsm + 8704;
    float* minS = dsm + 17408;
    int*   minI = (int*)(dsm + 18432);
    float* cn   = dsm + 19456;
    float* red  = dsm + 19584;
    uint32_t zt_s  = (uint32_t)__cvta_generic_to_shared(zt);
    uint32_t cbt_s = (uint32_t)__cvta_generic_to_shared(cbt);
    int t = threadIdx.x;
    int n = blockIdx.x >> 3, hw0 = (blockIdx.x & 7) * 128;
    int wid = t >> 5, lane = t & 31;
    int g = lane >> 2, tg = lane & 3;
    int mbase = wid * 16;

    const float* zsrc = g_z + n * 65536 + hw0;
    for (int j = t; j < 2048; j += 256) {          // zt rows: 64 x 32 cp16
        int row = j >> 5, c4 = j & 31;
        cp16(zt_s + (row * 136 + c4 * 4) * 4, zsrc + row * 1024 + c4 * 4);
    }
    for (int j = t; j < 2176; j += 256)            // cbt: contiguous
        cp16(cbt_s + j * 16, g_cbt + j * 4);
    cp_commit();
    if (t < 128) {                                  // exact code norms
        float s = 0.0f;
        const float* cp = cb + t * 64;
#pragma unroll
        for (int d = 0; d < 64; d++) s = fmaf(cp[d], cp[d], s);
        cn[t] = s;
    }
    cp_wait0();
    __syncthreads();

    float acc[16][4];
#pragma unroll
    for (int nt = 0; nt < 16; nt++)
#pragma unroll
        for (int j = 0; j < 4; j++) acc[nt][j] = 0.0f;

#pragma unroll
    for (int ks = 0; ks < 8; ks++) {
        const float* a0 = cbt + (ks * 8 + tg) * 136 + mbase + g;
        const float* a1 = cbt + (ks * 8 + tg + 4) * 136 + mbase + g;
        uint32_t ra0 = *(const uint32_t*)a0;
        uint32_t ra1 = *(const uint32_t*)(a0 + 8);
        uint32_t ra2 = *(const uint32_t*)a1;
        uint32_t ra3 = *(const uint32_t*)(a1 + 8);
        const float* b0 = zt + (ks * 8 + tg) * 136 + g;
        const float* b1 = zt + (ks * 8 + tg + 4) * 136 + g;
#pragma unroll
        for (int nt = 0; nt < 16; nt++) {
            uint32_t rb0 = f2tf(b0[nt * 8]);
            uint32_t rb1 = f2tf(b1[nt * 8]);
            mma_tf32(acc[nt][0], acc[nt][1], acc[nt][2], acc[nt][3],
                     ra0, ra1, ra2, ra3, rb0, rb1);
        }
    }

    // per-pixel argmin: score = cn[e] - 2*dot; lower index wins ties
    float cn_lo = cn[mbase + g], cn_hi = cn[mbase + g + 8];
#pragma unroll
    for (int nt = 0; nt < 16; nt++) {
#pragma unroll
        for (int c2 = 0; c2 < 2; c2++) {
            float s_lo = fmaf(-2.0f, acc[nt][c2],     cn_lo);
            float s_hi = fmaf(-2.0f, acc[nt][c2 + 2], cn_hi);
            float s = s_lo; int idx = mbase + g;
            if (s_hi < s) { s = s_hi; idx = mbase + g + 8; }
#pragma unroll
            for (int m = 4; m <= 16; m <<= 1) {
                float so = __shfl_xor_sync(0xffffffffu, s, m);
                int   io = __shfl_xor_sync(0xffffffffu, idx, m);
                if (so < s || (so == s && io < idx)) { s = so; idx = io; }
            }
            if (g == 0) {
                int px = nt * 8 + tg * 2 + c2;
                minS[wid * 128 + px] = s;
                minI[wid * 128 + px] = idx;
            }
        }
    }
    __syncthreads();

    float vs = 0.0f;
    if (t < 128) {
        float bs = minS[t]; int bi = minI[t];
#pragma unroll
        for (int w = 1; w < 8; w++) {
            float s = minS[w * 128 + t]; int i2 = minI[w * 128 + t];
            if (s < bs || (s == bs && i2 < bi)) { bs = s; bi = i2; }
        }
        const float* cbp = cb + bi * 64;            // exact codebook row (L2)
        float* zqp = g_zq + n * 65536 + hw0 + t;
#pragma unroll
        for (int d = 0; d < 64; d++) {
            float c = cbp[d];
            zqp[d * 1024] = f2tf_f(c);
            float df = zt[d * 136 + t] - c;
            vs = fmaf(df, df, vs);
        }
    }
    red[t] = vs;
    __syncthreads();
    for (int s = 128; s > 0; s >>= 1) {
        if (t < s) red[t] += red[t + s];
        __syncthreads();
    }
    if (t == 0) atomicAdd(out + N_XREC + 1, red[0] * (1.0f / (float)N_Z));
}

// ---------------- deconv2: 64->32, k4 s2 p1, relu — tf32 mma, parity GEMM ----------
__global__ void __launch_bounds__(256) deconv2m_k(const float* __restrict__ b) {
    extern __shared__ float dsm[];
    float* tin = dsm;               // [buf][cil(8)][4][36]
    float* ws  = dsm + 2304;        // [buf][par(4)][k(32)][40]
    uint32_t tin_s = (uint32_t)__cvta_generic_to_shared(tin);
    uint32_t ws_s  = (uint32_t)__cvta_generic_to_shared(ws);
    int n = blockIdx.x >> 4, u0 = (blockIdx.x & 15) * 2;
    int t = threadIdx.x;
    int wid = t >> 5, lane = t & 31;
    int g = lane >> 2, tg = lane & 3;
    int mt = wid & 1, par = wid >> 1;
    int py = par >> 1, px = par & 1;
    int obase = mt * 16;
    int o_lo = obase + g, o_hi = o_lo + 8;
    int jj = tg >> 1, ii = tg & 1;
    int dy = py ? (1 - jj) : (-jj);
    int dx = px ? (1 - ii) : (-ii);
    int toff = (1 + dy) * 36 + (1 + dx);
    const float* in0 = g_h2 + n * 65536;

    int boff[8];
#pragma unroll
    for (int nt = 0; nt < 8; nt++) {
        int pix = nt * 8 + g;
        boff[nt] = (pix >> 5) * 36 + (pix & 31);
    }

    float acc[8][4];
#pragma unroll
    for (int nt = 0; nt < 8; nt++)
#pragma unroll
        for (int j = 0; j < 4; j++) acc[nt][j] = 0.0f;

    auto load_chunk = [&](int buf, int ch) {
        for (int j = t; j < 1280; j += 256) {
            int p2 = j / 320, rem = j - p2 * 320;
            cp16(ws_s + (buf * 5120 + p2 * 1280 + rem * 4) * 4,
                 g_wd2t + p2 * 10240 + ch * 1280 + rem * 4);
        }
        for (int j = t; j < 1088; j += 256) {
            int cc = j / 136, rem = j - cc * 136, r = rem / 34, c = rem - r * 34;
            int yi = u0 - 1 + r, xi = c - 1;
            bool p = ((unsigned)yi < 32u) & ((unsigned)xi < 32u);
            const float* s2 = in0 + (ch * 8 + cc) * 1024 + (p ? yi * 32 + xi : 0);
            cp4(tin_s + (buf * 1152 + cc * 144 + r * 36 + c) * 4, s2, p);
        }
        cp_commit();
    };

    load_chunk(0, 0);
    for (int ch = 0; ch < 8; ch++) {
        if (ch < 7) { load_chunk((ch + 1) & 1, ch + 1); cp_wait1(); }
        else        { cp_wait0(); }
        __syncthreads();
        const float* tb = tin + (ch & 1) * 1152;
        const float* wb = ws  + (ch & 1) * 5120 + par * 1280;
#pragma unroll
        for (int s = 0; s < 4; s++) {
            uint32_t ra0 = *(const uint32_t*)&wb[(s * 8 + tg) * 40 + o_lo];
            uint32_t ra1 = *(const uint32_t*)&wb[(s * 8 + tg) * 40 + o_hi];
            uint32_t ra2 = *(const uint32_t*)&wb[(s * 8 + tg + 4) * 40 + o_lo];
            uint32_t ra3 = *(const uint32_t*)&wb[(s * 8 + tg + 4) * 40 + o_hi];
            const float* t0 = tb + (2 * s) * 144 + toff;
            const float* t1 = tb + (2 * s + 1) * 144 + toff;
#pragma unroll
            for (int nt = 0; nt < 8; nt++) {
                uint32_t rb0 = *(const uint32_t*)&t0[boff[nt]];
                uint32_t rb1 = *(const uint32_t*)&t1[boff[nt]];
                mma_tf32(acc[nt][0], acc[nt][1], acc[nt][2], acc[nt][3],
                         ra0, ra1, ra2, ra3, rb0, rb1);
            }
        }
        __syncthreads();
    }

    float bv_lo = b[o_lo], bv_hi = b[o_hi];
    float* ob = g_h1 + n * 131072;
#pragma unroll
    for (int nt = 0; nt < 8; nt++) {
#pragma unroll
        for (int c2 = 0; c2 < 2; c2++) {
            int np = nt * 8 + tg * 2 + c2;
            int u_l = np >> 5, v = np & 31;
            int yo = 2 * (u0 + u_l) + py, xo = 2 * v + px;
            ob[o_lo * 4096 + yo * 64 + xo] = fmaxf(acc[nt][c2]     + bv_lo, 0.0f);
            ob[o_hi * 4096 + yo * 64 + xo] = fmaxf(acc[nt][c2 + 2] + bv_hi, 0.0f);
        }
    }
}

// ---------------- deconv3: 32->1, k4 s2 p1, sigmoid + recon loss ----------------
__global__ void __launch_bounds__(256) deconv3t_k(const float* __restrict__ xin,
                                                  const float* __restrict__ w,
                                                  const float* __restrict__ b,
                                                  float* out) {
    __shared__ float tin[2][8][10][66];
    __shared__ float ws3[512];
    __shared__ float red[256];
    uint32_t tin_s = (uint32_t)__cvta_generic_to_shared(&tin[0][0][0][0]);
    int n = blockIdx.x >> 3, y0 = (blockIdx.x & 7) * 16;
    int t = threadIdx.x;
    int ys = t >> 4, x0 = (t & 15) * 8;
    int yo = y0 + ys;
    int ky0 = (yo + 1) & 1;
    int yiA = (yo + 1 - ky0) >> 1;
    int rowA = yiA - (y0 >> 1) + 1;
    int rowB = rowA - 1;
    int cbase = x0 >> 1;

    for (int j = t; j < 512; j += 256) ws3[j] = w[j];

    float acc[8];
#pragma unroll
    for (int s = 0; s < 8; s++) acc[s] = 0.0f;

    const float* in0 = g_h1 + n * 131072;
    auto load_chunk = [&](int buf, int ch) {
        for (int j = t; j < 5280; j += 256) {
            int cc = j / 660, rem = j - cc * 660, r = rem / 66, c = rem - r * 66;
            int yi = (y0 >> 1) - 1 + r, xi = c - 1;
            bool p = ((unsigned)yi < 64u) & ((unsigned)xi < 64u);
            const float* src = in0 + (ch * 8 + cc) * 4096 + (p ? yi * 64 + xi : 0);
            cp4(tin_s + (buf * 5280 + j) * 4, src, p);
        }
        cp_commit();
    };

    load_chunk(0, 0);
    for (int ch = 0; ch < 4; ch++) {
        if (ch < 3) { load_chunk((ch + 1) & 1, ch + 1); cp_wait1(); }
        else        { cp_wait0(); }
        __syncthreads();
        int buf = ch & 1;
#pragma unroll 2
        for (int cc = 0; cc < 8; cc++) {
            float a[6], bb[6];
#pragma unroll
            for (int c = 0; c < 6; c++) {
                a[c]  = tin[buf][cc][rowA][cbase + c];
                bb[c] = tin[buf][cc][rowB][cbase + c];
            }
            int ci = ch * 8 + cc;
            const float* wp = &ws3[ci * 16];
            float wa0 = wp[ky0 * 4 + 0], wa1 = wp[ky0 * 4 + 1];
            float wa2 = wp[ky0 * 4 + 2], wa3 = wp[ky0 * 4 + 3];
            float wb0 = wp[(ky0 + 2) * 4 + 0], wb1 = wp[(ky0 + 2) * 4 + 1];
            float wb2 = wp[(ky0 + 2) * 4 + 2], wb3 = wp[(ky0 + 2) * 4 + 3];
#pragma unroll
            for (int s = 0; s < 8; s++) {
                int ia = (s >> 1) + (s & 1) + 1, ib = ia - 1;
                float v = acc[s];
                if (s & 1) {
                    v = fmaf(a[ia],  wa0, v);
                    v = fmaf(a[ib],  wa2, v);
                    v = fmaf(bb[ia], wb0, v);
                    v = fmaf(bb[ib], wb2, v);
                } else {
                    v = fmaf(a[ia],  wa1, v);
                    v = fmaf(a[ib],  wa3, v);
                    v = fmaf(bb[ia], wb1, v);
                    v = fmaf(bb[ib], wb3, v);
                }
                acc[s] = v;
            }
        }
        __syncthreads();
    }

    float b0 = b[0];
    const float* xp = xin + n * 16384 + yo * 128 + x0;
    float* op = out + n * 16384 + yo * 128 + x0;
    float ls = 0.0f;
    float rv[8];
#pragma unroll
    for (int s = 0; s < 8; s++) {
        float r = 1.0f / (1.0f + expf(-(acc[s] + b0)));
        rv[s] = r;
        float df = r - xp[s];
        ls = fmaf(df, df, ls);
    }
    *(float4*)(op)     = make_float4(rv[0], rv[1], rv[2], rv[3]);
    *(float4*)(op + 4) = make_float4(rv[4], rv[5], rv[6], rv[7]);

    red[t] = ls;
    __syncthreads();
    for (int s = 128; s > 0; s >>= 1) {
        if (t < s) red[t] += red[t + s];
        __syncthreads();
    }
    if (t == 0) atomicAdd(out + N_XREC, red[0] * (1.0f / (float)N_XREC));
}

// ---------------- launch ----------------
extern "C" void kernel_launch(void* const* d_in, const int* in_sizes, int n_in,
                              void* d_out, int out_size) {
    const float* x   = (const float*)d_in[0];
    const float* w1  = (const float*)d_in[1];
    const float* b1  = (const float*)d_in[2];
    const float* w2  = (const float*)d_in[3];
    const float* b2  = (const float*)d_in[4];
    const float* w3  = (const float*)d_in[5];
    const float* b3  = (const float*)d_in[6];
    const float* cb  = (const float*)d_in[7];
    const float* dw1 = (const float*)d_in[8];
    const float* db1 = (const float*)d_in[9];
    const float* dw2 = (const float*)d_in[10];
    const float* db2 = (const float*)d_in[11];
    const float* dw3 = (const float*)d_in[12];
    const float* db3 = (const float*)d_in[13];
    float* out = (float*)d_out;

    static bool attr_done = false;
    if (!attr_done) {
        cudaFuncSetAttribute(conv2m_k, cudaFuncAttributeMaxDynamicSharedMemorySize, 99840);
        cudaFuncSetAttribute(conv3x3_k<0>, cudaFuncAttributeMaxDynamicSharedMemorySize, 55296);
        cudaFuncSetAttribute(conv3x3_k<1>, cudaFuncAttributeMaxDynamicSharedMemorySize, 55296);
        cudaFuncSetAttribute(deconv2m_k, cudaFuncAttributeMaxDynamicSharedMemorySize, 50176);
        cudaFuncSetAttribute(quantize_m_k, cudaFuncAttributeMaxDynamicSharedMemorySize, 79360);
        attr_done = true;
    }

    prep_all_k <<<662,  256>>>(w3, dw1, w2, dw2, cb, out);
    conv1_k    <<<2048, 256>>>(x, w1, b1);
    conv2m_k   <<<2048, 256, 99840>>>(b2);
    conv3x3_k<0><<<1024, 256, 55296>>>(b3);
    quantize_m_k<<<1024, 256, 79360>>>(cb, out);
    conv3x3_k<1><<<1024, 256, 55296>>>(db1);
    deconv2m_k <<<2048, 256, 50176>>>(db2);
    deconv3t_k <<<1024, 256>>>(x, dw3, db3, out);
}

// round 11
// speedup vs baseline: 2.8672x; 1.1254x over previous
#include <cuda_runtime.h>
#include <stdint.h>
#include <math.h>

// ---------------- geometry ----------------
// x      : [128,  1, 128, 128]
// h1     : [128, 32,  64,  64]   conv1 + relu [tf32]          (g_h1, reused for d2)
// h2b    : [128, 1024hw, 64ci]   conv2 (tf32 mma) -> bf16     (g_h2b)
// z      : [128, 64,  32,  32]   conv3 (bf16 mma) fp32        (g_z)
// zqb    : [128, 1024hw, 64ci]   codebook gather -> bf16      (g_zqb)
// d1     : [128, 64,  32,  32]   deconv1 (bf16 mma) [tf32]    (g_h2)
// x_rec  : [128,  1, 128, 128]   -> d_out[0 : 2097152]
// d_out[2097152] = recon_loss, d_out[2097153] = vq_loss

#define N_XREC   2097152
#define N_Z      8388608

__device__ float g_h1[128 * 32 * 64 * 64];
__device__ float g_h2[128 * 64 * 32 * 32];
__device__ float g_z [128 * 64 * 32 * 32];
__device__ uint32_t g_h2b[128 * 1024 * 32];   // bf16x2 pairs, [n][hw][ci/2]
__device__ uint32_t g_zqb[128 * 1024 * 32];
// bf16x2 3x3 weights: [set][sl(4)][tap(9)][kp(8)][72]
__device__ uint32_t g_wtb[2 * 20736];
// tf32-rounded conv2 weights: [ch(4)][tap(16)][k(8)][72]
__device__ float g_w2t[36864];
// tf32-rounded deconv2 weights: [par(4)][ci(64)][ji(4)][40]
__device__ float g_wd2t[40960];
// tf32-rounded codebook: [k(64)][136]
__device__ float g_cbt[8704];

// ---------------- cp.async helpers ----------------
__device__ __forceinline__ void cp4(uint32_t dst, const float* src, bool p) {
    asm volatile("cp.async.ca.shared.global [%0], [%1], 4, %2;"
                 :: "r"(dst), "l"(src), "r"(p ? 4u : 0u));
}
__device__ __forceinline__ void cp16(uint32_t dst, const void* src) {
    asm volatile("cp.async.ca.shared.global [%0], [%1], 16;"
                 :: "r"(dst), "l"(src));
}
__device__ __forceinline__ void cp16z(uint32_t dst, const void* src, bool p) {
    asm volatile("cp.async.ca.shared.global [%0], [%1], 16, %2;"
                 :: "r"(dst), "l"(src), "r"(p ? 16u : 0u));
}
__device__ __forceinline__ void cp_commit() {
    asm volatile("cp.async.commit_group;");
}
__device__ __forceinline__ void cp_wait1() {
    asm volatile("cp.async.wait_group 1;");
}
__device__ __forceinline__ void cp_wait0() {
    asm volatile("cp.async.wait_group 0;");
}

// ---------------- mma helpers ----------------
__device__ __forceinline__ uint32_t f2tf(float f) {
    uint32_t r; asm("cvt.rna.tf32.f32 %0, %1;" : "=r"(r) : "f"(f)); return r;
}
__device__ __forceinline__ float f2tf_f(float f) {
    uint32_t r = f2tf(f); return __uint_as_float(r);
}
// pack (lo -> bits[15:0], hi -> bits[31:16])
__device__ __forceinline__ uint32_t pk_bf16(float lo, float hi) {
    uint32_t r; asm("cvt.rn.bf16x2.f32 %0, %1, %2;" : "=r"(r) : "f"(hi), "f"(lo));
    return r;
}
__device__ __forceinline__ void mma_tf32(float& d0, float& d1, float& d2, float& d3,
                                         uint32_t a0, uint32_t a1, uint32_t a2, uint32_t a3,
                                         uint32_t b0, uint32_t b1) {
    asm volatile("mma.sync.aligned.m16n8k8.row.col.f32.tf32.tf32.f32 "
                 "{%0,%1,%2,%3}, {%4,%5,%6,%7}, {%8,%9}, {%0,%1,%2,%3};"
                 : "+f"(d0), "+f"(d1), "+f"(d2), "+f"(d3)
                 : "r"(a0), "r"(a1), "r"(a2), "r"(a3), "r"(b0), "r"(b1));
}
__device__ __forceinline__ void mma_bf16(float& d0, float& d1, float& d2, float& d3,
                                         uint32_t a0, uint32_t a1, uint32_t a2, uint32_t a3,
                                         uint32_t b0, uint32_t b1) {
    asm volatile("mma.sync.aligned.m16n8k16.row.col.f32.bf16.bf16.f32 "
                 "{%0,%1,%2,%3}, {%4,%5,%6,%7}, {%8,%9}, {%0,%1,%2,%3};"
                 : "+f"(d0), "+f"(d1), "+f"(d2), "+f"(d3)
                 : "r"(a0), "r"(a1), "r"(a2), "r"(a3), "r"(b0), "r"(b1));
}

// ---------------- merged prep ----------------
// ranges: [0,41472) g_wtb | [41472,78336) g_w2t | [78336,119296) g_wd2t
//         [119296,128000) g_cbt
__global__ void __launch_bounds__(256) prep_all_k(const float* __restrict__ w3,
                                                  const float* __restrict__ dw1,
                                                  const float* __restrict__ w2,
                                                  const float* __restrict__ dw2,
                                                  const float* __restrict__ cb,
                                                  float* out) {
    int i = blockIdx.x * 256 + threadIdx.x;
    if (i < 2) { out[N_XREC + i] = 0.0f; }
    if (i < 41472) {
        int set = i / 20736, r = i - set * 20736;
        int o = r % 72, q = r / 72;
        int kp = q & 7, q2 = q >> 3;
        int tap = q2 % 9, sl = q2 / 9;
        int ci0 = sl * 16 + 2 * kp;
        float v0 = 0.0f, v1 = 0.0f;
        if (o < 64) {
            if (set) {
                v0 = dw1[(ci0 * 64 + o) * 9 + (8 - tap)];
                v1 = dw1[((ci0 + 1) * 64 + o) * 9 + (8 - tap)];
            } else {
                v0 = w3[(o * 64 + ci0) * 9 + tap];
                v1 = w3[(o * 64 + ci0 + 1) * 9 + tap];
            }
        }
        g_wtb[i] = pk_bf16(v0, v1);
    } else if (i < 78336) {
        int j = i - 41472;
        int o = j % 72, q = j / 72;
        int k = q & 7, q2 = q >> 3;
        int tap = q2 & 15, ch = q2 >> 4;
        int ci = ch * 8 + k;
        float v = 0.0f;
        if (o < 64) v = w2[(o * 32 + ci) * 16 + tap];
        g_w2t[j] = f2tf_f(v);
    } else if (i < 119296) {
        int j = i - 78336;
        int o = j % 40, q = j / 40;
        int ji = q & 3, q2 = q >> 2;
        int ci = q2 & 63, par = q2 >> 6;
        int py = par >> 1, px = par & 1;
        int ky = (1 - py) + 2 * (ji >> 1);
        int kx = (1 - px) + 2 * (ji & 1);
        float v = 0.0f;
        if (o < 32) v = dw2[(ci * 32 + o) * 16 + ky * 4 + kx];
        g_wd2t[j] = f2tf_f(v);
    } else if (i < 128000) {
        int j = i - 119296;
        int m = j % 136, k = j / 136;
        float v = 0.0f;
        if (m < 128) v = cb[m * 64 + k];
        g_cbt[j] = f2tf_f(v);
    }
}

// ---------------- conv1: 1->32, k4 s2 p1, relu; output tf32-rounded ----------------
__global__ void __launch_bounds__(256) conv1_k(const float* __restrict__ x,
                                               const float* __restrict__ w,
                                               const float* __restrict__ b) {
    __shared__ float tin[10][132];
    __shared__ float ws[512];
    __shared__ float bs[32];
    int n = blockIdx.x >> 4, y0 = (blockIdx.x & 15) * 4;
    int t = threadIdx.x;
    int xo = t & 63, ys = t >> 6, yo = y0 + ys;
    for (int i = t; i < 512; i += 256) ws[i] = w[i];
    if (t < 32) bs[t] = b[t];
    const float* xp = x + n * 16384;
    for (int j = t; j < 1320; j += 256) {
        int r = j / 132, c = j - r * 132;
        int iy = 2 * y0 - 1 + r, ix = c - 1;
        float v = 0.0f;
        if ((unsigned)iy < 128u && (unsigned)ix < 128u) v = xp[iy * 128 + ix];
        tin[r][c] = v;
    }
    __syncthreads();

    float xin[16];
#pragma unroll
    for (int ky = 0; ky < 4; ky++)
#pragma unroll
        for (int kx = 0; kx < 4; kx++)
            xin[ky * 4 + kx] = tin[2 * ys + ky][2 * xo + kx];

    float* outp = g_h1 + n * 131072 + yo * 64 + xo;
#pragma unroll 4
    for (int o = 0; o < 32; o++) {
        float acc = bs[o];
#pragma unroll
        for (int k = 0; k < 16; k++) acc = fmaf(xin[k], ws[o * 16 + k], acc);
        outp[o * 4096] = f2tf_f(fmaxf(acc, 0.0f));
    }
}

// ---------------- conv2: 32->64, k4 s2 p1, relu — tf32 mma; bf16 [hw][ci] output ----
__global__ void __launch_bounds__(256) conv2m_k(const float* __restrict__ b) {
    extern __shared__ float dsm[];
    float* tin = dsm;               // [buf][ci][6][68]
    float* ws  = dsm + 6528;        // [buf][(tap*8 + k)][72]
    uint32_t tin_s = (uint32_t)__cvta_generic_to_shared(tin);
    uint32_t ws_s  = (uint32_t)__cvta_generic_to_shared(ws);
    int n = blockIdx.x >> 4, y0 = (blockIdx.x & 15) * 2;
    int t = threadIdx.x;
    int wid = t >> 5, lane = t & 31;
    int g = lane >> 2, tg = lane & 3;
    int obase = (wid & 3) * 16;
    int nbase = (wid >> 2) * 32;
    int o_lo = obase + g, o_hi = o_lo + 8;
    const float* in0 = g_h1 + n * 131072;

    int boff[4];
#pragma unroll
    for (int nt = 0; nt < 4; nt++) {
        int pix = nbase + nt * 8 + g;
        boff[nt] = (pix >> 5) * 136 + (pix & 31) * 2;
    }

    float acc[4][4];
#pragma unroll
    for (int nt = 0; nt < 4; nt++)
#pragma unroll
        for (int j = 0; j < 4; j++) acc[nt][j] = 0.0f;

    auto load_chunk = [&](int buf, int ch) {
        const float* src = g_w2t + ch * 9216;
        for (int j = t; j < 2304; j += 256)
            cp16(ws_s + (buf * 9216 + j * 4) * 4, src + j * 4);
        for (int j = t; j < 3168; j += 256) {
            int cc = j / 396, rem = j - cc * 396, r = rem / 66, c = rem - r * 66;
            int iy = 2 * y0 - 1 + r, ix = c - 1;
            bool p = ((unsigned)iy < 64u) & ((unsigned)ix < 64u);
            const float* s2 = in0 + (ch * 8 + cc) * 4096 + (p ? iy * 64 + ix : 0);
            cp4(tin_s + (buf * 3264 + cc * 408 + r * 68 + c) * 4, s2, p);
        }
        cp_commit();
    };

    load_chunk(0, 0);
    for (int ch = 0; ch < 4; ch++) {
        if (ch < 3) { load_chunk((ch + 1) & 1, ch + 1); cp_wait1(); }
        else        { cp_wait0(); }
        __syncthreads();
        const float* tb = tin + (ch & 1) * 3264;
        const float* wb = ws  + (ch & 1) * 9216;
#pragma unroll
        for (int tap = 0; tap < 16; tap++) {
            int ky = tap >> 2, kx = tap & 3;
            const float* wpb = wb + tap * 576;
            uint32_t ra0 = *(const uint32_t*)&wpb[tg * 72 + o_lo];
            uint32_t ra1 = *(const uint32_t*)&wpb[tg * 72 + o_hi];
            uint32_t ra2 = *(const uint32_t*)&wpb[(tg + 4) * 72 + o_lo];
            uint32_t ra3 = *(const uint32_t*)&wpb[(tg + 4) * 72 + o_hi];
            const float* tpb = tb + ky * 68 + kx;
#pragma unroll
            for (int nt = 0; nt < 4; nt++) {
                uint32_t rb0 = *(const uint32_t*)&tpb[tg * 408 + boff[nt]];
                uint32_t rb1 = *(const uint32_t*)&tpb[(tg + 4) * 408 + boff[nt]];
                mma_tf32(acc[nt][0], acc[nt][1], acc[nt][2], acc[nt][3],
                         ra0, ra1, ra2, ra3, rb0, rb1);
            }
        }
        __syncthreads();
    }

    // epilogue: relu, shfl-pair (g <-> g^1, lane^4), bf16x2 stores to [hw][ci]
    float bv_lo = b[o_lo], bv_hi = b[o_hi];
    uint32_t* ob = g_h2b + (n * 1024 + y0 * 32) * 32;
#pragma unroll
    for (int nt = 0; nt < 4; nt++) {
#pragma unroll
        for (int c = 0; c < 2; c++) {
            float v0 = fmaxf(acc[nt][c]     + bv_lo, 0.0f);
            float v2 = fmaxf(acc[nt][c + 2] + bv_hi, 0.0f);
            float p0 = __shfl_xor_sync(0xffffffffu, v0, 4);
            float p2 = __shfl_xor_sync(0xffffffffu, v2, 4);
            if (!(g & 1)) {
                int hw = nbase + nt * 8 + tg * 2 + c;
                uint32_t* row = ob + hw * 32;
                row[o_lo >> 1] = pk_bf16(v0, p0);
                row[o_hi >> 1] = pk_bf16(v2, p2);
            }
        }
    }
}

// ---------------- conv3 / deconv1: bf16 mma (m16n8k16) ----------------
// Input [hw][ci] bf16 (g_h2b / g_zqb). Full 64-ci tile resident in smem;
// weights double-buffered per 16-ci slice.
// smem u32: tinb[216 pix][36] (7776) + ws[2][9*8][72] (2*5184) = 72576 B
template <int SET>
__global__ void __launch_bounds__(256) conv3x3b_k(const float* __restrict__ b) {
    extern __shared__ float dsm[];
    uint32_t* tinb = (uint32_t*)dsm;
    uint32_t* ws   = (uint32_t*)dsm + 7776;
    uint32_t tin_s = (uint32_t)__cvta_generic_to_shared(tinb);
    uint32_t ws_s  = (uint32_t)__cvta_generic_to_shared(ws);
    int n = blockIdx.x >> 3, y0 = (blockIdx.x & 7) * 4;
    int t = threadIdx.x;
    int wid = t >> 5, lane = t & 31;
    int g = lane >> 2, tg = lane & 3;
    int obase = (wid & 3) * 16;
    int nbase = (wid >> 2) * 64;
    int o_lo = obase + g, o_hi = o_lo + 8;
    const uint32_t* in0 = (SET ? g_zqb : g_h2b) + n * 32768;
    const uint32_t* wsrc = g_wtb + SET * 20736;

    int idx0[8];
#pragma unroll
    for (int nt = 0; nt < 8; nt++) {
        int p = nbase + nt * 8 + g;
        idx0[nt] = (p >> 5) * 36 + (p & 31);
    }

    float acc[8][4];
#pragma unroll
    for (int nt = 0; nt < 8; nt++)
#pragma unroll
        for (int j = 0; j < 4; j++) acc[nt][j] = 0.0f;

    // stage full input tile (204 pixels x 128B), zero-filled halo
    for (int j = t; j < 1632; j += 256) {
        int pix = j >> 3, q = j & 7;
        int r = pix / 34, c = pix - r * 34;
        int iy = y0 - 1 + r, ix = c - 1;
        bool p = ((unsigned)iy < 32u) & ((unsigned)ix < 32u);
        const uint32_t* src = in0 + (p ? (iy * 32 + ix) * 32 : 0) + q * 4;
        cp16z(tin_s + ((r * 36 + c) * 36 + q * 4) * 4, src, p);
    }
    auto load_ws = [&](int buf, int s) {
        const uint32_t* src = wsrc + s * 5184;
        for (int j = t; j < 1296; j += 256)
            cp16(ws_s + (buf * 5184 + j * 4) * 4, src + j * 4);
        cp_commit();
    };
    load_ws(0, 0);                   // group 0 = tile + weights slice 0

    for (int s = 0; s < 4; s++) {
        if (s < 3) { load_ws((s + 1) & 1, s + 1); cp_wait1(); }
        else       { cp_wait0(); }
        __syncthreads();
        const uint32_t* wb = ws + (s & 1) * 5184;
        int koff = s * 8;
#pragma unroll
        for (int tap = 0; tap < 9; tap++) {
            int ky = tap / 3, kx = tap - ky * 3;
            const uint32_t* wpb = wb + tap * 576;
            uint32_t ra0 = wpb[tg * 72 + o_lo];
            uint32_t ra1 = wpb[tg * 72 + o_hi];
            uint32_t ra2 = wpb[(tg + 4) * 72 + o_lo];
            uint32_t ra3 = wpb[(tg + 4) * 72 + o_hi];
            int doff = ky * 36 + kx;
#pragma unroll
            for (int nt = 0; nt < 8; nt++) {
                const uint32_t* tp = tinb + (idx0[nt] + doff) * 36 + koff;
                uint32_t rb0 = tp[tg];
                uint32_t rb1 = tp[tg + 4];
                mma_bf16(acc[nt][0], acc[nt][1], acc[nt][2], acc[nt][3],
                         ra0, ra1, ra2, ra3, rb0, rb1);
            }
        }
        __syncthreads();
    }

    float bv_lo = b[o_lo], bv_hi = b[o_hi];
    float* outbase = (SET ? g_h2 : g_z) + n * 65536 + y0 * 32;
#pragma unroll
    for (int nt = 0; nt < 8; nt++) {
        int pc = nbase + nt * 8 + tg * 2;
        float v0 = acc[nt][0] + bv_lo, v1 = acc[nt][1] + bv_lo;
        float v2 = acc[nt][2] + bv_hi, v3 = acc[nt][3] + bv_hi;
        if (SET) {
            v0 = f2tf_f(fmaxf(v0, 0.0f)); v1 = f2tf_f(fmaxf(v1, 0.0f));
            v2 = f2tf_f(fmaxf(v2, 0.0f)); v3 = f2tf_f(fmaxf(v3, 0.0f));
        }
        *(float2*)(outbase + o_lo * 1024 + pc) = make_float2(v0, v1);
        *(float2*)(outbase + o_hi * 1024 + pc) = make_float2(v2, v3);
    }
}

// ---------------- quantize — tf32 mma GEMM + argmin; z_q out bf16 [hw][ci] ----------
// smem floats: zt[64][136] @0 | cbt[64][136] @8704 | minS[8][128] @17408
//              minI[8][128] @18432 | cn[128] @19456 | red[256] @19584  -> 79360 B
__global__ void __launch_bounds__(256) quantize_m_k(const float* __restrict__ cb,
                                                    float* out) {
    extern __shared__ float dsm[];
    float* zt   = dsm;
    float* cbt  = dsm + 8704;
    float* minS = dsm + 17408;
    int*   minI = (int*)(dsm + 18432);
    float* cn   = dsm + 19456;
    float* red  = dsm + 19584;
    uint32_t zt_s  = (uint32_t)__cvta_generic_to_shared(zt);
    uint32_t cbt_s = (uint32_t)__cvta_generic_to_shared(cbt);
    int t = threadIdx.x;
    int n = blockIdx.x >> 3, hw0 = (blockIdx.x & 7) * 128;
    int wid = t >> 5, lane = t & 31;
    int g = lane >> 2, tg = lane & 3;
    int mbase = wid * 16;

    const float* zsrc = g_z + n * 65536 + hw0;
    for (int j = t; j < 2048; j += 256) {
        int row = j >> 5, c4 = j & 31;
        cp16(zt_s + (row * 136 + c4 * 4) * 4, zsrc + row * 1024 + c4 * 4);
    }
    for (int j = t; j < 2176; j += 256)
        cp16(cbt_s + j * 16, g_cbt + j * 4);
    cp_commit();
    if (t < 128) {
        float s = 0.0f;
        const float* cp = cb + t * 64;
#pragma unroll
        for (int d = 0; d < 64; d++) s = fmaf(cp[d], cp[d], s);
        cn[t] = s;
    }
    cp_wait0();
    __syncthreads();

    float acc[16][4];
#pragma unroll
    for (int nt = 0; nt < 16; nt++)
#pragma unroll
        for (int j = 0; j < 4; j++) acc[nt][j] = 0.0f;

#pragma unroll
    for (int ks = 0; ks < 8; ks++) {
        const float* a0 = cbt + (ks * 8 + tg) * 136 + mbase + g;
        const float* a1 = cbt + (ks * 8 + tg + 4) * 136 + mbase + g;
        uint32_t ra0 = *(const uint32_t*)a0;
        uint32_t ra1 = *(const uint32_t*)(a0 + 8);
        uint32_t ra2 = *(const uint32_t*)a1;
        uint32_t ra3 = *(const uint32_t*)(a1 + 8);
        const float* b0 = zt + (ks * 8 + tg) * 136 + g;
        const float* b1 = zt + (ks * 8 + tg + 4) * 136 + g;
#pragma unroll
        for (int nt = 0; nt < 16; nt++) {
            uint32_t rb0 = f2tf(b0[nt * 8]);
            uint32_t rb1 = f2tf(b1[nt * 8]);
            mma_tf32(acc[nt][0], acc[nt][1], acc[nt][2], acc[nt][3],
                     ra0, ra1, ra2, ra3, rb0, rb1);
        }
    }

    float cn_lo = cn[mbase + g], cn_hi = cn[mbase + g + 8];
#pragma unroll
    for (int nt = 0; nt < 16; nt++) {
#pragma unroll
        for (int c2 = 0; c2 < 2; c2++) {
            float s_lo = fmaf(-2.0f, acc[nt][c2],     cn_lo);
            float s_hi = fmaf(-2.0f, acc[nt][c2 + 2], cn_hi);
            float s = s_lo; int idx = mbase + g;
            if (s_hi < s) { s = s_hi; idx = mbase + g + 8; }
#pragma unroll
            for (int m = 4; m <= 16; m <<= 1) {
                float so = __shfl_xor_sync(0xffffffffu, s, m);
                int   io = __shfl_xor_sync(0xffffffffu, idx, m);
                if (so < s || (so == s && io < idx)) { s = so; idx = io; }
            }
            if (g == 0) {
                int px = nt * 8 + tg * 2 + c2;
                minS[wid * 128 + px] = s;
                minI[wid * 128 + px] = idx;
            }
        }
    }
    __syncthreads();

    float vs = 0.0f;
    if (t < 128) {
        float bs = minS[t]; int bi = minI[t];
#pragma unroll
        for (int w = 1; w < 8; w++) {
            float s = minS[w * 128 + t]; int i2 = minI[w * 128 + t];
            if (s < bs || (s == bs && i2 < bi)) { bs = s; bi = i2; }
        }
        const float* cbp = cb + bi * 64;
        uint32_t* zq32 = g_zqb + (n * 1024 + hw0 + t) * 32;
#pragma unroll
        for (int d2 = 0; d2 < 32; d2++) {
            float c0 = cbp[2 * d2], c1 = cbp[2 * d2 + 1];
            zq32[d2] = pk_bf16(c0, c1);
            float df0 = zt[(2 * d2) * 136 + t] - c0;
            float df1 = zt[(2 * d2 + 1) * 136 + t] - c1;
            vs = fmaf(df0, df0, vs);
            vs = fmaf(df1, df1, vs);
        }
    }
    red[t] = vs;
    __syncthreads();
    for (int s = 128; s > 0; s >>= 1) {
        if (t < s) red[t] += red[t + s];
        __syncthreads();
    }
    if (t == 0) atomicAdd(out + N_XREC + 1, red[0] * (1.0f / (float)N_Z));
}

// ---------------- deconv2: 64->32, k4 s2 p1, relu — tf32 mma, parity GEMM ----------
__global__ void __launch_bounds__(256) deconv2m_k(const float* __restrict__ b) {
    extern __shared__ float dsm[];
    float* tin = dsm;               // [buf][cil(8)][4][36]
    float* ws  = dsm + 2304;        // [buf][par(4)][k(32)][40]
    uint32_t tin_s = (uint32_t)__cvta_generic_to_shared(tin);
    uint32_t ws_s  = (uint32_t)__cvta_generic_to_shared(ws);
    int n = blockIdx.x >> 4, u0 = (blockIdx.x & 15) * 2;
    int t = threadIdx.x;
    int wid = t >> 5, lane = t & 31;
    int g = lane >> 2, tg = lane & 3;
    int mt = wid & 1, par = wid >> 1;
    int py = par >> 1, px = par & 1;
    int obase = mt * 16;
    int o_lo = obase + g, o_hi = o_lo + 8;
    int jj = tg >> 1, ii = tg & 1;
    int dy = py ? (1 - jj) : (-jj);
    int dx = px ? (1 - ii) : (-ii);
    int toff = (1 + dy) * 36 + (1 + dx);
    const float* in0 = g_h2 + n * 65536;

    int boff[8];
#pragma unroll
    for (int nt = 0; nt < 8; nt++) {
        int pix = nt * 8 + g;
        boff[nt] = (pix >> 5) * 36 + (pix & 31);
    }

    float acc[8][4];
#pragma unroll
    for (int nt = 0; nt < 8; nt++)
#pragma unroll
        for (int j = 0; j < 4; j++) acc[nt][j] = 0.0f;

    auto load_chunk = [&](int buf, int ch) {
        for (int j = t; j < 1280; j += 256) {
            int p2 = j / 320, rem = j - p2 * 320;
            cp16(ws_s + (buf * 5120 + p2 * 1280 + rem * 4) * 4,
                 g_wd2t + p2 * 10240 + ch * 1280 + rem * 4);
        }
        for (int j = t; j < 1088; j += 256) {
            int cc = j / 136, rem = j - cc * 136, r = rem / 34, c = rem - r * 34;
            int yi = u0 - 1 + r, xi = c - 1;
            bool p = ((unsigned)yi < 32u) & ((unsigned)xi < 32u);
            const float* s2 = in0 + (ch * 8 + cc) * 1024 + (p ? yi * 32 + xi : 0);
            cp4(tin_s + (buf * 1152 + cc * 144 + r * 36 + c) * 4, s2, p);
        }
        cp_commit();
    };

    load_chunk(0, 0);
    for (int ch = 0; ch < 8; ch++) {
        if (ch < 7) { load_chunk((ch + 1) & 1, ch + 1); cp_wait1(); }
        else        { cp_wait0(); }
        __syncthreads();
        const float* tb = tin + (ch & 1) * 1152;
        const float* wb = ws  + (ch & 1) * 5120 + par * 1280;
#pragma unroll
        for (int s = 0; s < 4; s++) {
            uint32_t ra0 = *(const uint32_t*)&wb[(s * 8 + tg) * 40 + o_lo];
            uint32_t ra1 = *(const uint32_t*)&wb[(s * 8 + tg) * 40 + o_hi];
            uint32_t ra2 = *(const uint32_t*)&wb[(s * 8 + tg + 4) * 40 + o_lo];
            uint32_t ra3 = *(const uint32_t*)&wb[(s * 8 + tg + 4) * 40 + o_hi];
            const float* t0 = tb + (2 * s) * 144 + toff;
            const float* t1 = tb + (2 * s + 1) * 144 + toff;
#pragma unroll
            for (int nt = 0; nt < 8; nt++) {
                uint32_t rb0 = *(const uint32_t*)&t0[boff[nt]];
                uint32_t rb1 = *(const uint32_t*)&t1[boff[nt]];
                mma_tf32(acc[nt][0], acc[nt][1], acc[nt][2], acc[nt][3],
                         ra0, ra1, ra2, ra3, rb0, rb1);
            }
        }
        __syncthreads();
    }

    float bv_lo = b[o_lo], bv_hi = b[o_hi];
    float* ob = g_h1 + n * 131072;
#pragma unroll
    for (int nt = 0; nt < 8; nt++) {
#pragma unroll
        for (int c2 = 0; c2 < 2; c2++) {
            int np = nt * 8 + tg * 2 + c2;
            int u_l = np >> 5, v = np & 31;
            int yo = 2 * (u0 + u_l) + py, xo = 2 * v + px;
            ob[o_lo * 4096 + yo * 64 + xo] = fmaxf(acc[nt][c2]     + bv_lo, 0.0f);
            ob[o_hi * 4096 + yo * 64 + xo] = fmaxf(acc[nt][c2 + 2] + bv_hi, 0.0f);
        }
    }
}

// ---------------- deconv3: 32->1, k4 s2 p1, sigmoid + recon loss ----------------
__global__ void __launch_bounds__(256) deconv3t_k(const float* __restrict__ xin,
                                                  const float* __restrict__ w,
                                                  const float* __restrict__ b,
                                                  float* out) {
    __shared__ float tin[2][8][10][66];
    __shared__ float ws3[512];
    __shared__ float red[256];
    uint32_t tin_s = (uint32_t)__cvta_generic_to_shared(&tin[0][0][0][0]);
    int n = blockIdx.x >> 3, y0 = (blockIdx.x & 7) * 16;
    int t = threadIdx.x;
    int ys = t >> 4, x0 = (t & 15) * 8;
    int yo = y0 + ys;
    int ky0 = (yo + 1) & 1;
    int yiA = (yo + 1 - ky0) >> 1;
    int rowA = yiA - (y0 >> 1) + 1;
    int rowB = rowA - 1;
    int cbase = x0 >> 1;

    for (int j = t; j < 512; j += 256) ws3[j] = w[j];

    float acc[8];
#pragma unroll
    for (int s = 0; s < 8; s++) acc[s] = 0.0f;

    const float* in0 = g_h1 + n * 131072;
    auto load_chunk = [&](int buf, int ch) {
        for (int j = t; j < 5280; j += 256) {
            int cc = j / 660, rem = j - cc * 660, r = rem / 66, c = rem - r * 66;
            int yi = (y0 >> 1) - 1 + r, xi = c - 1;
            bool p = ((unsigned)yi < 64u) & ((unsigned)xi < 64u);
            const float* src = in0 + (ch * 8 + cc) * 4096 + (p ? yi * 64 + xi : 0);
            cp4(tin_s + (buf * 5280 + j) * 4, src, p);
        }
        cp_commit();
    };

    load_chunk(0, 0);
    for (int ch = 0; ch < 4; ch++) {
        if (ch < 3) { load_chunk((ch + 1) & 1, ch + 1); cp_wait1(); }
        else        { cp_wait0(); }
        __syncthreads();
        int buf = ch & 1;
#pragma unroll 2
        for (int cc = 0; cc < 8; cc++) {
            float a[6], bb[6];
#pragma unroll
            for (int c = 0; c < 6; c++) {
                a[c]  = tin[buf][cc][rowA][cbase + c];
                bb[c] = tin[buf][cc][rowB][cbase + c];
            }
            int ci = ch * 8 + cc;
            const float* wp = &ws3[ci * 16];
            float wa0 = wp[ky0 * 4 + 0], wa1 = wp[ky0 * 4 + 1];
            float wa2 = wp[ky0 * 4 + 2], wa3 = wp[ky0 * 4 + 3];
            float wb0 = wp[(ky0 + 2) * 4 + 0], wb1 = wp[(ky0 + 2) * 4 + 1];
            float wb2 = wp[(ky0 + 2) * 4 + 2], wb3 = wp[(ky0 + 2) * 4 + 3];
#pragma unroll
            for (int s = 0; s < 8; s++) {
                int ia = (s >> 1) + (s & 1) + 1, ib = ia - 1;
                float v = acc[s];
                if (s & 1) {
                    v = fmaf(a[ia],  wa0, v);
                    v = fmaf(a[ib],  wa2, v);
                    v = fmaf(bb[ia], wb0, v);
                    v = fmaf(bb[ib], wb2, v);
                } else {
                    v = fmaf(a[ia],  wa1, v);
                    v = fmaf(a[ib],  wa3, v);
                    v = fmaf(bb[ia], wb1, v);
                    v = fmaf(bb[ib], wb3, v);
                }
                acc[s] = v;
            }
        }
        __syncthreads();
    }

    float b0 = b[0];
    const float* xp = xin + n * 16384 + yo * 128 + x0;
    float* op = out + n * 16384 + yo * 128 + x0;
    float ls = 0.0f;
    float rv[8];
#pragma unroll
    for (int s = 0; s < 8; s++) {
        float r = 1.0f / (1.0f + expf(-(acc[s] + b0)));
        rv[s] = r;
        float df = r - xp[s];
        ls = fmaf(df, df, ls);
    }
    *(float4*)(op)     = make_float4(rv[0], rv[1], rv[2], rv[3]);
    *(float4*)(op + 4) = make_float4(rv[4], rv[5], rv[6], rv[7]);

    red[t] = ls;
    __syncthreads();
    for (int s = 128; s > 0; s >>= 1) {
        if (t < s) red[t] += red[t + s];
        __syncthreads();
    }
    if (t == 0) atomicAdd(out + N_XREC, red[0] * (1.0f / (float)N_XREC));
}

// ---------------- launch ----------------
extern "C" void kernel_launch(void* const* d_in, const int* in_sizes, int n_in,
                              void* d_out, int out_size) {
    const float* x   = (const float*)d_in[0];
    const float* w1  = (const float*)d_in[1];
    const float* b1  = (const float*)d_in[2];
    const float* w2  = (const float*)d_in[3];
    const float* b2  = (const float*)d_in[4];
    const float* w3  = (const float*)d_in[5];
    const float* b3  = (const float*)d_in[6];
    const float* cb  = (const float*)d_in[7];
    const float* dw1 = (const float*)d_in[8];
    const float* db1 = (const float*)d_in[9];
    const float* dw2 = (const float*)d_in[10];
    const float* db2 = (const float*)d_in[11];
    const float* dw3 = (const float*)d_in[12];
    const float* db3 = (const float*)d_in[13];
    float* out = (float*)d_out;

    static bool attr_done = false;
    if (!attr_done) {
        cudaFuncSetAttribute(conv2m_k, cudaFuncAttributeMaxDynamicSharedMemorySize, 99840);
        cudaFuncSetAttribute(conv3x3b_k<0>, cudaFuncAttributeMaxDynamicSharedMemorySize, 72576);
        cudaFuncSetAttribute(conv3x3b_k<1>, cudaFuncAttributeMaxDynamicSharedMemorySize, 72576);
        cudaFuncSetAttribute(deconv2m_k, cudaFuncAttributeMaxDynamicSharedMemorySize, 50176);
        cudaFuncSetAttribute(quantize_m_k, cudaFuncAttributeMaxDynamicSharedMemorySize, 79360);
        attr_done = true;
    }

    prep_all_k <<<500,  256>>>(w3, dw1, w2, dw2, cb, out);
    conv1_k    <<<2048, 256>>>(x, w1, b1);
    conv2m_k   <<<2048, 256, 99840>>>(b2);
    conv3x3b_k<0><<<1024, 256, 72576>>>(b3);
    quantize_m_k<<<1024, 256, 79360>>>(cb, out);
    conv3x3b_k<1><<<1024, 256, 72576>>>(db1);
    deconv2m_k <<<2048, 256, 50176>>>(db2);
    deconv3t_k <<<1024, 256>>>(x, dw3, db3, out);
}

// round 13
// speedup vs baseline: 3.8148x; 1.3305x over previous
#include <cuda_runtime.h>
#include <stdint.h>
#include <math.h>

// ---------------- geometry ----------------
// x      : [128,  1, 128, 128]
// h1b    : [128, 4096hw, 32ci]   conv1 + relu -> bf16         (g_h1b)
// h2b    : [128, 1024hw, 64ci]   conv2 (bf16 mma) -> bf16     (g_h2b)
// z      : [128, 64,  32,  32]   conv3 (bf16 mma) fp32        (g_z)
// zqb    : [128, 1024hw, 64ci]   codebook gather -> bf16      (g_zqb)
// d1b    : [128, 1024hw, 64ci]   deconv1 (bf16 mma) -> bf16   (g_d1b)
// d2     : [128, 32,  64,  64]   deconv2 (bf16 mma) fp32      (g_h1)
// x_rec  : [128,  1, 128, 128]   -> d_out[0 : 2097152]
// d_out[2097152] = recon_loss, d_out[2097153] = vq_loss

#define N_XREC   2097152
#define N_Z      8388608

__device__ float    g_h1[128 * 32 * 64 * 64];     // deconv2 output (fp32)
__device__ float    g_z [128 * 64 * 32 * 32];
__device__ uint32_t g_h1b[128 * 4096 * 16];       // bf16x2 pairs, [n][hw][ci/2]
__device__ uint32_t g_h2b[128 * 1024 * 32];
__device__ uint32_t g_zqb[128 * 1024 * 32];
__device__ uint32_t g_d1b[128 * 1024 * 32];
// bf16x2 3x3 weights: [set][sl(4)][tap(9)][kp(8)][72]
__device__ uint32_t g_wtb[2 * 20736];
// bf16x2 conv2 weights: [tap(16)][kp(16)][72]
__device__ uint32_t g_w2b[18432];
// bf16x2 deconv2 weights: [par(4)][tap(4)][kp(32)][40]
__device__ uint32_t g_wd2b[20480];
// tf32-rounded codebook: [k(64)][136]
__device__ float g_cbt[8704];

// ---------------- cp.async helpers ----------------
__device__ __forceinline__ void cp4(uint32_t dst, const float* src, bool p) {
    asm volatile("cp.async.ca.shared.global [%0], [%1], 4, %2;"
                 :: "r"(dst), "l"(src), "r"(p ? 4u : 0u));
}
__device__ __forceinline__ void cp8z(uint32_t dst, const void* src, bool p) {
    asm volatile("cp.async.ca.shared.global [%0], [%1], 8, %2;"
                 :: "r"(dst), "l"(src), "r"(p ? 8u : 0u));
}
__device__ __forceinline__ void cp16(uint32_t dst, const void* src) {
    asm volatile("cp.async.ca.shared.global [%0], [%1], 16;"
                 :: "r"(dst), "l"(src));
}
__device__ __forceinline__ void cp16z(uint32_t dst, const void* src, bool p) {
    asm volatile("cp.async.ca.shared.global [%0], [%1], 16, %2;"
                 :: "r"(dst), "l"(src), "r"(p ? 16u : 0u));
}
__device__ __forceinline__ void cp_commit() {
    asm volatile("cp.async.commit_group;");
}
__device__ __forceinline__ void cp_wait1() {
    asm volatile("cp.async.wait_group 1;");
}
__device__ __forceinline__ void cp_wait0() {
    asm volatile("cp.async.wait_group 0;");
}

// ---------------- mma helpers ----------------
__device__ __forceinline__ uint32_t f2tf(float f) {
    uint32_t r; asm("cvt.rna.tf32.f32 %0, %1;" : "=r"(r) : "f"(f)); return r;
}
__device__ __forceinline__ float f2tf_f(float f) {
    uint32_t r = f2tf(f); return __uint_as_float(r);
}
__device__ __forceinline__ uint32_t pk_bf16(float lo, float hi) {
    uint32_t r; asm("cvt.rn.bf16x2.f32 %0, %1, %2;" : "=r"(r) : "f"(hi), "f"(lo));
    return r;
}
__device__ __forceinline__ void mma_tf32(float& d0, float& d1, float& d2, float& d3,
                                         uint32_t a0, uint32_t a1, uint32_t a2, uint32_t a3,
                                         uint32_t b0, uint32_t b1) {
    asm volatile("mma.sync.aligned.m16n8k8.row.col.f32.tf32.tf32.f32 "
                 "{%0,%1,%2,%3}, {%4,%5,%6,%7}, {%8,%9}, {%0,%1,%2,%3};"
                 : "+f"(d0), "+f"(d1), "+f"(d2), "+f"(d3)
                 : "r"(a0), "r"(a1), "r"(a2), "r"(a3), "r"(b0), "r"(b1));
}
__device__ __forceinline__ void mma_bf16(float& d0, float& d1, float& d2, float& d3,
                                         uint32_t a0, uint32_t a1, uint32_t a2, uint32_t a3,
                                         uint32_t b0, uint32_t b1) {
    asm volatile("mma.sync.aligned.m16n8k16.row.col.f32.bf16.bf16.f32 "
                 "{%0,%1,%2,%3}, {%4,%5,%6,%7}, {%8,%9}, {%0,%1,%2,%3};"
                 : "+f"(d0), "+f"(d1), "+f"(d2), "+f"(d3)
                 : "r"(a0), "r"(a1), "r"(a2), "r"(a3), "r"(b0), "r"(b1));
}

// ---------------- merged prep ----------------
// ranges: [0,41472) g_wtb | [41472,59904) g_w2b | [59904,80384) g_wd2b
//         [80384,89088) g_cbt
__global__ void __launch_bounds__(256) prep_all_k(const float* __restrict__ w3,
                                                  const float* __restrict__ dw1,
                                                  const float* __restrict__ w2,
                                                  const float* __restrict__ dw2,
                                                  const float* __restrict__ cb,
                                                  float* out) {
    int i = blockIdx.x * 256 + threadIdx.x;
    if (i < 2) { out[N_XREC + i] = 0.0f; }
    if (i < 41472) {
        int set = i / 20736, r = i - set * 20736;
        int o = r % 72, q = r / 72;
        int kp = q & 7, q2 = q >> 3;
        int tap = q2 % 9, sl = q2 / 9;
        int ci0 = sl * 16 + 2 * kp;
        float v0 = 0.0f, v1 = 0.0f;
        if (o < 64) {
            if (set) {
                v0 = dw1[(ci0 * 64 + o) * 9 + (8 - tap)];
                v1 = dw1[((ci0 + 1) * 64 + o) * 9 + (8 - tap)];
            } else {
                v0 = w3[(o * 64 + ci0) * 9 + tap];
                v1 = w3[(o * 64 + ci0 + 1) * 9 + tap];
            }
        }
        g_wtb[i] = pk_bf16(v0, v1);
    } else if (i < 59904) {
        int j = i - 41472;
        int o = j % 72, q = j / 72;
        int kp = q & 15, tap = q >> 4;
        int ci0 = 2 * kp;
        float v0 = 0.0f, v1 = 0.0f;
        if (o < 64) {
            v0 = w2[(o * 32 + ci0) * 16 + tap];
            v1 = w2[(o * 32 + ci0 + 1) * 16 + tap];
        }
        g_w2b[j] = pk_bf16(v0, v1);
    } else if (i < 80384) {
        int j = i - 59904;
        int o = j % 40, q = j / 40;
        int kp = q & 31, q2 = q >> 5;
        int tap = q2 & 3, par = q2 >> 2;
        int py = par >> 1, px = par & 1;
        int ky = (1 - py) + 2 * (tap >> 1);
        int kx = (1 - px) + 2 * (tap & 1);
        int ci0 = 2 * kp;
        float v0 = 0.0f, v1 = 0.0f;
        if (o < 32) {
            v0 = dw2[(ci0 * 32 + o) * 16 + ky * 4 + kx];
            v1 = dw2[((ci0 + 1) * 32 + o) * 16 + ky * 4 + kx];
        }
        g_wd2b[j] = pk_bf16(v0, v1);
    } else if (i < 89088) {
        int j = i - 80384;
        int m = j % 136, k = j / 136;
        float v = 0.0f;
        if (m < 128) v = cb[m * 64 + k];
        g_cbt[j] = f2tf_f(v);
    }
}

// ---------------- conv1: 1->32, k4 s2 p1, relu; output bf16 [hw][ci] ----------------
__global__ void __launch_bounds__(256) conv1_k(const float* __restrict__ x,
                                               const float* __restrict__ w,
                                               const float* __restrict__ b) {
    __shared__ float tin[10][132];
    __shared__ float ws[512];
    __shared__ float bs[32];
    int n = blockIdx.x >> 4, y0 = (blockIdx.x & 15) * 4;
    int t = threadIdx.x;
    int xo = t & 63, ys = t >> 6, yo = y0 + ys;
    for (int i = t; i < 512; i += 256) ws[i] = w[i];
    if (t < 32) bs[t] = b[t];
    const float* xp = x + n * 16384;
    for (int j = t; j < 1320; j += 256) {
        int r = j / 132, c = j - r * 132;
        int iy = 2 * y0 - 1 + r, ix = c - 1;
        float v = 0.0f;
        if ((unsigned)iy < 128u && (unsigned)ix < 128u) v = xp[iy * 128 + ix];
        tin[r][c] = v;
    }
    __syncthreads();

    float xin[16];
#pragma unroll
    for (int ky = 0; ky < 4; ky++)
#pragma unroll
        for (int kx = 0; kx < 4; kx++)
            xin[ky * 4 + kx] = tin[2 * ys + ky][2 * xo + kx];

    float acc[32];
#pragma unroll 4
    for (int o = 0; o < 32; o++) {
        float a = bs[o];
#pragma unroll
        for (int k = 0; k < 16; k++) a = fmaf(xin[k], ws[o * 16 + k], a);
        acc[o] = fmaxf(a, 0.0f);
    }
    uint32_t pk[16];
#pragma unroll
    for (int j = 0; j < 16; j++) pk[j] = pk_bf16(acc[2 * j], acc[2 * j + 1]);
    uint4* op = (uint4*)(g_h1b + (n * 4096 + yo * 64 + xo) * 16);
#pragma unroll
    for (int q = 0; q < 4; q++)
        op[q] = make_uint4(pk[4 * q], pk[4 * q + 1], pk[4 * q + 2], pk[4 * q + 3]);
}

// ---------------- conv2: 32->64, k4 s2 p1, relu — bf16 mma ----------------
// Block: 1 image, 2 out rows (64 px). Full K=512 resident (tile + all weights).
// Pixel stride 18 u32 = 72B: bank-clean ((4g+tg)); staged via cp.async.8 (72 % 8 == 0).
// smem u32: tinb[6*66 pix][18] (7128) + ws[16*16][72] (18432) = 102240 B
__global__ void __launch_bounds__(256) conv2b_k(const float* __restrict__ b) {
    extern __shared__ float dsm[];
    uint32_t* tinb = (uint32_t*)dsm;
    uint32_t* ws   = (uint32_t*)dsm + 7128;
    uint32_t tin_s = (uint32_t)__cvta_generic_to_shared(tinb);
    uint32_t ws_s  = (uint32_t)__cvta_generic_to_shared(ws);
    int n = blockIdx.x >> 4, y0 = (blockIdx.x & 15) * 2;
    int t = threadIdx.x;
    int wid = t >> 5, lane = t & 31;
    int g = lane >> 2, tg = lane & 3;
    int obase = (wid & 3) * 16;
    int nbase = (wid >> 2) * 32;
    int o_lo = obase + g, o_hi = o_lo + 8;
    const uint32_t* in0 = g_h1b + n * 65536;

    int boff[4];
#pragma unroll
    for (int nt = 0; nt < 4; nt++) {
        int p = nbase + nt * 8 + g;
        boff[nt] = (p >> 5) * 132 + (p & 31) * 2;    // input pixel grid, 66/row
    }

    float acc[4][4];
#pragma unroll
    for (int nt = 0; nt < 4; nt++)
#pragma unroll
        for (int j = 0; j < 4; j++) acc[nt][j] = 0.0f;

    // stage: input tile 396 pixels x 16 u32 (zero halo, 8B copies) + all weights
    for (int j = t; j < 3168; j += 256) {
        int pix = j >> 3, q = j & 7;
        int r = pix / 66, c = pix - r * 66;
        int iy = 2 * y0 - 1 + r, ix = c - 1;
        bool p = ((unsigned)iy < 64u) & ((unsigned)ix < 64u);
        const uint32_t* src = in0 + (p ? (iy * 64 + ix) * 16 : 0) + q * 2;
        cp8z(tin_s + ((r * 66 + c) * 18 + q * 2) * 4, src, p);
    }
    for (int j = t; j < 4608; j += 256)
        cp16(ws_s + j * 16, g_w2b + j * 4);
    cp_commit();
    cp_wait0();
    __syncthreads();

#pragma unroll
    for (int tap = 0; tap < 16; tap++) {
        int ky = tap >> 2, kx = tap & 3;
#pragma unroll
        for (int ks = 0; ks < 2; ks++) {
            const uint32_t* wpb = ws + (tap * 16 + ks * 8) * 72;
            uint32_t ra0 = wpb[tg * 72 + o_lo];
            uint32_t ra1 = wpb[tg * 72 + o_hi];
            uint32_t ra2 = wpb[(tg + 4) * 72 + o_lo];
            uint32_t ra3 = wpb[(tg + 4) * 72 + o_hi];
            int doff = ky * 66 + kx;
#pragma unroll
            for (int nt = 0; nt < 4; nt++) {
                const uint32_t* tp = tinb + (boff[nt] + doff) * 18 + ks * 8;
                uint32_t rb0 = tp[tg];
                uint32_t rb1 = tp[tg + 4];
                mma_bf16(acc[nt][0], acc[nt][1], acc[nt][2], acc[nt][3],
                         ra0, ra1, ra2, ra3, rb0, rb1);
            }
        }
    }

    // epilogue: relu, shfl-pair (lane^4), bf16x2 stores to g_h2b [hw][ci]
    float bv_lo = b[o_lo], bv_hi = b[o_hi];
    uint32_t* ob = g_h2b + (n * 1024 + y0 * 32) * 32;
#pragma unroll
    for (int nt = 0; nt < 4; nt++) {
#pragma unroll
        for (int c = 0; c < 2; c++) {
            float v0 = fmaxf(acc[nt][c]     + bv_lo, 0.0f);
            float v2 = fmaxf(acc[nt][c + 2] + bv_hi, 0.0f);
            float p0 = __shfl_xor_sync(0xffffffffu, v0, 4);
            float p2 = __shfl_xor_sync(0xffffffffu, v2, 4);
            if (!(g & 1)) {
                int hw = nbase + nt * 8 + tg * 2 + c;
                uint32_t* row = ob + hw * 32;
                row[o_lo >> 1] = pk_bf16(v0, p0);
                row[o_hi >> 1] = pk_bf16(v2, p2);
            }
        }
    }
}

// ---------------- conv3 / deconv1: bf16 mma (m16n8k16) ----------------
// SET=0: in g_h2b, out g_z (fp32). SET=1: in g_zqb, out g_d1b (bf16 [hw][ci]).
// smem u32: tinb[216 pix][36] (7776) + ws[2][9*8][72] (2*5184) = 72576 B
template <int SET>
__global__ void __launch_bounds__(256) conv3x3b_k(const float* __restrict__ b) {
    extern __shared__ float dsm[];
    uint32_t* tinb = (uint32_t*)dsm;
    uint32_t* ws   = (uint32_t*)dsm + 7776;
    uint32_t tin_s = (uint32_t)__cvta_generic_to_shared(tinb);
    uint32_t ws_s  = (uint32_t)__cvta_generic_to_shared(ws);
    int n = blockIdx.x >> 3, y0 = (blockIdx.x & 7) * 4;
    int t = threadIdx.x;
    int wid = t >> 5, lane = t & 31;
    int g = lane >> 2, tg = lane & 3;
    int obase = (wid & 3) * 16;
    int nbase = (wid >> 2) * 64;
    int o_lo = obase + g, o_hi = o_lo + 8;
    const uint32_t* in0 = (SET ? g_zqb : g_h2b) + n * 32768;
    const uint32_t* wsrc = g_wtb + SET * 20736;

    int idx0[8];
#pragma unroll
    for (int nt = 0; nt < 8; nt++) {
        int p = nbase + nt * 8 + g;
        idx0[nt] = (p >> 5) * 36 + (p & 31);
    }

    float acc[8][4];
#pragma unroll
    for (int nt = 0; nt < 8; nt++)
#pragma unroll
        for (int j = 0; j < 4; j++) acc[nt][j] = 0.0f;

    for (int j = t; j < 1632; j += 256) {
        int pix = j >> 3, q = j & 7;
        int r = pix / 34, c = pix - r * 34;
        int iy = y0 - 1 + r, ix = c - 1;
        bool p = ((unsigned)iy < 32u) & ((unsigned)ix < 32u);
        const uint32_t* src = in0 + (p ? (iy * 32 + ix) * 32 : 0) + q * 4;
        cp16z(tin_s + ((r * 36 + c) * 36 + q * 4) * 4, src, p);
    }
    auto load_ws = [&](int buf, int s) {
        const uint32_t* src = wsrc + s * 5184;
        for (int j = t; j < 1296; j += 256)
            cp16(ws_s + (buf * 5184 + j * 4) * 4, src + j * 4);
        cp_commit();
    };
    load_ws(0, 0);

    for (int s = 0; s < 4; s++) {
        if (s < 3) { load_ws((s + 1) & 1, s + 1); cp_wait1(); }
        else       { cp_wait0(); }
        __syncthreads();
        const uint32_t* wb = ws + (s & 1) * 5184;
        int koff = s * 8;
#pragma unroll
        for (int tap = 0; tap < 9; tap++) {
            int ky = tap / 3, kx = tap - ky * 3;
            const uint32_t* wpb = wb + tap * 576;
            uint32_t ra0 = wpb[tg * 72 + o_lo];
            uint32_t ra1 = wpb[tg * 72 + o_hi];
            uint32_t ra2 = wpb[(tg + 4) * 72 + o_lo];
            uint32_t ra3 = wpb[(tg + 4) * 72 + o_hi];
            int doff = ky * 36 + kx;
#pragma unroll
            for (int nt = 0; nt < 8; nt++) {
                const uint32_t* tp = tinb + (idx0[nt] + doff) * 36 + koff;
                uint32_t rb0 = tp[tg];
                uint32_t rb1 = tp[tg + 4];
                mma_bf16(acc[nt][0], acc[nt][1], acc[nt][2], acc[nt][3],
                         ra0, ra1, ra2, ra3, rb0, rb1);
            }
        }
        __syncthreads();
    }

    float bv_lo = b[o_lo], bv_hi = b[o_hi];
    if (SET == 0) {
        float* outbase = g_z + n * 65536 + y0 * 32;
#pragma unroll
        for (int nt = 0; nt < 8; nt++) {
            int pc = nbase + nt * 8 + tg * 2;
            *(float2*)(outbase + o_lo * 1024 + pc) =
                make_float2(acc[nt][0] + bv_lo, acc[nt][1] + bv_lo);
            *(float2*)(outbase + o_hi * 1024 + pc) =
                make_float2(acc[nt][2] + bv_hi, acc[nt][3] + bv_hi);
        }
    } else {
        uint32_t* ob = g_d1b + (n * 1024 + y0 * 32) * 32;
#pragma unroll
        for (int nt = 0; nt < 8; nt++) {
            float v0 = fmaxf(acc[nt][0] + bv_lo, 0.0f);
            float v1 = fmaxf(acc[nt][1] + bv_lo, 0.0f);
            float v2 = fmaxf(acc[nt][2] + bv_hi, 0.0f);
            float v3 = fmaxf(acc[nt][3] + bv_hi, 0.0f);
            float p0 = __shfl_xor_sync(0xffffffffu, v0, 4);
            float p1 = __shfl_xor_sync(0xffffffffu, v1, 4);
            float p2 = __shfl_xor_sync(0xffffffffu, v2, 4);
            float p3 = __shfl_xor_sync(0xffffffffu, v3, 4);
            if (!(g & 1)) {
                int pc = nbase + nt * 8 + tg * 2;
                uint32_t* r0 = ob + pc * 32;
                uint32_t* r1 = r0 + 32;
                r0[o_lo >> 1] = pk_bf16(v0, p0);
                r1[o_lo >> 1] = pk_bf16(v1, p1);
                r0[o_hi >> 1] = pk_bf16(v2, p2);
                r1[o_hi >> 1] = pk_bf16(v3, p3);
            }
        }
    }
}

// ---------------- quantize — tf32 mma GEMM + argmin; z_q out bf16 [hw][ci] ----------
__global__ void __launch_bounds__(256) quantize_m_k(const float* __restrict__ cb,
                                                    float* out) {
    extern __shared__ float dsm[];
    float* zt   = dsm;
    float* cbt  = dsm + 8704;
    float* minS = dsm + 17408;
    int*   minI = (int*)(dsm + 18432);
    float* cn   = dsm + 19456;
    float* red  = dsm + 19584;
    uint32_t zt_s  = (uint32_t)__cvta_generic_to_shared(zt);
    uint32_t cbt_s = (uint32_t)__cvta_generic_to_shared(cbt);
    int t = threadIdx.x;
    int n = blockIdx.x >> 3, hw0 = (blockIdx.x & 7) * 128;
    int wid = t >> 5, lane = t & 31;
    int g = lane >> 2, tg = lane & 3;
    int mbase = wid * 16;

    const float* zsrc = g_z + n * 65536 + hw0;
    for (int j = t; j < 2048; j += 256) {
        int row = j >> 5, c4 = j & 31;
        cp16(zt_s + (row * 136 + c4 * 4) * 4, zsrc + row * 1024 + c4 * 4);
    }
    for (int j = t; j < 2176; j += 256)
        cp16(cbt_s + j * 16, g_cbt + j * 4);
    cp_commit();
    if (t < 128) {
        float s = 0.0f;
        const float* cp = cb + t * 64;
#pragma unroll
        for (int d = 0; d < 64; d++) s = fmaf(cp[d], cp[d], s);
        cn[t] = s;
    }
    cp_wait0();
    __syncthreads();

    float acc[16][4];
#pragma unroll
    for (int nt = 0; nt < 16; nt++)
#pragma unroll
        for (int j = 0; j < 4; j++) acc[nt][j] = 0.0f;

#pragma unroll
    for (int ks = 0; ks < 8; ks++) {
        const float* a0 = cbt + (ks * 8 + tg) * 136 + mbase + g;
        const float* a1 = cbt + (ks * 8 + tg + 4) * 136 + mbase + g;
        uint32_t ra0 = *(const uint32_t*)a0;
        uint32_t ra1 = *(const uint32_t*)(a0 + 8);
        uint32_t ra2 = *(const uint32_t*)a1;
        uint32_t ra3 = *(const uint32_t*)(a1 + 8);
        const float* b0 = zt + (ks * 8 + tg) * 136 + g;
        const float* b1 = zt + (ks * 8 + tg + 4) * 136 + g;
#pragma unroll
        for (int nt = 0; nt < 16; nt++) {
            uint32_t rb0 = f2tf(b0[nt * 8]);
            uint32_t rb1 = f2tf(b1[nt * 8]);
            mma_tf32(acc[nt][0], acc[nt][1], acc[nt][2], acc[nt][3],
                     ra0, ra1, ra2, ra3, rb0, rb1);
        }
    }

    float cn_lo = cn[mbase + g], cn_hi = cn[mbase + g + 8];
#pragma unroll
    for (int nt = 0; nt < 16; nt++) {
#pragma unroll
        for (int c2 = 0; c2 < 2; c2++) {
            float s_lo = fmaf(-2.0f, acc[nt][c2],     cn_lo);
            float s_hi = fmaf(-2.0f, acc[nt][c2 + 2], cn_hi);
            float s = s_lo; int idx = mbase + g;
            if (s_hi < s) { s = s_hi; idx = mbase + g + 8; }
#pragma unroll
            for (int m = 4; m <= 16; m <<= 1) {
                float so = __shfl_xor_sync(0xffffffffu, s, m);
                int   io = __shfl_xor_sync(0xffffffffu, idx, m);
                if (so < s || (so == s && io < idx)) { s = so; idx = io; }
            }
            if (g == 0) {
                int px = nt * 8 + tg * 2 + c2;
                minS[wid * 128 + px] = s;
                minI[wid * 128 + px] = idx;
            }
        }
    }
    __syncthreads();

    float vs = 0.0f;
    if (t < 128) {
        float bs = minS[t]; int bi = minI[t];
#pragma unroll
        for (int w = 1; w < 8; w++) {
            float s = minS[w * 128 + t]; int i2 = minI[w * 128 + t];
            if (s < bs || (s == bs && i2 < bi)) { bs = s; bi = i2; }
        }
        const float* cbp = cb + bi * 64;
        uint32_t* zq32 = g_zqb + (n * 1024 + hw0 + t) * 32;
#pragma unroll
        for (int d2 = 0; d2 < 32; d2++) {
            float c0 = cbp[2 * d2], c1 = cbp[2 * d2 + 1];
            zq32[d2] = pk_bf16(c0, c1);
            float df0 = zt[(2 * d2) * 136 + t] - c0;
            float df1 = zt[(2 * d2 + 1) * 136 + t] - c1;
            vs = fmaf(df0, df0, vs);
            vs = fmaf(df1, df1, vs);
        }
    }
    red[t] = vs;
    __syncthreads();
    for (int s = 128; s > 0; s >>= 1) {
        if (t < s) red[t] += red[t + s];
        __syncthreads();
    }
    if (t == 0) atomicAdd(out + N_XREC + 1, red[0] * (1.0f / (float)N_Z));
}

// ---------------- deconv2: 64->32, k4 s2 p1, relu — bf16 mma, parity GEMM ----------
// smem u32: tinb[4*36 pix][36] (5184) + ws[par(4)][tap(4)][kp(32)][40] (20480) = 102656 B
__global__ void __launch_bounds__(256) deconv2b_k(const float* __restrict__ b) {
    extern __shared__ float dsm[];
    uint32_t* tinb = (uint32_t*)dsm;
    uint32_t* ws   = (uint32_t*)dsm + 5184;
    uint32_t tin_s = (uint32_t)__cvta_generic_to_shared(tinb);
    uint32_t ws_s  = (uint32_t)__cvta_generic_to_shared(ws);
    int n = blockIdx.x >> 4, u0 = (blockIdx.x & 15) * 2;
    int t = threadIdx.x;
    int wid = t >> 5, lane = t & 31;
    int g = lane >> 2, tg = lane & 3;
    int mt = wid & 1, par = wid >> 1;
    int py = par >> 1, px = par & 1;
    int obase = mt * 16;
    int o_lo = obase + g, o_hi = o_lo + 8;
    const uint32_t* in0 = g_d1b + n * 32768;

    int boff[8];
#pragma unroll
    for (int nt = 0; nt < 8; nt++) {
        int p = nt * 8 + g;                       // n = u_l*32 + v
        boff[nt] = (p >> 5) * 36 + (p & 31);
    }

    float acc[8][4];
#pragma unroll
    for (int nt = 0; nt < 8; nt++)
#pragma unroll
        for (int j = 0; j < 4; j++) acc[nt][j] = 0.0f;

    for (int j = t; j < 1088; j += 256) {
        int pix = j >> 3, q = j & 7;
        int r = pix / 34, c = pix - r * 34;
        int yi = u0 - 1 + r, xi = c - 1;
        bool p = ((unsigned)yi < 32u) & ((unsigned)xi < 32u);
        const uint32_t* src = in0 + (p ? (yi * 32 + xi) * 32 : 0) + q * 4;
        cp16z(tin_s + ((r * 36 + c) * 36 + q * 4) * 4, src, p);
    }
    for (int j = t; j < 5120; j += 256)
        cp16(ws_s + j * 16, g_wd2b + j * 4);
    cp_commit();
    cp_wait0();
    __syncthreads();

    const uint32_t* wp0 = ws + par * 5120;
#pragma unroll
    for (int tap = 0; tap < 4; tap++) {
        int jj = tap >> 1, ii = tap & 1;
        int dy = py - jj, dx = px - ii;
        int doff = (1 + dy) * 36 + (1 + dx);
        const uint32_t* wpt = wp0 + tap * 1280;   // [kp(32)][40]
#pragma unroll
        for (int ks = 0; ks < 4; ks++) {
            const uint32_t* wpb = wpt + ks * 8 * 40;
            uint32_t ra0 = wpb[tg * 40 + o_lo];
            uint32_t ra1 = wpb[tg * 40 + o_hi];
            uint32_t ra2 = wpb[(tg + 4) * 40 + o_lo];
            uint32_t ra3 = wpb[(tg + 4) * 40 + o_hi];
#pragma unroll
            for (int nt = 0; nt < 8; nt++) {
                const uint32_t* tp = tinb + (boff[nt] + doff) * 36 + ks * 8;
                uint32_t rb0 = tp[tg];
                uint32_t rb1 = tp[tg + 4];
                mma_bf16(acc[nt][0], acc[nt][1], acc[nt][2], acc[nt][3],
                         ra0, ra1, ra2, ra3, rb0, rb1);
            }
        }
    }

    float bv_lo = b[o_lo], bv_hi = b[o_hi];
    float* ob = g_h1 + n * 131072;
#pragma unroll
    for (int nt = 0; nt < 8; nt++) {
#pragma unroll
        for (int c2 = 0; c2 < 2; c2++) {
            int np = nt * 8 + tg * 2 + c2;
            int u_l = np >> 5, v = np & 31;
            int yo = 2 * (u0 + u_l) + py, xo = 2 * v + px;
            ob[o_lo * 4096 + yo * 64 + xo] = fmaxf(acc[nt][c2]     + bv_lo, 0.0f);
            ob[o_hi * 4096 + yo * 64 + xo] = fmaxf(acc[nt][c2 + 2] + bv_hi, 0.0f);
        }
    }
}

// ---------------- deconv3: 32->1, k4 s2 p1, sigmoid + recon loss ----------------
__global__ void __launch_bounds__(256) deconv3t_k(const float* __restrict__ xin,
                                                  const float* __restrict__ w,
                                                  const float* __restrict__ b,
                                                  float* out) {
    __shared__ float tin[2][8][10][66];
    __shared__ float ws3[512];
    __shared__ float red[256];
    uint32_t tin_s = (uint32_t)__cvta_generic_to_shared(&tin[0][0][0][0]);
    int n = blockIdx.x >> 3, y0 = (blockIdx.x & 7) * 16;
    int t = threadIdx.x;
    int ys = t >> 4, x0 = (t & 15) * 8;
    int yo = y0 + ys;
    int ky0 = (yo + 1) & 1;
    int yiA = (yo + 1 - ky0) >> 1;
    int rowA = yiA - (y0 >> 1) + 1;
    int rowB = rowA - 1;
    int cbase = x0 >> 1;

    for (int j = t; j < 512; j += 256) ws3[j] = w[j];

    float acc[8];
#pragma unroll
    for (int s = 0; s < 8; s++) acc[s] = 0.0f;

    const float* in0 = g_h1 + n * 131072;
    auto load_chunk = [&](int buf, int ch) {
        for (int j = t; j < 5280; j += 256) {
            int cc = j / 660, rem = j - cc * 660, r = rem / 66, c = rem - r * 66;
            int yi = (y0 >> 1) - 1 + r, xi = c - 1;
            bool p = ((unsigned)yi < 64u) & ((unsigned)xi < 64u);
            const float* src = in0 + (ch * 8 + cc) * 4096 + (p ? yi * 64 + xi : 0);
            cp4(tin_s + (buf * 5280 + j) * 4, src, p);
        }
        cp_commit();
    };

    load_chunk(0, 0);
    for (int ch = 0; ch < 4; ch++) {
        if (ch < 3) { load_chunk((ch + 1) & 1, ch + 1); cp_wait1(); }
        else        { cp_wait0(); }
        __syncthreads();
        int buf = ch & 1;
#pragma unroll 2
        for (int cc = 0; cc < 8; cc++) {
            float a[6], bb[6];
#pragma unroll
            for (int c = 0; c < 6; c++) {
                a[c]  = tin[buf][cc][rowA][cbase + c];
                bb[c] = tin[buf][cc][rowB][cbase + c];
            }
            int ci = ch * 8 + cc;
            const float* wp = &ws3[ci * 16];
            float wa0 = wp[ky0 * 4 + 0], wa1 = wp[ky0 * 4 + 1];
            float wa2 = wp[ky0 * 4 + 2], wa3 = wp[ky0 * 4 + 3];
            float wb0 = wp[(ky0 + 2) * 4 + 0], wb1 = wp[(ky0 + 2) * 4 + 1];
            float wb2 = wp[(ky0 + 2) * 4 + 2], wb3 = wp[(ky0 + 2) * 4 + 3];
#pragma unroll
            for (int s = 0; s < 8; s++) {
                int ia = (s >> 1) + (s & 1) + 1, ib = ia - 1;
                float v = acc[s];
                if (s & 1) {
                    v = fmaf(a[ia],  wa0, v);
                    v = fmaf(a[ib],  wa2, v);
                    v = fmaf(bb[ia], wb0, v);
                    v = fmaf(bb[ib], wb2, v);
                } else {
                    v = fmaf(a[ia],  wa1, v);
                    v = fmaf(a[ib],  wa3, v);
                    v = fmaf(bb[ia], wb1, v);
                    v = fmaf(bb[ib], wb3, v);
                }
                acc[s] = v;
            }
        }
        __syncthreads();
    }

    float b0 = b[0];
    const float* xp = xin + n * 16384 + yo * 128 + x0;
    float* op = out + n * 16384 + yo * 128 + x0;
    float ls = 0.0f;
    float rv[8];
#pragma unroll
    for (int s = 0; s < 8; s++) {
        float r = 1.0f / (1.0f + expf(-(acc[s] + b0)));
        rv[s] = r;
        float df = r - xp[s];
        ls = fmaf(df, df, ls);
    }
    *(float4*)(op)     = make_float4(rv[0], rv[1], rv[2], rv[3]);
    *(float4*)(op + 4) = make_float4(rv[4], rv[5], rv[6], rv[7]);

    red[t] = ls;
    __syncthreads();
    for (int s = 128; s > 0; s >>= 1) {
        if (t < s) red[t] += red[t + s];
        __syncthreads();
    }
    if (t == 0) atomicAdd(out + N_XREC, red[0] * (1.0f / (float)N_XREC));
}

// ---------------- launch ----------------
extern "C" void kernel_launch(void* const* d_in, const int* in_sizes, int n_in,
                              void* d_out, int out_size) {
    const float* x   = (const float*)d_in[0];
    const float* w1  = (const float*)d_in[1];
    const float* b1  = (const float*)d_in[2];
    const float* w2  = (const float*)d_in[3];
    const float* b2  = (const float*)d_in[4];
    const float* w3  = (const float*)d_in[5];
    const float* b3  = (const float*)d_in[6];
    const float* cb  = (const float*)d_in[7];
    const float* dw1 = (const float*)d_in[8];
    const float* db1 = (const float*)d_in[9];
    const float* dw2 = (const float*)d_in[10];
    const float* db2 = (const float*)d_in[11];
    const float* dw3 = (const float*)d_in[12];
    const float* db3 = (const float*)d_in[13];
    float* out = (float*)d_out;

    static bool attr_done = false;
    if (!attr_done) {
        cudaFuncSetAttribute(conv2b_k, cudaFuncAttributeMaxDynamicSharedMemorySize, 102240);
        cudaFuncSetAttribute(conv3x3b_k<0>, cudaFuncAttributeMaxDynamicSharedMemorySize, 72576);
        cudaFuncSetAttribute(conv3x3b_k<1>, cudaFuncAttributeMaxDynamicSharedMemorySize, 72576);
        cudaFuncSetAttribute(deconv2b_k, cudaFuncAttributeMaxDynamicSharedMemorySize, 102656);
        cudaFuncSetAttribute(quantize_m_k, cudaFuncAttributeMaxDynamicSharedMemorySize, 79360);
        attr_done = true;
    }

    prep_all_k <<<348,  256>>>(w3, dw1, w2, dw2, cb, out);
    conv1_k    <<<2048, 256>>>(x, w1, b1);
    conv2b_k   <<<2048, 256, 102240>>>(b2);
    conv3x3b_k<0><<<1024, 256, 72576>>>(b3);
    quantize_m_k<<<1024, 256, 79360>>>(cb, out);
    conv3x3b_k<1><<<1024, 256, 72576>>>(db1);
    deconv2b_k <<<2048, 256, 102656>>>(db2);
    deconv3t_k <<<1024, 256>>>(x, dw3, db3, out);
}

// round 14
// speedup vs baseline: 3.9185x; 1.0272x over previous
#include <cuda_runtime.h>
#include <stdint.h>
#include <math.h>

// ---------------- geometry ----------------
// x      : [128,  1, 128, 128]
// h1b    : [128, 4096hw, 32ci]   conv1 + relu -> bf16         (g_h1b)
// h2b    : [128, 1024hw, 64ci]   conv2 (bf16 mma) -> bf16     (g_h2b)
// z      : [128, 64,  32,  32]   conv3 (bf16 mma) [tf32]      (g_z)
// zqb    : [128, 1024hw, 64ci]   codebook gather -> bf16      (g_zqb)
// d1b    : [128, 1024hw, 64ci]   deconv1 (bf16 mma) -> bf16   (g_d1b)
// d2     : [128, 32,  64,  64]   deconv2 (bf16 mma) fp32      (g_h1)
// x_rec  : [128,  1, 128, 128]   -> d_out[0 : 2097152]
// d_out[2097152] = recon_loss, d_out[2097153] = vq_loss

#define N_XREC   2097152
#define N_Z      8388608

__device__ float    g_h1[128 * 32 * 64 * 64];     // deconv2 output (fp32)
__device__ float    g_z [128 * 64 * 32 * 32];
__device__ uint32_t g_h1b[128 * 4096 * 16];       // bf16x2 pairs, [n][hw][ci/2]
__device__ uint32_t g_h2b[128 * 1024 * 32];
__device__ uint32_t g_zqb[128 * 1024 * 32];
__device__ uint32_t g_d1b[128 * 1024 * 32];
// bf16x2 3x3 weights: [set][sl(4)][tap(9)][kp(8)][72]
__device__ uint32_t g_wtb[2 * 20736];
// bf16x2 conv2 weights: [tap(16)][kp(16)][72]
__device__ uint32_t g_w2b[18432];
// bf16x2 deconv2 weights: [par(4)][tap(4)][kp(32)][40]
__device__ uint32_t g_wd2b[20480];
// tf32-rounded codebook: [k(64)][136]
__device__ float g_cbt[8704];

// ---------------- cp.async helpers ----------------
__device__ __forceinline__ void cp4(uint32_t dst, const float* src, bool p) {
    asm volatile("cp.async.ca.shared.global [%0], [%1], 4, %2;"
                 :: "r"(dst), "l"(src), "r"(p ? 4u : 0u));
}
__device__ __forceinline__ void cp8z(uint32_t dst, const void* src, bool p) {
    asm volatile("cp.async.ca.shared.global [%0], [%1], 8, %2;"
                 :: "r"(dst), "l"(src), "r"(p ? 8u : 0u));
}
__device__ __forceinline__ void cp16(uint32_t dst, const void* src) {
    asm volatile("cp.async.ca.shared.global [%0], [%1], 16;"
                 :: "r"(dst), "l"(src));
}
__device__ __forceinline__ void cp16z(uint32_t dst, const void* src, bool p) {
    asm volatile("cp.async.ca.shared.global [%0], [%1], 16, %2;"
                 :: "r"(dst), "l"(src), "r"(p ? 16u : 0u));
}
__device__ __forceinline__ void cp_commit() {
    asm volatile("cp.async.commit_group;");
}
__device__ __forceinline__ void cp_wait1() {
    asm volatile("cp.async.wait_group 1;");
}
__device__ __forceinline__ void cp_wait0() {
    asm volatile("cp.async.wait_group 0;");
}

// ---------------- mma helpers ----------------
__device__ __forceinline__ uint32_t f2tf(float f) {
    uint32_t r; asm("cvt.rna.tf32.f32 %0, %1;" : "=r"(r) : "f"(f)); return r;
}
__device__ __forceinline__ float f2tf_f(float f) {
    uint32_t r = f2tf(f); return __uint_as_float(r);
}
__device__ __forceinline__ uint32_t pk_bf16(float lo, float hi) {
    uint32_t r; asm("cvt.rn.bf16x2.f32 %0, %1, %2;" : "=r"(r) : "f"(hi), "f"(lo));
    return r;
}
__device__ __forceinline__ void mma_tf32(float& d0, float& d1, float& d2, float& d3,
                                         uint32_t a0, uint32_t a1, uint32_t a2, uint32_t a3,
                                         uint32_t b0, uint32_t b1) {
    asm volatile("mma.sync.aligned.m16n8k8.row.col.f32.tf32.tf32.f32 "
                 "{%0,%1,%2,%3}, {%4,%5,%6,%7}, {%8,%9}, {%0,%1,%2,%3};"
                 : "+f"(d0), "+f"(d1), "+f"(d2), "+f"(d3)
                 : "r"(a0), "r"(a1), "r"(a2), "r"(a3), "r"(b0), "r"(b1));
}
__device__ __forceinline__ void mma_bf16(float& d0, float& d1, float& d2, float& d3,
                                         uint32_t a0, uint32_t a1, uint32_t a2, uint32_t a3,
                                         uint32_t b0, uint32_t b1) {
    asm volatile("mma.sync.aligned.m16n8k16.row.col.f32.bf16.bf16.f32 "
                 "{%0,%1,%2,%3}, {%4,%5,%6,%7}, {%8,%9}, {%0,%1,%2,%3};"
                 : "+f"(d0), "+f"(d1), "+f"(d2), "+f"(d3)
                 : "r"(a0), "r"(a1), "r"(a2), "r"(a3), "r"(b0), "r"(b1));
}

// ---------------- merged prep ----------------
__global__ void __launch_bounds__(256) prep_all_k(const float* __restrict__ w3,
                                                  const float* __restrict__ dw1,
                                                  const float* __restrict__ w2,
                                                  const float* __restrict__ dw2,
                                                  const float* __restrict__ cb,
                                                  float* out) {
    int i = blockIdx.x * 256 + threadIdx.x;
    if (i < 2) { out[N_XREC + i] = 0.0f; }
    if (i < 41472) {
        int set = i / 20736, r = i - set * 20736;
        int o = r % 72, q = r / 72;
        int kp = q & 7, q2 = q >> 3;
        int tap = q2 % 9, sl = q2 / 9;
        int ci0 = sl * 16 + 2 * kp;
        float v0 = 0.0f, v1 = 0.0f;
        if (o < 64) {
            if (set) {
                v0 = dw1[(ci0 * 64 + o) * 9 + (8 - tap)];
                v1 = dw1[((ci0 + 1) * 64 + o) * 9 + (8 - tap)];
            } else {
                v0 = w3[(o * 64 + ci0) * 9 + tap];
                v1 = w3[(o * 64 + ci0 + 1) * 9 + tap];
            }
        }
        g_wtb[i] = pk_bf16(v0, v1);
    } else if (i < 59904) {
        int j = i - 41472;
        int o = j % 72, q = j / 72;
        int kp = q & 15, tap = q >> 4;
        int ci0 = 2 * kp;
        float v0 = 0.0f, v1 = 0.0f;
        if (o < 64) {
            v0 = w2[(o * 32 + ci0) * 16 + tap];
            v1 = w2[(o * 32 + ci0 + 1) * 16 + tap];
        }
        g_w2b[j] = pk_bf16(v0, v1);
    } else if (i < 80384) {
        int j = i - 59904;
        int o = j % 40, q = j / 40;
        int kp = q & 31, q2 = q >> 5;
        int tap = q2 & 3, par = q2 >> 2;
        int py = par >> 1, px = par & 1;
        int ky = (1 - py) + 2 * (tap >> 1);
        int kx = (1 - px) + 2 * (tap & 1);
        int ci0 = 2 * kp;
        float v0 = 0.0f, v1 = 0.0f;
        if (o < 32) {
            v0 = dw2[(ci0 * 32 + o) * 16 + ky * 4 + kx];
            v1 = dw2[((ci0 + 1) * 32 + o) * 16 + ky * 4 + kx];
        }
        g_wd2b[j] = pk_bf16(v0, v1);
    } else if (i < 89088) {
        int j = i - 80384;
        int m = j % 136, k = j / 136;
        float v = 0.0f;
        if (m < 128) v = cb[m * 64 + k];
        g_cbt[j] = f2tf_f(v);
    }
}

// ---------------- conv1: 1->32, k4 s2 p1, relu; output bf16 [hw][ci] ----------------
__global__ void __launch_bounds__(256) conv1_k(const float* __restrict__ x,
                                               const float* __restrict__ w,
                                               const float* __restrict__ b) {
    __shared__ float tin[10][132];
    __shared__ float ws[512];
    __shared__ float bs[32];
    int n = blockIdx.x >> 4, y0 = (blockIdx.x & 15) * 4;
    int t = threadIdx.x;
    int xo = t & 63, ys = t >> 6, yo = y0 + ys;
    for (int i = t; i < 512; i += 256) ws[i] = w[i];
    if (t < 32) bs[t] = b[t];
    const float* xp = x + n * 16384;
    for (int j = t; j < 1320; j += 256) {
        int r = j / 132, c = j - r * 132;
        int iy = 2 * y0 - 1 + r, ix = c - 1;
        float v = 0.0f;
        if ((unsigned)iy < 128u && (unsigned)ix < 128u) v = xp[iy * 128 + ix];
        tin[r][c] = v;
    }
    __syncthreads();

    float xin[16];
#pragma unroll
    for (int ky = 0; ky < 4; ky++)
#pragma unroll
        for (int kx = 0; kx < 4; kx++)
            xin[ky * 4 + kx] = tin[2 * ys + ky][2 * xo + kx];

    float acc[32];
#pragma unroll 4
    for (int o = 0; o < 32; o++) {
        float a = bs[o];
#pragma unroll
        for (int k = 0; k < 16; k++) a = fmaf(xin[k], ws[o * 16 + k], a);
        acc[o] = fmaxf(a, 0.0f);
    }
    uint32_t pk[16];
#pragma unroll
    for (int j = 0; j < 16; j++) pk[j] = pk_bf16(acc[2 * j], acc[2 * j + 1]);
    uint4* op = (uint4*)(g_h1b + (n * 4096 + yo * 64 + xo) * 16);
#pragma unroll
    for (int q = 0; q < 4; q++)
        op[q] = make_uint4(pk[4 * q], pk[4 * q + 1], pk[4 * q + 2], pk[4 * q + 3]);
}

// ---------------- conv2: 32->64, k4 s2 p1, relu — bf16 mma ----------------
__global__ void __launch_bounds__(256) conv2b_k(const float* __restrict__ b) {
    extern __shared__ float dsm[];
    uint32_t* tinb = (uint32_t*)dsm;
    uint32_t* ws   = (uint32_t*)dsm + 7128;
    uint32_t tin_s = (uint32_t)__cvta_generic_to_shared(tinb);
    uint32_t ws_s  = (uint32_t)__cvta_generic_to_shared(ws);
    int n = blockIdx.x >> 4, y0 = (blockIdx.x & 15) * 2;
    int t = threadIdx.x;
    int wid = t >> 5, lane = t & 31;
    int g = lane >> 2, tg = lane & 3;
    int obase = (wid & 3) * 16;
    int nbase = (wid >> 2) * 32;
    int o_lo = obase + g, o_hi = o_lo + 8;
    const uint32_t* in0 = g_h1b + n * 65536;

    int boff[4];
#pragma unroll
    for (int nt = 0; nt < 4; nt++) {
        int p = nbase + nt * 8 + g;
        boff[nt] = (p >> 5) * 132 + (p & 31) * 2;
    }

    float acc[4][4];
#pragma unroll
    for (int nt = 0; nt < 4; nt++)
#pragma unroll
        for (int j = 0; j < 4; j++) acc[nt][j] = 0.0f;

    for (int j = t; j < 3168; j += 256) {
        int pix = j >> 3, q = j & 7;
        int r = pix / 66, c = pix - r * 66;
        int iy = 2 * y0 - 1 + r, ix = c - 1;
        bool p = ((unsigned)iy < 64u) & ((unsigned)ix < 64u);
        const uint32_t* src = in0 + (p ? (iy * 64 + ix) * 16 : 0) + q * 2;
        cp8z(tin_s + ((r * 66 + c) * 18 + q * 2) * 4, src, p);
    }
    for (int j = t; j < 4608; j += 256)
        cp16(ws_s + j * 16, g_w2b + j * 4);
    cp_commit();
    cp_wait0();
    __syncthreads();

#pragma unroll
    for (int tap = 0; tap < 16; tap++) {
        int ky = tap >> 2, kx = tap & 3;
#pragma unroll
        for (int ks = 0; ks < 2; ks++) {
            const uint32_t* wpb = ws + (tap * 16 + ks * 8) * 72;
            uint32_t ra0 = wpb[tg * 72 + o_lo];
            uint32_t ra1 = wpb[tg * 72 + o_hi];
            uint32_t ra2 = wpb[(tg + 4) * 72 + o_lo];
            uint32_t ra3 = wpb[(tg + 4) * 72 + o_hi];
            int doff = ky * 66 + kx;
#pragma unroll
            for (int nt = 0; nt < 4; nt++) {
                const uint32_t* tp = tinb + (boff[nt] + doff) * 18 + ks * 8;
                uint32_t rb0 = tp[tg];
                uint32_t rb1 = tp[tg + 4];
                mma_bf16(acc[nt][0], acc[nt][1], acc[nt][2], acc[nt][3],
                         ra0, ra1, ra2, ra3, rb0, rb1);
            }
        }
    }

    float bv_lo = b[o_lo], bv_hi = b[o_hi];
    uint32_t* ob = g_h2b + (n * 1024 + y0 * 32) * 32;
#pragma unroll
    for (int nt = 0; nt < 4; nt++) {
#pragma unroll
        for (int c = 0; c < 2; c++) {
            float v0 = fmaxf(acc[nt][c]     + bv_lo, 0.0f);
            float v2 = fmaxf(acc[nt][c + 2] + bv_hi, 0.0f);
            float p0 = __shfl_xor_sync(0xffffffffu, v0, 4);
            float p2 = __shfl_xor_sync(0xffffffffu, v2, 4);
            if (!(g & 1)) {
                int hw = nbase + nt * 8 + tg * 2 + c;
                uint32_t* row = ob + hw * 32;
                row[o_lo >> 1] = pk_bf16(v0, p0);
                row[o_hi >> 1] = pk_bf16(v2, p2);
            }
        }
    }
}

// ---------------- conv3 / deconv1: bf16 mma, warp tile m=2 x n=4 ----------------
// SET=0: in g_h2b, out g_z (tf32-rounded fp32). SET=1: in g_zqb, out g_d1b (bf16).
// Warp w: obase0=(w&1)*32 (m-tiles obase0, obase0+16); nbase=(w>>1)*32 (4 n-tiles).
// smem u32: tinb[216 pix][36] (7776) + ws[2][9*8][72] (2*5184) = 72576 B
template <int SET>
__global__ void __launch_bounds__(256) conv3x3b_k(const float* __restrict__ b) {
    extern __shared__ float dsm[];
    uint32_t* tinb = (uint32_t*)dsm;
    uint32_t* ws   = (uint32_t*)dsm + 7776;
    uint32_t tin_s = (uint32_t)__cvta_generic_to_shared(tinb);
    uint32_t ws_s  = (uint32_t)__cvta_generic_to_shared(ws);
    int n = blockIdx.x >> 3, y0 = (blockIdx.x & 7) * 4;
    int t = threadIdx.x;
    int wid = t >> 5, lane = t & 31;
    int g = lane >> 2, tg = lane & 3;
    int obase0 = (wid & 1) * 32;
    int nbase = (wid >> 1) * 32;
    int o_l0 = obase0 + g,      o_h0 = o_l0 + 8;
    int o_l1 = obase0 + 16 + g, o_h1 = o_l1 + 8;
    const uint32_t* in0 = (SET ? g_zqb : g_h2b) + n * 32768;
    const uint32_t* wsrc = g_wtb + SET * 20736;

    int idx0[4];
#pragma unroll
    for (int nt = 0; nt < 4; nt++) {
        int p = nbase + nt * 8 + g;
        idx0[nt] = (p >> 5) * 36 + (p & 31);
    }

    float acc[2][4][4];
#pragma unroll
    for (int m2 = 0; m2 < 2; m2++)
#pragma unroll
        for (int nt = 0; nt < 4; nt++)
#pragma unroll
            for (int j = 0; j < 4; j++) acc[m2][nt][j] = 0.0f;

    for (int j = t; j < 1632; j += 256) {
        int pix = j >> 3, q = j & 7;
        int r = pix / 34, c = pix - r * 34;
        int iy = y0 - 1 + r, ix = c - 1;
        bool p = ((unsigned)iy < 32u) & ((unsigned)ix < 32u);
        const uint32_t* src = in0 + (p ? (iy * 32 + ix) * 32 : 0) + q * 4;
        cp16z(tin_s + ((r * 36 + c) * 36 + q * 4) * 4, src, p);
    }
    auto load_ws = [&](int buf, int s) {
        const uint32_t* src = wsrc + s * 5184;
        for (int j = t; j < 1296; j += 256)
            cp16(ws_s + (buf * 5184 + j * 4) * 4, src + j * 4);
        cp_commit();
    };
    load_ws(0, 0);

    for (int s = 0; s < 4; s++) {
        if (s < 3) { load_ws((s + 1) & 1, s + 1); cp_wait1(); }
        else       { cp_wait0(); }
        __syncthreads();
        const uint32_t* wb = ws + (s & 1) * 5184;
        int koff = s * 8;
#pragma unroll
        for (int tap = 0; tap < 9; tap++) {
            int ky = tap / 3, kx = tap - ky * 3;
            const uint32_t* wpb = wb + tap * 576;
            uint32_t a00 = wpb[tg * 72 + o_l0];
            uint32_t a01 = wpb[tg * 72 + o_h0];
            uint32_t a02 = wpb[(tg + 4) * 72 + o_l0];
            uint32_t a03 = wpb[(tg + 4) * 72 + o_h0];
            uint32_t a10 = wpb[tg * 72 + o_l1];
            uint32_t a11 = wpb[tg * 72 + o_h1];
            uint32_t a12 = wpb[(tg + 4) * 72 + o_l1];
            uint32_t a13 = wpb[(tg + 4) * 72 + o_h1];
            int doff = ky * 36 + kx;
#pragma unroll
            for (int nt = 0; nt < 4; nt++) {
                const uint32_t* tp = tinb + (idx0[nt] + doff) * 36 + koff;
                uint32_t rb0 = tp[tg];
                uint32_t rb1 = tp[tg + 4];
                mma_bf16(acc[0][nt][0], acc[0][nt][1], acc[0][nt][2], acc[0][nt][3],
                         a00, a01, a02, a03, rb0, rb1);
                mma_bf16(acc[1][nt][0], acc[1][nt][1], acc[1][nt][2], acc[1][nt][3],
                         a10, a11, a12, a13, rb0, rb1);
            }
        }
        __syncthreads();
    }

    if (SET == 0) {
        float* outbase = g_z + n * 65536 + y0 * 32;
#pragma unroll
        for (int m2 = 0; m2 < 2; m2++) {
            int olo = obase0 + m2 * 16 + g, ohi = olo + 8;
            float bl = b[olo], bh = b[ohi];
#pragma unroll
            for (int nt = 0; nt < 4; nt++) {
                int pc = nbase + nt * 8 + tg * 2;
                *(float2*)(outbase + olo * 1024 + pc) =
                    make_float2(f2tf_f(acc[m2][nt][0] + bl), f2tf_f(acc[m2][nt][1] + bl));
                *(float2*)(outbase + ohi * 1024 + pc) =
                    make_float2(f2tf_f(acc[m2][nt][2] + bh), f2tf_f(acc[m2][nt][3] + bh));
            }
        }
    } else {
        uint32_t* ob = g_d1b + (n * 1024 + y0 * 32) * 32;
#pragma unroll
        for (int m2 = 0; m2 < 2; m2++) {
            int olo = obase0 + m2 * 16 + g, ohi = olo + 8;
            float bl = b[olo], bh = b[ohi];
#pragma unroll
            for (int nt = 0; nt < 4; nt++) {
                float v0 = fmaxf(acc[m2][nt][0] + bl, 0.0f);
                float v1 = fmaxf(acc[m2][nt][1] + bl, 0.0f);
                float v2 = fmaxf(acc[m2][nt][2] + bh, 0.0f);
                float v3 = fmaxf(acc[m2][nt][3] + bh, 0.0f);
                float p0 = __shfl_xor_sync(0xffffffffu, v0, 4);
                float p1 = __shfl_xor_sync(0xffffffffu, v1, 4);
                float p2 = __shfl_xor_sync(0xffffffffu, v2, 4);
                float p3 = __shfl_xor_sync(0xffffffffu, v3, 4);
                if (!(g & 1)) {
                    int pc = nbase + nt * 8 + tg * 2;
                    uint32_t* r0 = ob + pc * 32;
                    uint32_t* r1 = r0 + 32;
                    r0[olo >> 1] = pk_bf16(v0, p0);
                    r1[olo >> 1] = pk_bf16(v1, p1);
                    r0[ohi >> 1] = pk_bf16(v2, p2);
                    r1[ohi >> 1] = pk_bf16(v3, p3);
                }
            }
        }
    }
}

// ---------------- quantize — tf32 mma GEMM + argmin (z pre-rounded tf32) ----------
__global__ void __launch_bounds__(256) quantize_m_k(const float* __restrict__ cb,
                                                    float* out) {
    extern __shared__ float dsm[];
    float* zt   = dsm;
    float* cbt  = dsm + 8704;
    float* minS = dsm + 17408;
    int*   minI = (int*)(dsm + 18432);
    float* cn   = dsm + 19456;
    float* red  = dsm + 19584;
    uint32_t zt_s  = (uint32_t)__cvta_generic_to_shared(zt);
    uint32_t cbt_s = (uint32_t)__cvta_generic_to_shared(cbt);
    int t = threadIdx.x;
    int n = blockIdx.x >> 3, hw0 = (blockIdx.x & 7) * 128;
    int wid = t >> 5, lane = t & 31;
    int g = lane >> 2, tg = lane & 3;
    int mbase = wid * 16;

    const float* zsrc = g_z + n * 65536 + hw0;
    for (int j = t; j < 2048; j += 256) {
        int row = j >> 5, c4 = j & 31;
        cp16(zt_s + (row * 136 + c4 * 4) * 4, zsrc + row * 1024 + c4 * 4);
    }
    for (int j = t; j < 2176; j += 256)
        cp16(cbt_s + j * 16, g_cbt + j * 4);
    cp_commit();
    if (t < 128) {
        float s = 0.0f;
        const float* cp = cb + t * 64;
#pragma unroll
        for (int d = 0; d < 64; d++) s = fmaf(cp[d], cp[d], s);
        cn[t] = s;
    }
    cp_wait0();
    __syncthreads();

    float acc[16][4];
#pragma unroll
    for (int nt = 0; nt < 16; nt++)
#pragma unroll
        for (int j = 0; j < 4; j++) acc[nt][j] = 0.0f;

#pragma unroll
    for (int ks = 0; ks < 8; ks++) {
        const float* a0 = cbt + (ks * 8 + tg) * 136 + mbase + g;
        const float* a1 = cbt + (ks * 8 + tg + 4) * 136 + mbase + g;
        uint32_t ra0 = *(const uint32_t*)a0;
        uint32_t ra1 = *(const uint32_t*)(a0 + 8);
        uint32_t ra2 = *(const uint32_t*)a1;
        uint32_t ra3 = *(const uint32_t*)(a1 + 8);
        const float* b0 = zt + (ks * 8 + tg) * 136 + g;
        const float* b1 = zt + (ks * 8 + tg + 4) * 136 + g;
#pragma unroll
        for (int nt = 0; nt < 16; nt++) {
            uint32_t rb0 = *(const uint32_t*)&b0[nt * 8];     // z pre-rounded tf32
            uint32_t rb1 = *(const uint32_t*)&b1[nt * 8];
            mma_tf32(acc[nt][0], acc[nt][1], acc[nt][2], acc[nt][3],
                     ra0, ra1, ra2, ra3, rb0, rb1);
        }
    }

    float cn_lo = cn[mbase + g], cn_hi = cn[mbase + g + 8];
#pragma unroll
    for (int nt = 0; nt < 16; nt++) {
#pragma unroll
        for (int c2 = 0; c2 < 2; c2++) {
            float s_lo = fmaf(-2.0f, acc[nt][c2],     cn_lo);
            float s_hi = fmaf(-2.0f, acc[nt][c2 + 2], cn_hi);
            float s = s_lo; int idx = mbase + g;
            if (s_hi < s) { s = s_hi; idx = mbase + g + 8; }
#pragma unroll
            for (int m = 4; m <= 16; m <<= 1) {
                float so = __shfl_xor_sync(0xffffffffu, s, m);
                int   io = __shfl_xor_sync(0xffffffffu, idx, m);
                if (so < s || (so == s && io < idx)) { s = so; idx = io; }
            }
            if (g == 0) {
                int px = nt * 8 + tg * 2 + c2;
                minS[wid * 128 + px] = s;
                minI[wid * 128 + px] = idx;
            }
        }
    }
    __syncthreads();

    // epilogue split over 256 threads: 2 threads per pixel, 32 dims each
    int px = t & 127, half = t >> 7;
    float bs = minS[px]; int bi = minI[px];
#pragma unroll
    for (int w = 1; w < 8; w++) {
        float s = minS[w * 128 + px]; int i2 = minI[w * 128 + px];
        if (s < bs || (s == bs && i2 < bi)) { bs = s; bi = i2; }
    }
    float vs = 0.0f;
    const float* cbp = cb + bi * 64 + half * 32;
    uint32_t* zq32 = g_zqb + (n * 1024 + hw0 + px) * 32 + half * 16;
#pragma unroll
    for (int d2 = 0; d2 < 16; d2++) {
        float c0 = cbp[2 * d2], c1 = cbp[2 * d2 + 1];
        zq32[d2] = pk_bf16(c0, c1);
        float df0 = zt[(half * 32 + 2 * d2) * 136 + px] - c0;
        float df1 = zt[(half * 32 + 2 * d2 + 1) * 136 + px] - c1;
        vs = fmaf(df0, df0, vs);
        vs = fmaf(df1, df1, vs);
    }
    red[t] = vs;
    __syncthreads();
    for (int s = 128; s > 0; s >>= 1) {
        if (t < s) red[t] += red[t + s];
        __syncthreads();
    }
    if (t == 0) atomicAdd(out + N_XREC + 1, red[0] * (1.0f / (float)N_Z));
}

// ---------------- deconv2: bf16 mma, parity GEMM, warp tile m=2 x n=4 ----------
// Warp w: par = w>>1 (py,px); half = w&1 -> pixels half*32 + nt*8; all 32 o.
// smem u32: tinb[4*36 pix][36] (5184) + ws[par(4)][tap(4)][kp(32)][40] (20480) = 102656 B
__global__ void __launch_bounds__(256) deconv2b_k(const float* __restrict__ b) {
    extern __shared__ float dsm[];
    uint32_t* tinb = (uint32_t*)dsm;
    uint32_t* ws   = (uint32_t*)dsm + 5184;
    uint32_t tin_s = (uint32_t)__cvta_generic_to_shared(tinb);
    uint32_t ws_s  = (uint32_t)__cvta_generic_to_shared(ws);
    int n = blockIdx.x >> 4, u0 = (blockIdx.x & 15) * 2;
    int t = threadIdx.x;
    int wid = t >> 5, lane = t & 31;
    int g = lane >> 2, tg = lane & 3;
    int half = wid & 1, par = wid >> 1;
    int py = par >> 1, px = par & 1;
    int o_l0 = g, o_h0 = g + 8, o_l1 = g + 16, o_h1 = g + 24;
    const uint32_t* in0 = g_d1b + n * 32768;

    int boff[4];
#pragma unroll
    for (int nt = 0; nt < 4; nt++) {
        int p = half * 32 + nt * 8 + g;
        boff[nt] = (p >> 5) * 36 + (p & 31);
    }

    float acc[2][4][4];
#pragma unroll
    for (int m2 = 0; m2 < 2; m2++)
#pragma unroll
        for (int nt = 0; nt < 4; nt++)
#pragma unroll
            for (int j = 0; j < 4; j++) acc[m2][nt][j] = 0.0f;

    for (int j = t; j < 1088; j += 256) {
        int pix = j >> 3, q = j & 7;
        int r = pix / 34, c = pix - r * 34;
        int yi = u0 - 1 + r, xi = c - 1;
        bool p = ((unsigned)yi < 32u) & ((unsigned)xi < 32u);
        const uint32_t* src = in0 + (p ? (yi * 32 + xi) * 32 : 0) + q * 4;
        cp16z(tin_s + ((r * 36 + c) * 36 + q * 4) * 4, src, p);
    }
    for (int j = t; j < 5120; j += 256)
        cp16(ws_s + j * 16, g_wd2b + j * 4);
    cp_commit();
    cp_wait0();
    __syncthreads();

    const uint32_t* wp0 = ws + par * 5120;
#pragma unroll
    for (int tap = 0; tap < 4; tap++) {
        int jj = tap >> 1, ii = tap & 1;
        int dy = py - jj, dx = px - ii;
        int doff = (1 + dy) * 36 + (1 + dx);
        const uint32_t* wpt = wp0 + tap * 1280;   // [kp(32)][40]
#pragma unroll
        for (int ks = 0; ks < 4; ks++) {
            const uint32_t* wpb = wpt + ks * 8 * 40;
            uint32_t a00 = wpb[tg * 40 + o_l0];
            uint32_t a01 = wpb[tg * 40 + o_h0];
            uint32_t a02 = wpb[(tg + 4) * 40 + o_l0];
            uint32_t a03 = wpb[(tg + 4) * 40 + o_h0];
            uint32_t a10 = wpb[tg * 40 + o_l1];
            uint32_t a11 = wpb[tg * 40 + o_h1];
            uint32_t a12 = wpb[(tg + 4) * 40 + o_l1];
            uint32_t a13 = wpb[(tg + 4) * 40 + o_h1];
#pragma unroll
            for (int nt = 0; nt < 4; nt++) {
                const uint32_t* tp = tinb + (boff[nt] + doff) * 36 + ks * 8;
                uint32_t rb0 = tp[tg];
                uint32_t rb1 = tp[tg + 4];
                mma_bf16(acc[0][nt][0], acc[0][nt][1], acc[0][nt][2], acc[0][nt][3],
                         a00, a01, a02, a03, rb0, rb1);
                mma_bf16(acc[1][nt][0], acc[1][nt][1], acc[1][nt][2], acc[1][nt][3],
                         a10, a11, a12, a13, rb0, rb1);
            }
        }
    }

    float* ob = g_h1 + n * 131072;
#pragma unroll
    for (int m2 = 0; m2 < 2; m2++) {
        int olo = m2 * 16 + g, ohi = olo + 8;
        float bl = b[olo], bh = b[ohi];
#pragma unroll
        for (int nt = 0; nt < 4; nt++) {
#pragma unroll
            for (int c2 = 0; c2 < 2; c2++) {
                int np = half * 32 + nt * 8 + tg * 2 + c2;
                int u_l = np >> 5, v = np & 31;
                int yo = 2 * (u0 + u_l) + py, xo = 2 * v + px;
                ob[olo * 4096 + yo * 64 + xo] = fmaxf(acc[m2][nt][c2]     + bl, 0.0f);
                ob[ohi * 4096 + yo * 64 + xo] = fmaxf(acc[m2][nt][c2 + 2] + bh, 0.0f);
            }
        }
    }
}

// ---------------- deconv3: 32->1, k4 s2 p1, sigmoid + recon loss ----------------
__global__ void __launch_bounds__(256) deconv3t_k(const float* __restrict__ xin,
                                                  const float* __restrict__ w,
                                                  const float* __restrict__ b,
                                                  float* out) {
    __shared__ float tin[2][8][10][66];
    __shared__ float ws3[512];
    __shared__ float red[256];
    uint32_t tin_s = (uint32_t)__cvta_generic_to_shared(&tin[0][0][0][0]);
    int n = blockIdx.x >> 3, y0 = (blockIdx.x & 7) * 16;
    int t = threadIdx.x;
    int ys = t >> 4, x0 = (t & 15) * 8;
    int yo = y0 + ys;
    int ky0 = (yo + 1) & 1;
    int yiA = (yo + 1 - ky0) >> 1;
    int rowA = yiA - (y0 >> 1) + 1;
    int rowB = rowA - 1;
    int cbase = x0 >> 1;

    for (int j = t; j < 512; j += 256) ws3[j] = w[j];

    float acc[8];
#pragma unroll
    for (int s = 0; s < 8; s++) acc[s] = 0.0f;

    const float* in0 = g_h1 + n * 131072;
    auto load_chunk = [&](int buf, int ch) {
        for (int j = t; j < 5280; j += 256) {
            int cc = j / 660, rem = j - cc * 660, r = rem / 66, c = rem - r * 66;
            int yi = (y0 >> 1) - 1 + r, xi = c - 1;
            bool p = ((unsigned)yi < 64u) & ((unsigned)xi < 64u);
            const float* src = in0 + (ch * 8 + cc) * 4096 + (p ? yi * 64 + xi : 0);
            cp4(tin_s + (buf * 5280 + j) * 4, src, p);
        }
        cp_commit();
    };

    load_chunk(0, 0);
    for (int ch = 0; ch < 4; ch++) {
        if (ch < 3) { load_chunk((ch + 1) & 1, ch + 1); cp_wait1(); }
        else        { cp_wait0(); }
        __syncthreads();
        int buf = ch & 1;
#pragma unroll 2
        for (int cc = 0; cc < 8; cc++) {
            float a[6], bb[6];
#pragma unroll
            for (int c = 0; c < 6; c++) {
                a[c]  = tin[buf][cc][rowA][cbase + c];
                bb[c] = tin[buf][cc][rowB][cbase + c];
            }
            int ci = ch * 8 + cc;
            const float* wp = &ws3[ci * 16];
            float wa0 = wp[ky0 * 4 + 0], wa1 = wp[ky0 * 4 + 1];
            float wa2 = wp[ky0 * 4 + 2], wa3 = wp[ky0 * 4 + 3];
            float wb0 = wp[(ky0 + 2) * 4 + 0], wb1 = wp[(ky0 + 2) * 4 + 1];
            float wb2 = wp[(ky0 + 2) * 4 + 2], wb3 = wp[(ky0 + 2) * 4 + 3];
#pragma unroll
            for (int s = 0; s < 8; s++) {
                int ia = (s >> 1) + (s & 1) + 1, ib = ia - 1;
                float v = acc[s];
                if (s & 1) {
                    v = fmaf(a[ia],  wa0, v);
                    v = fmaf(a[ib],  wa2, v);
                    v = fmaf(bb[ia], wb0, v);
                    v = fmaf(bb[ib], wb2, v);
                } else {
                    v = fmaf(a[ia],  wa1, v);
                    v = fmaf(a[ib],  wa3, v);
                    v = fmaf(bb[ia], wb1, v);
                    v = fmaf(bb[ib], wb3, v);
                }
                acc[s] = v;
            }
        }
        __syncthreads();
    }

    float b0 = b[0];
    const float* xp = xin + n * 16384 + yo * 128 + x0;
    float* op = out + n * 16384 + yo * 128 + x0;
    float ls = 0.0f;
    float rv[8];
#pragma unroll
    for (int s = 0; s < 8; s++) {
        float r = 1.0f / (1.0f + expf(-(acc[s] + b0)));
        rv[s] = r;
        float df = r - xp[s];
        ls = fmaf(df, df, ls);
    }
    *(float4*)(op)     = make_float4(rv[0], rv[1], rv[2], rv[3]);
    *(float4*)(op + 4) = make_float4(rv[4], rv[5], rv[6], rv[7]);

    red[t] = ls;
    __syncthreads();
    for (int s = 128; s > 0; s >>= 1) {
        if (t < s) red[t] += red[t + s];
        __syncthreads();
    }
    if (t == 0) atomicAdd(out + N_XREC, red[0] * (1.0f / (float)N_XREC));
}

// ---------------- launch ----------------
extern "C" void kernel_launch(void* const* d_in, const int* in_sizes, int n_in,
                              void* d_out, int out_size) {
    const float* x   = (const float*)d_in[0];
    const float* w1  = (const float*)d_in[1];
    const float* b1  = (const float*)d_in[2];
    const float* w2  = (const float*)d_in[3];
    const float* b2  = (const float*)d_in[4];
    const float* w3  = (const float*)d_in[5];
    const float* b3  = (const float*)d_in[6];
    const float* cb  = (const float*)d_in[7];
    const float* dw1 = (const float*)d_in[8];
    const float* db1 = (const float*)d_in[9];
    const float* dw2 = (const float*)d_in[10];
    const float* db2 = (const float*)d_in[11];
    const float* dw3 = (const float*)d_in[12];
    const float* db3 = (const float*)d_in[13];
    float* out = (float*)d_out;

    static bool attr_done = false;
    if (!attr_done) {
        cudaFuncSetAttribute(conv2b_k, cudaFuncAttributeMaxDynamicSharedMemorySize, 102240);
        cudaFuncSetAttribute(conv3x3b_k<0>, cudaFuncAttributeMaxDynamicSharedMemorySize, 72576);
        cudaFuncSetAttribute(conv3x3b_k<1>, cudaFuncAttributeMaxDynamicSharedMemorySize, 72576);
        cudaFuncSetAttribute(deconv2b_k, cudaFuncAttributeMaxDynamicSharedMemorySize, 102656);
        cudaFuncSetAttribute(quantize_m_k, cudaFuncAttributeMaxDynamicSharedMemorySize, 79360);
        attr_done = true;
    }

    prep_all_k <<<348,  256>>>(w3, dw1, w2, dw2, cb, out);
    conv1_k    <<<2048, 256>>>(x, w1, b1);
    conv2b_k   <<<2048, 256, 102240>>>(b2);
    conv3x3b_k<0><<<1024, 256, 72576>>>(b3);
    quantize_m_k<<<1024, 256, 79360>>>(cb, out);
    conv3x3b_k<1><<<1024, 256, 72576>>>(db1);
    deconv2b_k <<<2048, 256, 102656>>>(db2);
    deconv3t_k <<<1024, 256>>>(x, dw3, db3, out);
}